// round 1
// baseline (speedup 1.0000x reference)
#include <cuda_runtime.h>
#include <cuda_bf16.h>
#include <math_constants.h>

// ---------------------------------------------------------------------------
// SwinV2 block: window cosine-attention + res-post-norm MLP
// b=2, H=W=192, C=128, WS=16, NH=8, d=16
// Tokens M = 2*192*192 = 73728; windows 288; per-window n=256.
// All GEMMs run in original token order; window permutation is handled by
// gather/scatter inside the attention kernel only.
// ---------------------------------------------------------------------------

#define M_TOK   73728
#define C_DIM   128
#define NH      8
#define HD      16          // head dim
#define NWIN    288
#define NTOK    256         // tokens per window
#define IMG     192
#define WPR     12          // windows per row

// scratch (static device arrays; no allocation allowed)
__device__ float g_qkv [ (size_t)M_TOK * 384 ];   // 113 MB
__device__ float g_biasT[ (size_t)NH * NTOK * NTOK ]; // 2 MB  [h][j][i]
__device__ float g_attn[ (size_t)M_TOK * C_DIM ]; // 37.7 MB
__device__ float g_proj[ (size_t)M_TOK * C_DIM ];
__device__ float g_x1  [ (size_t)M_TOK * C_DIM ];
__device__ float g_hid [ (size_t)M_TOK * 256 ];   // 75.5 MB
__device__ float g_y   [ (size_t)M_TOK * C_DIM ];

// ---------------------------------------------------------------------------
// Generic tiled fp32 GEMM: C = act(A[M,K] @ B[K,N] + bias[N])
// BM=BN=BK=64, 256 threads, 4x4 micro-tile per thread.
// act: 0 = none, 1 = exact GELU
// ---------------------------------------------------------------------------
__global__ __launch_bounds__(256) void gemm_kernel(
    const float* __restrict__ A, const float* __restrict__ B,
    const float* __restrict__ bias, float* __restrict__ C,
    int M, int N, int K, int act)
{
    __shared__ float As[64][65];
    __shared__ float Bs[64][64];

    const int tid = threadIdx.x;
    const int tx  = tid & 15;       // col group 0..15
    const int ty  = tid >> 4;       // row group 0..15
    const int blockRow = blockIdx.y * 64;
    const int blockCol = blockIdx.x * 64;

    float acc[4][4];
    #pragma unroll
    for (int i = 0; i < 4; i++)
        #pragma unroll
        for (int j = 0; j < 4; j++) acc[i][j] = 0.f;

    for (int kt = 0; kt < K; kt += 64) {
        // load A tile 64x64 (row-major, padded smem)
        #pragma unroll
        for (int t = 0; t < 4; t++) {
            int idx = tid + t * 256;
            int r   = idx >> 4;
            int c4  = (idx & 15) << 2;
            float4 av = *reinterpret_cast<const float4*>(
                &A[(size_t)(blockRow + r) * K + kt + c4]);
            As[r][c4 + 0] = av.x; As[r][c4 + 1] = av.y;
            As[r][c4 + 2] = av.z; As[r][c4 + 3] = av.w;
        }
        // load B tile 64x64
        #pragma unroll
        for (int t = 0; t < 4; t++) {
            int idx = tid + t * 256;
            int r   = idx >> 4;
            int c4  = (idx & 15) << 2;
            *reinterpret_cast<float4*>(&Bs[r][c4]) =
                *reinterpret_cast<const float4*>(
                    &B[(size_t)(kt + r) * N + blockCol + c4]);
        }
        __syncthreads();

        #pragma unroll 16
        for (int k = 0; k < 64; k++) {
            float a0 = As[ty * 4 + 0][k];
            float a1 = As[ty * 4 + 1][k];
            float a2 = As[ty * 4 + 2][k];
            float a3 = As[ty * 4 + 3][k];
            float4 b = *reinterpret_cast<float4*>(&Bs[k][tx * 4]);
            acc[0][0] += a0 * b.x; acc[0][1] += a0 * b.y; acc[0][2] += a0 * b.z; acc[0][3] += a0 * b.w;
            acc[1][0] += a1 * b.x; acc[1][1] += a1 * b.y; acc[1][2] += a1 * b.z; acc[1][3] += a1 * b.w;
            acc[2][0] += a2 * b.x; acc[2][1] += a2 * b.y; acc[2][2] += a2 * b.z; acc[2][3] += a2 * b.w;
            acc[3][0] += a3 * b.x; acc[3][1] += a3 * b.y; acc[3][2] += a3 * b.z; acc[3][3] += a3 * b.w;
        }
        __syncthreads();
    }

    const int row0 = blockRow + ty * 4;
    const int col0 = blockCol + tx * 4;
    float4 bb = *reinterpret_cast<const float4*>(&bias[col0]);
    #pragma unroll
    for (int i = 0; i < 4; i++) {
        float4 v;
        v.x = acc[i][0] + bb.x;
        v.y = acc[i][1] + bb.y;
        v.z = acc[i][2] + bb.z;
        v.w = acc[i][3] + bb.w;
        if (act == 1) {
            v.x = v.x * normcdff(v.x);
            v.y = v.y * normcdff(v.y);
            v.z = v.z * normcdff(v.z);
            v.w = v.w * normcdff(v.w);
        }
        *reinterpret_cast<float4*>(&C[(size_t)(row0 + i) * N + col0]) = v;
    }
}

// ---------------------------------------------------------------------------
// Materialize transposed attention bias: biasT[h][j][i] = table[rpi[i][j]][h]
// ---------------------------------------------------------------------------
__global__ void bias_kernel(const int* __restrict__ rpi,
                            const float* __restrict__ table,
                            float* __restrict__ biasT)
{
    int j  = blockIdx.x;     // 0..255
    int hd = blockIdx.y;     // 0..7
    int i  = threadIdx.x;    // 0..255
    int t  = rpi[i * NTOK + j];
    biasT[((size_t)hd * NTOK + j) * NTOK + i] = table[t * NH + hd];
}

// ---------------------------------------------------------------------------
// Window cosine attention. One block per (window, head), 256 threads,
// thread i = query row i. Two-pass softmax, k/v in smem, q in registers.
// Reads qkv (orig token order, 384 per row), writes g_attn (orig order, 128).
// ---------------------------------------------------------------------------
__global__ __launch_bounds__(256) void attn_kernel(
    const float* __restrict__ qkv, const float* __restrict__ biasT,
    const float* __restrict__ logit_scale, float* __restrict__ attn_out)
{
    __shared__ float4 kn[NTOK * 4];  // normalized K rows, 16 floats each
    __shared__ float4 vv[NTOK * 4];  // V rows

    const int wi = blockIdx.x;   // 0..287
    const int hd = blockIdx.y;   // 0..7
    const int i  = threadIdx.x;  // 0..255

    const int bimg = wi / 144;
    const int wrem = wi % 144;
    const int wr = wrem / WPR, wc = wrem % WPR;
    const int rowbase = bimg * (IMG * IMG) + (wr * 16) * IMG + wc * 16;
    const int morig = rowbase + (i >> 4) * IMG + (i & 15);

    const float* base = qkv + (size_t)morig * 384 + hd * HD;

    // q row -> registers, L2-normalize
    float q[16];
    {
        const float4* q4 = reinterpret_cast<const float4*>(base);
        float qs = 0.f;
        #pragma unroll
        for (int z = 0; z < 4; z++) {
            float4 v = q4[z];
            q[z*4+0] = v.x; q[z*4+1] = v.y; q[z*4+2] = v.z; q[z*4+3] = v.w;
            qs += v.x*v.x + v.y*v.y + v.z*v.z + v.w*v.w;
        }
        float qr = 1.f / fmaxf(sqrtf(qs), 1e-12f);
        #pragma unroll
        for (int z = 0; z < 16; z++) q[z] *= qr;
    }
    // k row -> normalize -> smem; v row -> smem
    {
        const float4* k4 = reinterpret_cast<const float4*>(base + 128);
        float kv[16]; float ks = 0.f;
        #pragma unroll
        for (int z = 0; z < 4; z++) {
            float4 v = k4[z];
            kv[z*4+0] = v.x; kv[z*4+1] = v.y; kv[z*4+2] = v.z; kv[z*4+3] = v.w;
            ks += v.x*v.x + v.y*v.y + v.z*v.z + v.w*v.w;
        }
        float kr = 1.f / fmaxf(sqrtf(ks), 1e-12f);
        #pragma unroll
        for (int z = 0; z < 4; z++)
            kn[i*4+z] = make_float4(kv[z*4+0]*kr, kv[z*4+1]*kr, kv[z*4+2]*kr, kv[z*4+3]*kr);
        const float4* v4 = reinterpret_cast<const float4*>(base + 256);
        #pragma unroll
        for (int z = 0; z < 4; z++) vv[i*4+z] = v4[z];
    }

    const float scale = __expf(fminf(logit_scale[hd], 4.6051702f)); // ln(100)
    const float* brow = biasT + (size_t)hd * NTOK * NTOK;           // [j*256+i]
    __syncthreads();

    // pass 1: row max
    float mmax = -1e30f;
    for (int j = 0; j < NTOK; j++) {
        float4 k0 = kn[j*4+0], k1 = kn[j*4+1], k2 = kn[j*4+2], k3 = kn[j*4+3];
        float s = q[0]*k0.x + q[1]*k0.y + q[2]*k0.z + q[3]*k0.w
                + q[4]*k1.x + q[5]*k1.y + q[6]*k1.z + q[7]*k1.w
                + q[8]*k2.x + q[9]*k2.y + q[10]*k2.z + q[11]*k2.w
                + q[12]*k3.x + q[13]*k3.y + q[14]*k3.z + q[15]*k3.w;
        s = s * scale + brow[j * NTOK + i];
        mmax = fmaxf(mmax, s);
    }

    // pass 2: exp-sum + weighted V
    float l = 0.f;
    float acc[16];
    #pragma unroll
    for (int z = 0; z < 16; z++) acc[z] = 0.f;
    for (int j = 0; j < NTOK; j++) {
        float4 k0 = kn[j*4+0], k1 = kn[j*4+1], k2 = kn[j*4+2], k3 = kn[j*4+3];
        float s = q[0]*k0.x + q[1]*k0.y + q[2]*k0.z + q[3]*k0.w
                + q[4]*k1.x + q[5]*k1.y + q[6]*k1.z + q[7]*k1.w
                + q[8]*k2.x + q[9]*k2.y + q[10]*k2.z + q[11]*k2.w
                + q[12]*k3.x + q[13]*k3.y + q[14]*k3.z + q[15]*k3.w;
        s = s * scale + brow[j * NTOK + i];
        float p = __expf(s - mmax);
        l += p;
        float4 v0 = vv[j*4+0], v1 = vv[j*4+1], v2 = vv[j*4+2], v3 = vv[j*4+3];
        acc[0]  += p*v0.x; acc[1]  += p*v0.y; acc[2]  += p*v0.z; acc[3]  += p*v0.w;
        acc[4]  += p*v1.x; acc[5]  += p*v1.y; acc[6]  += p*v1.z; acc[7]  += p*v1.w;
        acc[8]  += p*v2.x; acc[9]  += p*v2.y; acc[10] += p*v2.z; acc[11] += p*v2.w;
        acc[12] += p*v3.x; acc[13] += p*v3.y; acc[14] += p*v3.z; acc[15] += p*v3.w;
    }
    float inv = 1.f / l;
    float* orow = attn_out + (size_t)morig * C_DIM + hd * HD;
    float4* o4 = reinterpret_cast<float4*>(orow);
    #pragma unroll
    for (int z = 0; z < 4; z++)
        o4[z] = make_float4(acc[z*4+0]*inv, acc[z*4+1]*inv, acc[z*4+2]*inv, acc[z*4+3]*inv);
}

// ---------------------------------------------------------------------------
// out = res + LayerNorm(in) * w + b   (row length 128, one warp per row)
// ---------------------------------------------------------------------------
__global__ __launch_bounds__(256) void ln_res_kernel(
    const float* __restrict__ inp, const float* __restrict__ res,
    const float* __restrict__ w, const float* __restrict__ b,
    float* __restrict__ out)
{
    int row  = blockIdx.x * 8 + (threadIdx.x >> 5);
    int lane = threadIdx.x & 31;

    const float4 v  = reinterpret_cast<const float4*>(inp + (size_t)row * 128)[lane];
    float s  = v.x + v.y + v.z + v.w;
    float s2 = v.x*v.x + v.y*v.y + v.z*v.z + v.w*v.w;
    #pragma unroll
    for (int off = 16; off > 0; off >>= 1) {
        s  += __shfl_xor_sync(0xffffffffu, s,  off);
        s2 += __shfl_xor_sync(0xffffffffu, s2, off);
    }
    const float mu   = s * (1.f / 128.f);
    const float var  = s2 * (1.f / 128.f) - mu * mu;
    const float rstd = rsqrtf(var + 1e-5f);

    const float4 wv = reinterpret_cast<const float4*>(w)[lane];
    const float4 bv = reinterpret_cast<const float4*>(b)[lane];
    const float4 rv = reinterpret_cast<const float4*>(res + (size_t)row * 128)[lane];
    float4 o;
    o.x = rv.x + (v.x - mu) * rstd * wv.x + bv.x;
    o.y = rv.y + (v.y - mu) * rstd * wv.y + bv.y;
    o.z = rv.z + (v.z - mu) * rstd * wv.z + bv.z;
    o.w = rv.w + (v.w - mu) * rstd * wv.w + bv.w;
    reinterpret_cast<float4*>(out + (size_t)row * 128)[lane] = o;
}

// ---------------------------------------------------------------------------
extern "C" void kernel_launch(void* const* d_in, const int* in_sizes, int n_in,
                              void* d_out, int out_size)
{
    const float* x           = (const float*)d_in[0];
    const float* qkv_w       = (const float*)d_in[1];
    const float* qkv_b       = (const float*)d_in[2];
    const float* proj_w      = (const float*)d_in[3];
    const float* proj_b      = (const float*)d_in[4];
    const float* logit_scale = (const float*)d_in[5];
    const float* rpb_table   = (const float*)d_in[6];
    const float* n1w         = (const float*)d_in[7];
    const float* n1b         = (const float*)d_in[8];
    const float* n2w         = (const float*)d_in[9];
    const float* n2b         = (const float*)d_in[10];
    const float* fc1_w       = (const float*)d_in[11];
    const float* fc1_b       = (const float*)d_in[12];
    const float* fc2_w       = (const float*)d_in[13];
    const float* fc2_b       = (const float*)d_in[14];
    // d_in[15]=h, d_in[16]=w (fixed 192), d_in[17]=rpi
    const int*   rpi         = (const int*)d_in[17];
    float* out = (float*)d_out;

    float *p_qkv, *p_biasT, *p_attn, *p_proj, *p_x1, *p_hid, *p_y;
    cudaGetSymbolAddress((void**)&p_qkv,   g_qkv);
    cudaGetSymbolAddress((void**)&p_biasT, g_biasT);
    cudaGetSymbolAddress((void**)&p_attn,  g_attn);
    cudaGetSymbolAddress((void**)&p_proj,  g_proj);
    cudaGetSymbolAddress((void**)&p_x1,    g_x1);
    cudaGetSymbolAddress((void**)&p_hid,   g_hid);
    cudaGetSymbolAddress((void**)&p_y,     g_y);

    // 1) materialize transposed attention bias
    bias_kernel<<<dim3(NTOK, NH), NTOK>>>(rpi, rpb_table, p_biasT);

    // 2) QKV GEMM: [73728,128] @ [128,384]
    gemm_kernel<<<dim3(384/64, M_TOK/64), 256>>>(x, qkv_w, qkv_b, p_qkv,
                                                 M_TOK, 384, 128, 0);

    // 3) window cosine attention
    attn_kernel<<<dim3(NWIN, NH), NTOK>>>(p_qkv, p_biasT, logit_scale, p_attn);

    // 4) proj GEMM: [73728,128] @ [128,128]
    gemm_kernel<<<dim3(128/64, M_TOK/64), 256>>>(p_attn, proj_w, proj_b, p_proj,
                                                 M_TOK, 128, 128, 0);

    // 5) x1 = x + LN(proj)
    ln_res_kernel<<<M_TOK/8, 256>>>(p_proj, x, n1w, n1b, p_x1);

    // 6) fc1 + GELU: [73728,128] @ [128,256]
    gemm_kernel<<<dim3(256/64, M_TOK/64), 256>>>(p_x1, fc1_w, fc1_b, p_hid,
                                                 M_TOK, 256, 128, 1);

    // 7) fc2: [73728,256] @ [256,128]
    gemm_kernel<<<dim3(128/64, M_TOK/64), 256>>>(p_hid, fc2_w, fc2_b, p_y,
                                                 M_TOK, 128, 256, 0);

    // 8) out = x1 + LN(y)
    ln_res_kernel<<<M_TOK/8, 256>>>(p_y, p_x1, n2w, n2b, out);
}

// round 2
// speedup vs baseline: 1.2934x; 1.2934x over previous
#include <cuda_runtime.h>
#include <cuda_bf16.h>
#include <math_constants.h>

// ---------------------------------------------------------------------------
// SwinV2 block: window cosine-attention + res-post-norm MLP
// b=2, H=W=192, C=128, WS=16, NH=8, d=16
// ---------------------------------------------------------------------------

#define M_TOK   73728
#define C_DIM   128
#define NH      8
#define HD      16
#define NWIN    288
#define NTOK    256
#define IMG     192
#define WPR     12

__device__ float g_qkv [ (size_t)M_TOK * 384 ];
__device__ float g_biasT[ (size_t)NH * NTOK * NTOK ];  // [h][j][i]
__device__ float g_attn[ (size_t)M_TOK * C_DIM ];
__device__ float g_proj[ (size_t)M_TOK * C_DIM ];
__device__ float g_x1  [ (size_t)M_TOK * C_DIM ];
__device__ float g_hid [ (size_t)M_TOK * 256 ];
__device__ float g_y   [ (size_t)M_TOK * C_DIM ];

// ---------------------------------------------------------------------------
// fp32 GEMM: C = act(A[M,K] @ B[K,N] + bias[N]); 128x128 tile, 8x8 microtile,
// KT=16, A stored k-major in smem, register prefetch of next tile.
// act: 0 = none, 1 = exact GELU. M%128==0, N%128==0, K%16==0.
// ---------------------------------------------------------------------------
__global__ __launch_bounds__(256) void gemm128_kernel(
    const float* __restrict__ A, const float* __restrict__ B,
    const float* __restrict__ bias, float* __restrict__ C,
    int M, int N, int K, int act)
{
    __shared__ float As[16][132];   // [k][m], padded (132*4 % 16 == 0)
    __shared__ float Bs[16][128];   // [k][n]

    const int tid = threadIdx.x;
    const int tx  = tid & 15;          // 0..15 (col group)
    const int ty  = tid >> 4;          // 0..15 (row group)
    const int brow = blockIdx.y * 128;
    const int bcol = blockIdx.x * 128;

    // load-index decomposition (both tiles: 2048 floats = 256 thr * 2 float4)
    const int a_r0  = tid >> 2;              // rows for A loads (t adds 64)
    const int a_kc  = (tid & 3) << 2;        // k-col within 16
    const int b_r0  = tid >> 5;              // rows for B loads (t adds 8)
    const int b_c   = (tid & 31) << 2;       // col within 128

    float acc[8][8];
    #pragma unroll
    for (int i = 0; i < 8; i++)
        #pragma unroll
        for (int j = 0; j < 8; j++) acc[i][j] = 0.f;

    // prefetch first tile into registers
    float4 a_pf[2], b_pf[2];
    #pragma unroll
    for (int t = 0; t < 2; t++) {
        a_pf[t] = *reinterpret_cast<const float4*>(
            &A[(size_t)(brow + a_r0 + t * 64) * K + a_kc]);
        b_pf[t] = *reinterpret_cast<const float4*>(
            &B[(size_t)(b_r0 + t * 8) * N + bcol + b_c]);
    }

    for (int kt = 0; kt < K; kt += 16) {
        // store prefetched tile to smem
        #pragma unroll
        for (int t = 0; t < 2; t++) {
            int r = a_r0 + t * 64;
            As[a_kc + 0][r] = a_pf[t].x;
            As[a_kc + 1][r] = a_pf[t].y;
            As[a_kc + 2][r] = a_pf[t].z;
            As[a_kc + 3][r] = a_pf[t].w;
            *reinterpret_cast<float4*>(&Bs[b_r0 + t * 8][b_c]) = b_pf[t];
        }
        __syncthreads();

        // prefetch next tile
        if (kt + 16 < K) {
            #pragma unroll
            for (int t = 0; t < 2; t++) {
                a_pf[t] = *reinterpret_cast<const float4*>(
                    &A[(size_t)(brow + a_r0 + t * 64) * K + kt + 16 + a_kc]);
                b_pf[t] = *reinterpret_cast<const float4*>(
                    &B[(size_t)(kt + 16 + b_r0 + t * 8) * N + bcol + b_c]);
            }
        }

        #pragma unroll
        for (int k = 0; k < 16; k++) {
            float4 a0 = *reinterpret_cast<float4*>(&As[k][ty * 4]);
            float4 a1 = *reinterpret_cast<float4*>(&As[k][ty * 4 + 64]);
            float4 b0 = *reinterpret_cast<float4*>(&Bs[k][tx * 4]);
            float4 b1 = *reinterpret_cast<float4*>(&Bs[k][tx * 4 + 64]);
            float ar[8] = {a0.x, a0.y, a0.z, a0.w, a1.x, a1.y, a1.z, a1.w};
            float br[8] = {b0.x, b0.y, b0.z, b0.w, b1.x, b1.y, b1.z, b1.w};
            #pragma unroll
            for (int i = 0; i < 8; i++)
                #pragma unroll
                for (int j = 0; j < 8; j++)
                    acc[i][j] += ar[i] * br[j];
        }
        __syncthreads();
    }

    // epilogue: 4 quads of 4x4
    #pragma unroll
    for (int qi = 0; qi < 2; qi++) {
        #pragma unroll
        for (int qj = 0; qj < 2; qj++) {
            const int c0 = bcol + tx * 4 + qj * 64;
            float4 bb = *reinterpret_cast<const float4*>(&bias[c0]);
            #pragma unroll
            for (int ii = 0; ii < 4; ii++) {
                const int r = brow + ty * 4 + qi * 64 + ii;
                float4 v;
                v.x = acc[qi * 4 + ii][qj * 4 + 0] + bb.x;
                v.y = acc[qi * 4 + ii][qj * 4 + 1] + bb.y;
                v.z = acc[qi * 4 + ii][qj * 4 + 2] + bb.z;
                v.w = acc[qi * 4 + ii][qj * 4 + 3] + bb.w;
                if (act == 1) {
                    v.x *= normcdff(v.x);
                    v.y *= normcdff(v.y);
                    v.z *= normcdff(v.z);
                    v.w *= normcdff(v.w);
                }
                *reinterpret_cast<float4*>(&C[(size_t)r * N + c0]) = v;
            }
        }
    }
}

// ---------------------------------------------------------------------------
// biasT[h][j][i] = table[rpi[i][j]][h]
// ---------------------------------------------------------------------------
__global__ void bias_kernel(const int* __restrict__ rpi,
                            const float* __restrict__ table,
                            float* __restrict__ biasT)
{
    int j  = blockIdx.x;
    int hd = blockIdx.y;
    int i  = threadIdx.x;
    int t  = rpi[i * NTOK + j];
    biasT[((size_t)hd * NTOK + j) * NTOK + i] = table[t * NH + hd];
}

// ---------------------------------------------------------------------------
// Window cosine attention. One block per (window, head), 256 threads,
// thread i = query row i. SINGLE-pass softmax with fixed upper-bound shift:
// logits = cos*scale + bias, |cos|<=1, |bias| small -> logits <= scale + eps,
// so exp(logit - scale) never overflows and never all-underflows.
// q is pre-scaled by `scale` so the dot yields the logit directly.
// ---------------------------------------------------------------------------
__global__ __launch_bounds__(256) void attn_kernel(
    const float* __restrict__ qkv, const float* __restrict__ biasT,
    const float* __restrict__ logit_scale, float* __restrict__ attn_out)
{
    __shared__ float4 kn[NTOK * 4];  // normalized K rows (16 floats each)
    __shared__ float4 vv[NTOK * 4];  // V rows

    const int wi = blockIdx.x;
    const int hd = blockIdx.y;
    const int i  = threadIdx.x;

    const int bimg = wi / 144;
    const int wrem = wi % 144;
    const int wr = wrem / WPR, wc = wrem % WPR;
    const int rowbase = bimg * (IMG * IMG) + (wr * 16) * IMG + wc * 16;
    const int morig = rowbase + (i >> 4) * IMG + (i & 15);

    const float* base = qkv + (size_t)morig * 384 + hd * HD;
    const float scale = __expf(fminf(logit_scale[hd], 4.6051702f)); // ln(100)

    // q row -> registers, L2-normalize, fold in scale
    float q[16];
    {
        const float4* q4 = reinterpret_cast<const float4*>(base);
        float qs = 0.f;
        #pragma unroll
        for (int z = 0; z < 4; z++) {
            float4 v = q4[z];
            q[z*4+0] = v.x; q[z*4+1] = v.y; q[z*4+2] = v.z; q[z*4+3] = v.w;
            qs += v.x*v.x + v.y*v.y + v.z*v.z + v.w*v.w;
        }
        float qr = scale / fmaxf(sqrtf(qs), 1e-12f);
        #pragma unroll
        for (int z = 0; z < 16; z++) q[z] *= qr;
    }
    // k row -> normalize -> smem; v row -> smem
    {
        const float4* k4 = reinterpret_cast<const float4*>(base + 128);
        float kv[16]; float ks = 0.f;
        #pragma unroll
        for (int z = 0; z < 4; z++) {
            float4 v = k4[z];
            kv[z*4+0] = v.x; kv[z*4+1] = v.y; kv[z*4+2] = v.z; kv[z*4+3] = v.w;
            ks += v.x*v.x + v.y*v.y + v.z*v.z + v.w*v.w;
        }
        float kr = 1.f / fmaxf(sqrtf(ks), 1e-12f);
        #pragma unroll
        for (int z = 0; z < 4; z++)
            kn[i*4+z] = make_float4(kv[z*4+0]*kr, kv[z*4+1]*kr, kv[z*4+2]*kr, kv[z*4+3]*kr);
        const float4* v4 = reinterpret_cast<const float4*>(base + 256);
        #pragma unroll
        for (int z = 0; z < 4; z++) vv[i*4+z] = v4[z];
    }

    const float* brow = biasT + (size_t)hd * NTOK * NTOK;  // [j*256+i]
    __syncthreads();

    float l = 0.f;
    float acc[16];
    #pragma unroll
    for (int z = 0; z < 16; z++) acc[z] = 0.f;

    #pragma unroll 1
    for (int j0 = 0; j0 < NTOK; j0 += 4) {
        float bs[4];
        #pragma unroll
        for (int u = 0; u < 4; u++) bs[u] = brow[(j0 + u) * NTOK + i];
        #pragma unroll
        for (int u = 0; u < 4; u++) {
            const int j = j0 + u;
            float4 k0 = kn[j*4+0], k1 = kn[j*4+1], k2 = kn[j*4+2], k3 = kn[j*4+3];
            float s = q[0]*k0.x + q[1]*k0.y + q[2]*k0.z + q[3]*k0.w
                    + q[4]*k1.x + q[5]*k1.y + q[6]*k1.z + q[7]*k1.w
                    + q[8]*k2.x + q[9]*k2.y + q[10]*k2.z + q[11]*k2.w
                    + q[12]*k3.x + q[13]*k3.y + q[14]*k3.z + q[15]*k3.w;
            s += bs[u];
            float p = __expf(s - scale);
            l += p;
            float4 v0 = vv[j*4+0], v1 = vv[j*4+1], v2 = vv[j*4+2], v3 = vv[j*4+3];
            acc[0]  += p*v0.x; acc[1]  += p*v0.y; acc[2]  += p*v0.z; acc[3]  += p*v0.w;
            acc[4]  += p*v1.x; acc[5]  += p*v1.y; acc[6]  += p*v1.z; acc[7]  += p*v1.w;
            acc[8]  += p*v2.x; acc[9]  += p*v2.y; acc[10] += p*v2.z; acc[11] += p*v2.w;
            acc[12] += p*v3.x; acc[13] += p*v3.y; acc[14] += p*v3.z; acc[15] += p*v3.w;
        }
    }
    float inv = 1.f / l;
    float4* o4 = reinterpret_cast<float4*>(attn_out + (size_t)morig * C_DIM + hd * HD);
    #pragma unroll
    for (int z = 0; z < 4; z++)
        o4[z] = make_float4(acc[z*4+0]*inv, acc[z*4+1]*inv, acc[z*4+2]*inv, acc[z*4+3]*inv);
}

// ---------------------------------------------------------------------------
// out = res + LayerNorm(in) * w + b   (row length 128, one warp per row)
// ---------------------------------------------------------------------------
__global__ __launch_bounds__(256) void ln_res_kernel(
    const float* __restrict__ inp, const float* __restrict__ res,
    const float* __restrict__ w, const float* __restrict__ b,
    float* __restrict__ out)
{
    int row  = blockIdx.x * 8 + (threadIdx.x >> 5);
    int lane = threadIdx.x & 31;

    const float4 v  = reinterpret_cast<const float4*>(inp + (size_t)row * 128)[lane];
    float s  = v.x + v.y + v.z + v.w;
    float s2 = v.x*v.x + v.y*v.y + v.z*v.z + v.w*v.w;
    #pragma unroll
    for (int off = 16; off > 0; off >>= 1) {
        s  += __shfl_xor_sync(0xffffffffu, s,  off);
        s2 += __shfl_xor_sync(0xffffffffu, s2, off);
    }
    const float mu   = s * (1.f / 128.f);
    const float var  = s2 * (1.f / 128.f) - mu * mu;
    const float rstd = rsqrtf(var + 1e-5f);

    const float4 wv = reinterpret_cast<const float4*>(w)[lane];
    const float4 bv = reinterpret_cast<const float4*>(b)[lane];
    const float4 rv = reinterpret_cast<const float4*>(res + (size_t)row * 128)[lane];
    float4 o;
    o.x = rv.x + (v.x - mu) * rstd * wv.x + bv.x;
    o.y = rv.y + (v.y - mu) * rstd * wv.y + bv.y;
    o.z = rv.z + (v.z - mu) * rstd * wv.z + bv.z;
    o.w = rv.w + (v.w - mu) * rstd * wv.w + bv.w;
    reinterpret_cast<float4*>(out + (size_t)row * 128)[lane] = o;
}

// ---------------------------------------------------------------------------
extern "C" void kernel_launch(void* const* d_in, const int* in_sizes, int n_in,
                              void* d_out, int out_size)
{
    const float* x           = (const float*)d_in[0];
    const float* qkv_w       = (const float*)d_in[1];
    const float* qkv_b       = (const float*)d_in[2];
    const float* proj_w      = (const float*)d_in[3];
    const float* proj_b      = (const float*)d_in[4];
    const float* logit_scale = (const float*)d_in[5];
    const float* rpb_table   = (const float*)d_in[6];
    const float* n1w         = (const float*)d_in[7];
    const float* n1b         = (const float*)d_in[8];
    const float* n2w         = (const float*)d_in[9];
    const float* n2b         = (const float*)d_in[10];
    const float* fc1_w       = (const float*)d_in[11];
    const float* fc1_b       = (const float*)d_in[12];
    const float* fc2_w       = (const float*)d_in[13];
    const float* fc2_b       = (const float*)d_in[14];
    const int*   rpi         = (const int*)d_in[17];
    float* out = (float*)d_out;

    float *p_qkv, *p_biasT, *p_attn, *p_proj, *p_x1, *p_hid, *p_y;
    cudaGetSymbolAddress((void**)&p_qkv,   g_qkv);
    cudaGetSymbolAddress((void**)&p_biasT, g_biasT);
    cudaGetSymbolAddress((void**)&p_attn,  g_attn);
    cudaGetSymbolAddress((void**)&p_proj,  g_proj);
    cudaGetSymbolAddress((void**)&p_x1,    g_x1);
    cudaGetSymbolAddress((void**)&p_hid,   g_hid);
    cudaGetSymbolAddress((void**)&p_y,     g_y);

    bias_kernel<<<dim3(NTOK, NH), NTOK>>>(rpi, rpb_table, p_biasT);

    // QKV: [73728,128] @ [128,384]
    gemm128_kernel<<<dim3(384/128, M_TOK/128), 256>>>(x, qkv_w, qkv_b, p_qkv,
                                                      M_TOK, 384, 128, 0);
    attn_kernel<<<dim3(NWIN, NH), NTOK>>>(p_qkv, p_biasT, logit_scale, p_attn);

    // proj: [73728,128] @ [128,128]
    gemm128_kernel<<<dim3(128/128, M_TOK/128), 256>>>(p_attn, proj_w, proj_b, p_proj,
                                                      M_TOK, 128, 128, 0);
    ln_res_kernel<<<M_TOK/8, 256>>>(p_proj, x, n1w, n1b, p_x1);

    // fc1 + GELU: [73728,128] @ [128,256]
    gemm128_kernel<<<dim3(256/128, M_TOK/128), 256>>>(p_x1, fc1_w, fc1_b, p_hid,
                                                      M_TOK, 256, 128, 1);
    // fc2: [73728,256] @ [256,128]
    gemm128_kernel<<<dim3(128/128, M_TOK/128), 256>>>(p_hid, fc2_w, fc2_b, p_y,
                                                      M_TOK, 128, 256, 0);

    ln_res_kernel<<<M_TOK/8, 256>>>(p_y, p_x1, n2w, n2b, out);
}

// round 3
// speedup vs baseline: 1.3664x; 1.0564x over previous
#include <cuda_runtime.h>
#include <cuda_bf16.h>
#include <math_constants.h>

// ---------------------------------------------------------------------------
// SwinV2 block: window cosine-attention + res-post-norm MLP
// b=2, H=W=192, C=128, WS=16, NH=8, d=16
// ---------------------------------------------------------------------------

#define M_TOK   73728
#define C_DIM   128
#define NH      8
#define HD      16
#define NWIN    288
#define NTOK    256
#define IMG     192
#define WPR     12

__device__ float g_qkv [ (size_t)M_TOK * 384 ];
__device__ float g_biasT[ (size_t)NH * NTOK * NTOK ];  // [h][j][i]
__device__ float g_attn[ (size_t)M_TOK * C_DIM ];
__device__ float g_proj[ (size_t)M_TOK * C_DIM ];
__device__ float g_x1  [ (size_t)M_TOK * C_DIM ];
__device__ float g_hid [ (size_t)M_TOK * 256 ];
__device__ float g_y   [ (size_t)M_TOK * C_DIM ];

// ---------------------------------------------------------------------------
// fp32 GEMM: C = act(A[M,K] @ B[K,N] + bias[N]); 128x128 tile, 8x8 microtile,
// KT=16, A stored k-major in smem, register prefetch of next tile.
// ---------------------------------------------------------------------------
__global__ __launch_bounds__(256) void gemm128_kernel(
    const float* __restrict__ A, const float* __restrict__ B,
    const float* __restrict__ bias, float* __restrict__ C,
    int M, int N, int K, int act)
{
    __shared__ float As[16][132];
    __shared__ float Bs[16][128];

    const int tid = threadIdx.x;
    const int tx  = tid & 15;
    const int ty  = tid >> 4;
    const int brow = blockIdx.y * 128;
    const int bcol = blockIdx.x * 128;

    const int a_r0  = tid >> 2;
    const int a_kc  = (tid & 3) << 2;
    const int b_r0  = tid >> 5;
    const int b_c   = (tid & 31) << 2;

    float acc[8][8];
    #pragma unroll
    for (int i = 0; i < 8; i++)
        #pragma unroll
        for (int j = 0; j < 8; j++) acc[i][j] = 0.f;

    float4 a_pf[2], b_pf[2];
    #pragma unroll
    for (int t = 0; t < 2; t++) {
        a_pf[t] = *reinterpret_cast<const float4*>(
            &A[(size_t)(brow + a_r0 + t * 64) * K + a_kc]);
        b_pf[t] = *reinterpret_cast<const float4*>(
            &B[(size_t)(b_r0 + t * 8) * N + bcol + b_c]);
    }

    for (int kt = 0; kt < K; kt += 16) {
        #pragma unroll
        for (int t = 0; t < 2; t++) {
            int r = a_r0 + t * 64;
            As[a_kc + 0][r] = a_pf[t].x;
            As[a_kc + 1][r] = a_pf[t].y;
            As[a_kc + 2][r] = a_pf[t].z;
            As[a_kc + 3][r] = a_pf[t].w;
            *reinterpret_cast<float4*>(&Bs[b_r0 + t * 8][b_c]) = b_pf[t];
        }
        __syncthreads();

        if (kt + 16 < K) {
            #pragma unroll
            for (int t = 0; t < 2; t++) {
                a_pf[t] = *reinterpret_cast<const float4*>(
                    &A[(size_t)(brow + a_r0 + t * 64) * K + kt + 16 + a_kc]);
                b_pf[t] = *reinterpret_cast<const float4*>(
                    &B[(size_t)(kt + 16 + b_r0 + t * 8) * N + bcol + b_c]);
            }
        }

        #pragma unroll
        for (int k = 0; k < 16; k++) {
            float4 a0 = *reinterpret_cast<float4*>(&As[k][ty * 4]);
            float4 a1 = *reinterpret_cast<float4*>(&As[k][ty * 4 + 64]);
            float4 b0 = *reinterpret_cast<float4*>(&Bs[k][tx * 4]);
            float4 b1 = *reinterpret_cast<float4*>(&Bs[k][tx * 4 + 64]);
            float ar[8] = {a0.x, a0.y, a0.z, a0.w, a1.x, a1.y, a1.z, a1.w};
            float br[8] = {b0.x, b0.y, b0.z, b0.w, b1.x, b1.y, b1.z, b1.w};
            #pragma unroll
            for (int i = 0; i < 8; i++)
                #pragma unroll
                for (int j = 0; j < 8; j++)
                    acc[i][j] += ar[i] * br[j];
        }
        __syncthreads();
    }

    #pragma unroll
    for (int qi = 0; qi < 2; qi++) {
        #pragma unroll
        for (int qj = 0; qj < 2; qj++) {
            const int c0 = bcol + tx * 4 + qj * 64;
            float4 bb = *reinterpret_cast<const float4*>(&bias[c0]);
            #pragma unroll
            for (int ii = 0; ii < 4; ii++) {
                const int r = brow + ty * 4 + qi * 64 + ii;
                float4 v;
                v.x = acc[qi * 4 + ii][qj * 4 + 0] + bb.x;
                v.y = acc[qi * 4 + ii][qj * 4 + 1] + bb.y;
                v.z = acc[qi * 4 + ii][qj * 4 + 2] + bb.z;
                v.w = acc[qi * 4 + ii][qj * 4 + 3] + bb.w;
                if (act == 1) {
                    v.x *= normcdff(v.x);
                    v.y *= normcdff(v.y);
                    v.z *= normcdff(v.z);
                    v.w *= normcdff(v.w);
                }
                *reinterpret_cast<float4*>(&C[(size_t)r * N + c0]) = v;
            }
        }
    }
}

// ---------------------------------------------------------------------------
// biasT[h][j][i] = table[rpi[i][j]][h]
// ---------------------------------------------------------------------------
__global__ void bias_kernel(const int* __restrict__ rpi,
                            const float* __restrict__ table,
                            float* __restrict__ biasT)
{
    int j  = blockIdx.x;
    int hd = blockIdx.y;
    int i  = threadIdx.x;
    int t  = rpi[i * NTOK + j];
    biasT[((size_t)hd * NTOK + j) * NTOK + i] = table[t * NH + hd];
}

// ---------------------------------------------------------------------------
// Window cosine attention, query-blocked 4x.
// One block per (window, head), 64 threads; thread t owns queries
// t, t+64, t+128, t+192. k/v rows in smem, read ONCE per key and reused
// across 4 queries (4x fewer LDS than 1-query-per-thread).
// Single-pass softmax: logits <= scale + |bias|, shift by `scale`.
// ---------------------------------------------------------------------------
__global__ __launch_bounds__(64) void attn_kernel(
    const float* __restrict__ qkv, const float* __restrict__ biasT,
    const float* __restrict__ logit_scale, float* __restrict__ attn_out)
{
    __shared__ float4 kn[NTOK * 4];  // normalized K rows (16 floats each)
    __shared__ float4 vv[NTOK * 4];  // V rows

    const int wi = blockIdx.x;
    const int hd = blockIdx.y;
    const int t  = threadIdx.x;      // 0..63

    const int bimg = wi / 144;
    const int wrem = wi % 144;
    const int wr = wrem / WPR, wc = wrem % WPR;
    const int rowbase = bimg * (IMG * IMG) + (wr * 16) * IMG + wc * 16;

    const float scale = __expf(fminf(logit_scale[hd], 4.6051702f)); // ln(100)

    int morig[4];
    float q[4][16];

    #pragma unroll
    for (int u = 0; u < 4; u++) {
        const int i = t + 64 * u;
        const int m = rowbase + (i >> 4) * IMG + (i & 15);
        morig[u] = m;
        const float* base = qkv + (size_t)m * 384 + hd * HD;

        // q -> registers, L2-normalize, fold in scale
        const float4* q4 = reinterpret_cast<const float4*>(base);
        float qs = 0.f;
        #pragma unroll
        for (int z = 0; z < 4; z++) {
            float4 v = q4[z];
            q[u][z*4+0] = v.x; q[u][z*4+1] = v.y;
            q[u][z*4+2] = v.z; q[u][z*4+3] = v.w;
            qs += v.x*v.x + v.y*v.y + v.z*v.z + v.w*v.w;
        }
        float qr = scale / fmaxf(sqrtf(qs), 1e-12f);
        #pragma unroll
        for (int z = 0; z < 16; z++) q[u][z] *= qr;

        // k -> normalize -> smem; v -> smem
        const float4* k4 = reinterpret_cast<const float4*>(base + 128);
        float kv[16]; float ks = 0.f;
        #pragma unroll
        for (int z = 0; z < 4; z++) {
            float4 v = k4[z];
            kv[z*4+0] = v.x; kv[z*4+1] = v.y; kv[z*4+2] = v.z; kv[z*4+3] = v.w;
            ks += v.x*v.x + v.y*v.y + v.z*v.z + v.w*v.w;
        }
        float kr = 1.f / fmaxf(sqrtf(ks), 1e-12f);
        #pragma unroll
        for (int z = 0; z < 4; z++)
            kn[i*4+z] = make_float4(kv[z*4+0]*kr, kv[z*4+1]*kr,
                                    kv[z*4+2]*kr, kv[z*4+3]*kr);
        const float4* v4 = reinterpret_cast<const float4*>(base + 256);
        #pragma unroll
        for (int z = 0; z < 4; z++) vv[i*4+z] = v4[z];
    }

    const float* brow = biasT + (size_t)hd * NTOK * NTOK;  // [j*256+i]
    __syncthreads();

    float l[4] = {0.f, 0.f, 0.f, 0.f};
    float acc[4][16];
    #pragma unroll
    for (int u = 0; u < 4; u++)
        #pragma unroll
        for (int z = 0; z < 16; z++) acc[u][z] = 0.f;

    #pragma unroll 1
    for (int j0 = 0; j0 < NTOK; j0 += 2) {
        // batched bias loads for 2 keys x 4 queries (coalesced within warp)
        float bs[2][4];
        #pragma unroll
        for (int w = 0; w < 2; w++)
            #pragma unroll
            for (int u = 0; u < 4; u++)
                bs[w][u] = brow[(j0 + w) * NTOK + t + 64 * u];

        #pragma unroll
        for (int w = 0; w < 2; w++) {
            const int j = j0 + w;
            float4 k0 = kn[j*4+0], k1 = kn[j*4+1], k2 = kn[j*4+2], k3 = kn[j*4+3];
            float4 v0 = vv[j*4+0], v1 = vv[j*4+1], v2 = vv[j*4+2], v3 = vv[j*4+3];
            #pragma unroll
            for (int u = 0; u < 4; u++) {
                float s = q[u][0]*k0.x + q[u][1]*k0.y + q[u][2]*k0.z + q[u][3]*k0.w
                        + q[u][4]*k1.x + q[u][5]*k1.y + q[u][6]*k1.z + q[u][7]*k1.w
                        + q[u][8]*k2.x + q[u][9]*k2.y + q[u][10]*k2.z + q[u][11]*k2.w
                        + q[u][12]*k3.x + q[u][13]*k3.y + q[u][14]*k3.z + q[u][15]*k3.w;
                s += bs[w][u];
                float p = __expf(s - scale);
                l[u] += p;
                acc[u][0]  += p*v0.x; acc[u][1]  += p*v0.y; acc[u][2]  += p*v0.z; acc[u][3]  += p*v0.w;
                acc[u][4]  += p*v1.x; acc[u][5]  += p*v1.y; acc[u][6]  += p*v1.z; acc[u][7]  += p*v1.w;
                acc[u][8]  += p*v2.x; acc[u][9]  += p*v2.y; acc[u][10] += p*v2.z; acc[u][11] += p*v2.w;
                acc[u][12] += p*v3.x; acc[u][13] += p*v3.y; acc[u][14] += p*v3.z; acc[u][15] += p*v3.w;
            }
        }
    }

    #pragma unroll
    for (int u = 0; u < 4; u++) {
        float inv = 1.f / l[u];
        float4* o4 = reinterpret_cast<float4*>(
            attn_out + (size_t)morig[u] * C_DIM + hd * HD);
        #pragma unroll
        for (int z = 0; z < 4; z++)
            o4[z] = make_float4(acc[u][z*4+0]*inv, acc[u][z*4+1]*inv,
                                acc[u][z*4+2]*inv, acc[u][z*4+3]*inv);
    }
}

// ---------------------------------------------------------------------------
// out = res + LayerNorm(in) * w + b   (row length 128, one warp per row)
// ---------------------------------------------------------------------------
__global__ __launch_bounds__(256) void ln_res_kernel(
    const float* __restrict__ inp, const float* __restrict__ res,
    const float* __restrict__ w, const float* __restrict__ b,
    float* __restrict__ out)
{
    int row  = blockIdx.x * 8 + (threadIdx.x >> 5);
    int lane = threadIdx.x & 31;

    const float4 v  = reinterpret_cast<const float4*>(inp + (size_t)row * 128)[lane];
    float s  = v.x + v.y + v.z + v.w;
    float s2 = v.x*v.x + v.y*v.y + v.z*v.z + v.w*v.w;
    #pragma unroll
    for (int off = 16; off > 0; off >>= 1) {
        s  += __shfl_xor_sync(0xffffffffu, s,  off);
        s2 += __shfl_xor_sync(0xffffffffu, s2, off);
    }
    const float mu   = s * (1.f / 128.f);
    const float var  = s2 * (1.f / 128.f) - mu * mu;
    const float rstd = rsqrtf(var + 1e-5f);

    const float4 wv = reinterpret_cast<const float4*>(w)[lane];
    const float4 bv = reinterpret_cast<const float4*>(b)[lane];
    const float4 rv = reinterpret_cast<const float4*>(res + (size_t)row * 128)[lane];
    float4 o;
    o.x = rv.x + (v.x - mu) * rstd * wv.x + bv.x;
    o.y = rv.y + (v.y - mu) * rstd * wv.y + bv.y;
    o.z = rv.z + (v.z - mu) * rstd * wv.z + bv.z;
    o.w = rv.w + (v.w - mu) * rstd * wv.w + bv.w;
    reinterpret_cast<float4*>(out + (size_t)row * 128)[lane] = o;
}

// ---------------------------------------------------------------------------
extern "C" void kernel_launch(void* const* d_in, const int* in_sizes, int n_in,
                              void* d_out, int out_size)
{
    const float* x           = (const float*)d_in[0];
    const float* qkv_w       = (const float*)d_in[1];
    const float* qkv_b       = (const float*)d_in[2];
    const float* proj_w      = (const float*)d_in[3];
    const float* proj_b      = (const float*)d_in[4];
    const float* logit_scale = (const float*)d_in[5];
    const float* rpb_table   = (const float*)d_in[6];
    const float* n1w         = (const float*)d_in[7];
    const float* n1b         = (const float*)d_in[8];
    const float* n2w         = (const float*)d_in[9];
    const float* n2b         = (const float*)d_in[10];
    const float* fc1_w       = (const float*)d_in[11];
    const float* fc1_b       = (const float*)d_in[12];
    const float* fc2_w       = (const float*)d_in[13];
    const float* fc2_b       = (const float*)d_in[14];
    const int*   rpi         = (const int*)d_in[17];
    float* out = (float*)d_out;

    float *p_qkv, *p_biasT, *p_attn, *p_proj, *p_x1, *p_hid, *p_y;
    cudaGetSymbolAddress((void**)&p_qkv,   g_qkv);
    cudaGetSymbolAddress((void**)&p_biasT, g_biasT);
    cudaGetSymbolAddress((void**)&p_attn,  g_attn);
    cudaGetSymbolAddress((void**)&p_proj,  g_proj);
    cudaGetSymbolAddress((void**)&p_x1,    g_x1);
    cudaGetSymbolAddress((void**)&p_hid,   g_hid);
    cudaGetSymbolAddress((void**)&p_y,     g_y);

    bias_kernel<<<dim3(NTOK, NH), NTOK>>>(rpi, rpb_table, p_biasT);

    // QKV: [73728,128] @ [128,384]
    gemm128_kernel<<<dim3(384/128, M_TOK/128), 256>>>(x, qkv_w, qkv_b, p_qkv,
                                                      M_TOK, 384, 128, 0);
    attn_kernel<<<dim3(NWIN, NH), 64>>>(p_qkv, p_biasT, logit_scale, p_attn);

    // proj: [73728,128] @ [128,128]
    gemm128_kernel<<<dim3(128/128, M_TOK/128), 256>>>(p_attn, proj_w, proj_b, p_proj,
                                                      M_TOK, 128, 128, 0);
    ln_res_kernel<<<M_TOK/8, 256>>>(p_proj, x, n1w, n1b, p_x1);

    // fc1 + GELU: [73728,128] @ [128,256]
    gemm128_kernel<<<dim3(256/128, M_TOK/128), 256>>>(p_x1, fc1_w, fc1_b, p_hid,
                                                      M_TOK, 256, 128, 1);
    // fc2: [73728,256] @ [256,128]
    gemm128_kernel<<<dim3(128/128, M_TOK/128), 256>>>(p_hid, fc2_w, fc2_b, p_y,
                                                      M_TOK, 128, 256, 0);

    ln_res_kernel<<<M_TOK/8, 256>>>(p_y, p_x1, n2w, n2b, out);
}

// round 5
// speedup vs baseline: 2.0438x; 1.4957x over previous
#include <cuda_runtime.h>
#include <cuda_fp16.h>
#include <cuda_bf16.h>
#include <math_constants.h>

// ---------------------------------------------------------------------------
// SwinV2 block: window cosine-attention + res-post-norm MLP
// b=2, H=W=192, C=128, WS=16, NH=8, d=16
// GEMMs: fp16 tensor cores (mma.sync m16n8k16), fp32 accumulate.
// ---------------------------------------------------------------------------

#define M_TOK   73728
#define C_DIM   128
#define NH      8
#define HD      16
#define NWIN    288
#define NTOK    256
#define IMG     192
#define WPR     12

typedef unsigned int u32;

__device__ float g_qkv [ (size_t)M_TOK * 384 ];
__device__ float g_biasT[ (size_t)NH * NTOK * NTOK ];  // [h][j][i]
__device__ float g_attn[ (size_t)M_TOK * C_DIM ];
__device__ float g_proj[ (size_t)M_TOK * C_DIM ];
__device__ float g_x1  [ (size_t)M_TOK * C_DIM ];
__device__ float g_hid [ (size_t)M_TOK * 256 ];
__device__ float g_y   [ (size_t)M_TOK * C_DIM ];

// ---------------------------------------------------------------------------
// fp16 tensor-core GEMM: C = act(A[M,K]fp32 @ B[K,N]fp32 + bias), fp32 accum.
// Tile 128x128, BK=32, 8 warps (2m x 4n), warp tile 64x32.
// fp32->fp16 conversion happens while staging gmem->smem.
// act: 0 = none, 1 = exact GELU. M%128==0, N%128==0, K%32==0.
// ---------------------------------------------------------------------------
__global__ __launch_bounds__(256) void hgemm_kernel(
    const float* __restrict__ A, const float* __restrict__ B,
    const float* __restrict__ bias, float* __restrict__ C,
    int M, int N, int K, int act)
{
    __shared__ __half As[128][40];    // [m][k], pad 8 -> conflict-free ldmatrix
    __shared__ __half Bs[32][136];    // [k][n], pad 8 -> conflict-free ldmatrix.trans

    const int tid  = threadIdx.x;
    const int lane = tid & 31;
    const int wid  = tid >> 5;
    const int warp_m = wid >> 2;          // 0..1
    const int warp_n = wid & 3;           // 0..3
    const int brow = blockIdx.y * 128;
    const int bcol = blockIdx.x * 128;

    const int a_m0 = tid >> 3;            // + t*32
    const int a_k4 = (tid & 7) << 2;
    const int b_k0 = tid >> 5;            // + t*8
    const int b_n4 = (tid & 31) << 2;

    const u32 a_smem = (u32)__cvta_generic_to_shared(&As[0][0]);
    const u32 b_smem = (u32)__cvta_generic_to_shared(&Bs[0][0]);

    float acc[4][4][4];
    #pragma unroll
    for (int mi = 0; mi < 4; mi++)
        #pragma unroll
        for (int ni = 0; ni < 4; ni++)
            #pragma unroll
            for (int z = 0; z < 4; z++) acc[mi][ni][z] = 0.f;

    float4 a_pf[4], b_pf[4];
    #pragma unroll
    for (int t = 0; t < 4; t++) {
        a_pf[t] = *reinterpret_cast<const float4*>(
            &A[(size_t)(brow + a_m0 + t * 32) * K + a_k4]);
        b_pf[t] = *reinterpret_cast<const float4*>(
            &B[(size_t)(b_k0 + t * 8) * N + bcol + b_n4]);
    }

    for (int kt = 0; kt < K; kt += 32) {
        #pragma unroll
        for (int t = 0; t < 4; t++) {
            __half2 h0 = __float22half2_rn(make_float2(a_pf[t].x, a_pf[t].y));
            __half2 h1 = __float22half2_rn(make_float2(a_pf[t].z, a_pf[t].w));
            *reinterpret_cast<__half2*>(&As[a_m0 + t * 32][a_k4 + 0]) = h0;
            *reinterpret_cast<__half2*>(&As[a_m0 + t * 32][a_k4 + 2]) = h1;
            __half2 g0 = __float22half2_rn(make_float2(b_pf[t].x, b_pf[t].y));
            __half2 g1 = __float22half2_rn(make_float2(b_pf[t].z, b_pf[t].w));
            *reinterpret_cast<__half2*>(&Bs[b_k0 + t * 8][b_n4 + 0]) = g0;
            *reinterpret_cast<__half2*>(&Bs[b_k0 + t * 8][b_n4 + 2]) = g1;
        }
        __syncthreads();

        if (kt + 32 < K) {
            #pragma unroll
            for (int t = 0; t < 4; t++) {
                a_pf[t] = *reinterpret_cast<const float4*>(
                    &A[(size_t)(brow + a_m0 + t * 32) * K + kt + 32 + a_k4]);
                b_pf[t] = *reinterpret_cast<const float4*>(
                    &B[(size_t)(kt + 32 + b_k0 + t * 8) * N + bcol + b_n4]);
            }
        }

        #pragma unroll
        for (int ks = 0; ks < 32; ks += 16) {
            u32 af[4][4];
            #pragma unroll
            for (int mi = 0; mi < 4; mi++) {
                int r = warp_m * 64 + mi * 16 + (lane & 15);
                int c = ks + ((lane >> 4) << 3);
                u32 addr = a_smem + (u32)(r * 40 + c) * 2u;
                asm volatile(
                    "ldmatrix.sync.aligned.m8n8.x4.shared.b16 {%0,%1,%2,%3}, [%4];"
                    : "=r"(af[mi][0]), "=r"(af[mi][1]), "=r"(af[mi][2]), "=r"(af[mi][3])
                    : "r"(addr));
            }
            u32 bf[4][2];
            #pragma unroll
            for (int p = 0; p < 2; p++) {
                int r = ks + (lane & 15);
                int c = warp_n * 32 + p * 16 + ((lane >> 4) << 3);
                u32 addr = b_smem + (u32)(r * 136 + c) * 2u;
                asm volatile(
                    "ldmatrix.sync.aligned.m8n8.x4.trans.shared.b16 {%0,%1,%2,%3}, [%4];"
                    : "=r"(bf[2*p][0]), "=r"(bf[2*p][1]),
                      "=r"(bf[2*p+1][0]), "=r"(bf[2*p+1][1])
                    : "r"(addr));
            }
            #pragma unroll
            for (int mi = 0; mi < 4; mi++)
                #pragma unroll
                for (int ni = 0; ni < 4; ni++) {
                    asm volatile(
                        "mma.sync.aligned.m16n8k16.row.col.f32.f16.f16.f32 "
                        "{%0,%1,%2,%3}, {%4,%5,%6,%7}, {%8,%9}, {%0,%1,%2,%3};"
                        : "+f"(acc[mi][ni][0]), "+f"(acc[mi][ni][1]),
                          "+f"(acc[mi][ni][2]), "+f"(acc[mi][ni][3])
                        : "r"(af[mi][0]), "r"(af[mi][1]), "r"(af[mi][2]), "r"(af[mi][3]),
                          "r"(bf[ni][0]), "r"(bf[ni][1]));
                }
        }
        __syncthreads();
    }

    #pragma unroll
    for (int mi = 0; mi < 4; mi++) {
        #pragma unroll
        for (int ni = 0; ni < 4; ni++) {
            const int r0 = brow + warp_m * 64 + mi * 16 + (lane >> 2);
            const int c  = bcol + warp_n * 32 + ni * 8 + ((lane & 3) << 1);
            float2 bb = *reinterpret_cast<const float2*>(&bias[c]);
            float2 v0, v1;
            v0.x = acc[mi][ni][0] + bb.x; v0.y = acc[mi][ni][1] + bb.y;
            v1.x = acc[mi][ni][2] + bb.x; v1.y = acc[mi][ni][3] + bb.y;
            if (act == 1) {
                v0.x *= normcdff(v0.x); v0.y *= normcdff(v0.y);
                v1.x *= normcdff(v1.x); v1.y *= normcdff(v1.y);
            }
            *reinterpret_cast<float2*>(&C[(size_t)r0 * N + c])       = v0;
            *reinterpret_cast<float2*>(&C[(size_t)(r0 + 8) * N + c]) = v1;
        }
    }
}

// ---------------------------------------------------------------------------
// biasT[h][j][i] = table[rpi[i][j]][h]
// ---------------------------------------------------------------------------
__global__ void bias_kernel(const int* __restrict__ rpi,
                            const float* __restrict__ table,
                            float* __restrict__ biasT)
{
    int j  = blockIdx.x;
    int hd = blockIdx.y;
    int i  = threadIdx.x;
    int t  = rpi[i * NTOK + j];
    biasT[((size_t)hd * NTOK + j) * NTOK + i] = table[t * NH + hd];
}

// ---------------------------------------------------------------------------
// Window cosine attention, query-blocked 4x (64 threads, 4 queries/thread).
// Single-pass softmax with fixed shift by `scale` (logit upper bound).
// ---------------------------------------------------------------------------
__global__ __launch_bounds__(64) void attn_kernel(
    const float* __restrict__ qkv, const float* __restrict__ biasT,
    const float* __restrict__ logit_scale, float* __restrict__ attn_out)
{
    __shared__ float4 kn[NTOK * 4];
    __shared__ float4 vv[NTOK * 4];

    const int wi = blockIdx.x;
    const int hd = blockIdx.y;
    const int t  = threadIdx.x;

    const int bimg = wi / 144;
    const int wrem = wi % 144;
    const int wr = wrem / WPR, wc = wrem % WPR;
    const int rowbase = bimg * (IMG * IMG) + (wr * 16) * IMG + wc * 16;

    const float scale = __expf(fminf(logit_scale[hd], 4.6051702f));

    int morig[4];
    float q[4][16];

    #pragma unroll
    for (int u = 0; u < 4; u++) {
        const int i = t + 64 * u;
        const int m = rowbase + (i >> 4) * IMG + (i & 15);
        morig[u] = m;
        const float* base = qkv + (size_t)m * 384 + hd * HD;

        const float4* q4 = reinterpret_cast<const float4*>(base);
        float qs = 0.f;
        #pragma unroll
        for (int z = 0; z < 4; z++) {
            float4 v = q4[z];
            q[u][z*4+0] = v.x; q[u][z*4+1] = v.y;
            q[u][z*4+2] = v.z; q[u][z*4+3] = v.w;
            qs += v.x*v.x + v.y*v.y + v.z*v.z + v.w*v.w;
        }
        float qr = scale / fmaxf(sqrtf(qs), 1e-12f);
        #pragma unroll
        for (int z = 0; z < 16; z++) q[u][z] *= qr;

        const float4* k4 = reinterpret_cast<const float4*>(base + 128);
        float kv[16]; float ks = 0.f;
        #pragma unroll
        for (int z = 0; z < 4; z++) {
            float4 v = k4[z];
            kv[z*4+0] = v.x; kv[z*4+1] = v.y; kv[z*4+2] = v.z; kv[z*4+3] = v.w;
            ks += v.x*v.x + v.y*v.y + v.z*v.z + v.w*v.w;
        }
        float kr = 1.f / fmaxf(sqrtf(ks), 1e-12f);
        #pragma unroll
        for (int z = 0; z < 4; z++)
            kn[i*4+z] = make_float4(kv[z*4+0]*kr, kv[z*4+1]*kr,
                                    kv[z*4+2]*kr, kv[z*4+3]*kr);
        const float4* v4 = reinterpret_cast<const float4*>(base + 256);
        #pragma unroll
        for (int z = 0; z < 4; z++) vv[i*4+z] = v4[z];
    }

    const float* brow = biasT + (size_t)hd * NTOK * NTOK;
    __syncthreads();

    float l[4] = {0.f, 0.f, 0.f, 0.f};
    float acc[4][16];
    #pragma unroll
    for (int u = 0; u < 4; u++)
        #pragma unroll
        for (int z = 0; z < 16; z++) acc[u][z] = 0.f;

    #pragma unroll 1
    for (int j0 = 0; j0 < NTOK; j0 += 2) {
        float bs[2][4];
        #pragma unroll
        for (int w = 0; w < 2; w++)
            #pragma unroll
            for (int u = 0; u < 4; u++)
                bs[w][u] = brow[(j0 + w) * NTOK + t + 64 * u];

        #pragma unroll
        for (int w = 0; w < 2; w++) {
            const int j = j0 + w;
            float4 k0 = kn[j*4+0], k1 = kn[j*4+1], k2 = kn[j*4+2], k3 = kn[j*4+3];
            float4 v0 = vv[j*4+0], v1 = vv[j*4+1], v2 = vv[j*4+2], v3 = vv[j*4+3];
            #pragma unroll
            for (int u = 0; u < 4; u++) {
                float s = q[u][0]*k0.x + q[u][1]*k0.y + q[u][2]*k0.z + q[u][3]*k0.w
                        + q[u][4]*k1.x + q[u][5]*k1.y + q[u][6]*k1.z + q[u][7]*k1.w
                        + q[u][8]*k2.x + q[u][9]*k2.y + q[u][10]*k2.z + q[u][11]*k2.w
                        + q[u][12]*k3.x + q[u][13]*k3.y + q[u][14]*k3.z + q[u][15]*k3.w;
                s += bs[w][u];
                float p = __expf(s - scale);
                l[u] += p;
                acc[u][0]  += p*v0.x; acc[u][1]  += p*v0.y; acc[u][2]  += p*v0.z; acc[u][3]  += p*v0.w;
                acc[u][4]  += p*v1.x; acc[u][5]  += p*v1.y; acc[u][6]  += p*v1.z; acc[u][7]  += p*v1.w;
                acc[u][8]  += p*v2.x; acc[u][9]  += p*v2.y; acc[u][10] += p*v2.z; acc[u][11] += p*v2.w;
                acc[u][12] += p*v3.x; acc[u][13] += p*v3.y; acc[u][14] += p*v3.z; acc[u][15] += p*v3.w;
            }
        }
    }

    #pragma unroll
    for (int u = 0; u < 4; u++) {
        float inv = 1.f / l[u];
        float4* o4 = reinterpret_cast<float4*>(
            attn_out + (size_t)morig[u] * C_DIM + hd * HD);
        #pragma unroll
        for (int z = 0; z < 4; z++)
            o4[z] = make_float4(acc[u][z*4+0]*inv, acc[u][z*4+1]*inv,
                                acc[u][z*4+2]*inv, acc[u][z*4+3]*inv);
    }
}

// ---------------------------------------------------------------------------
// out = res + LayerNorm(in) * w + b
// ---------------------------------------------------------------------------
__global__ __launch_bounds__(256) void ln_res_kernel(
    const float* __restrict__ inp, const float* __restrict__ res,
    const float* __restrict__ w, const float* __restrict__ b,
    float* __restrict__ out)
{
    int row  = blockIdx.x * 8 + (threadIdx.x >> 5);
    int lane = threadIdx.x & 31;

    const float4 v  = reinterpret_cast<const float4*>(inp + (size_t)row * 128)[lane];
    float s  = v.x + v.y + v.z + v.w;
    float s2 = v.x*v.x + v.y*v.y + v.z*v.z + v.w*v.w;
    #pragma unroll
    for (int off = 16; off > 0; off >>= 1) {
        s  += __shfl_xor_sync(0xffffffffu, s,  off);
        s2 += __shfl_xor_sync(0xffffffffu, s2, off);
    }
    const float mu   = s * (1.f / 128.f);
    const float var  = s2 * (1.f / 128.f) - mu * mu;
    const float rstd = rsqrtf(var + 1e-5f);

    const float4 wv = reinterpret_cast<const float4*>(w)[lane];
    const float4 bv = reinterpret_cast<const float4*>(b)[lane];
    const float4 rv = reinterpret_cast<const float4*>(res + (size_t)row * 128)[lane];
    float4 o;
    o.x = rv.x + (v.x - mu) * rstd * wv.x + bv.x;
    o.y = rv.y + (v.y - mu) * rstd * wv.y + bv.y;
    o.z = rv.z + (v.z - mu) * rstd * wv.z + bv.z;
    o.w = rv.w + (v.w - mu) * rstd * wv.w + bv.w;
    reinterpret_cast<float4*>(out + (size_t)row * 128)[lane] = o;
}

// ---------------------------------------------------------------------------
extern "C" void kernel_launch(void* const* d_in, const int* in_sizes, int n_in,
                              void* d_out, int out_size)
{
    const float* x           = (const float*)d_in[0];
    const float* qkv_w       = (const float*)d_in[1];
    const float* qkv_b       = (const float*)d_in[2];
    const float* proj_w      = (const float*)d_in[3];
    const float* proj_b      = (const float*)d_in[4];
    const float* logit_scale = (const float*)d_in[5];
    const float* rpb_table   = (const float*)d_in[6];
    const float* n1w         = (const float*)d_in[7];
    const float* n1b         = (const float*)d_in[8];
    const float* n2w         = (const float*)d_in[9];
    const float* n2b         = (const float*)d_in[10];
    const float* fc1_w       = (const float*)d_in[11];
    const float* fc1_b       = (const float*)d_in[12];
    const float* fc2_w       = (const float*)d_in[13];
    const float* fc2_b       = (const float*)d_in[14];
    const int*   rpi         = (const int*)d_in[17];
    float* out = (float*)d_out;

    float *p_qkv, *p_biasT, *p_attn, *p_proj, *p_x1, *p_hid, *p_y;
    cudaGetSymbolAddress((void**)&p_qkv,   g_qkv);
    cudaGetSymbolAddress((void**)&p_biasT, g_biasT);
    cudaGetSymbolAddress((void**)&p_attn,  g_attn);
    cudaGetSymbolAddress((void**)&p_proj,  g_proj);
    cudaGetSymbolAddress((void**)&p_x1,    g_x1);
    cudaGetSymbolAddress((void**)&p_hid,   g_hid);
    cudaGetSymbolAddress((void**)&p_y,     g_y);

    bias_kernel<<<dim3(NTOK, NH), NTOK>>>(rpi, rpb_table, p_biasT);

    // QKV: [73728,128] @ [128,384]
    hgemm_kernel<<<dim3(384/128, M_TOK/128), 256>>>(x, qkv_w, qkv_b, p_qkv,
                                                    M_TOK, 384, 128, 0);
    attn_kernel<<<dim3(NWIN, NH), 64>>>(p_qkv, p_biasT, logit_scale, p_attn);

    // proj: [73728,128] @ [128,128]
    hgemm_kernel<<<dim3(128/128, M_TOK/128), 256>>>(p_attn, proj_w, proj_b, p_proj,
                                                    M_TOK, 128, 128, 0);
    ln_res_kernel<<<M_TOK/8, 256>>>(p_proj, x, n1w, n1b, p_x1);

    // fc1 + GELU: [73728,128] @ [128,256]
    hgemm_kernel<<<dim3(256/128, M_TOK/128), 256>>>(p_x1, fc1_w, fc1_b, p_hid,
                                                    M_TOK, 256, 128, 1);
    // fc2: [73728,256] @ [256,128]
    hgemm_kernel<<<dim3(128/128, M_TOK/128), 256>>>(p_hid, fc2_w, fc2_b, p_y,
                                                    M_TOK, 128, 256, 0);

    ln_res_kernel<<<M_TOK/8, 256>>>(p_y, p_x1, n2w, n2b, out);
}

// round 6
// speedup vs baseline: 3.0836x; 1.5088x over previous
#include <cuda_runtime.h>
#include <cuda_fp16.h>
#include <cuda_bf16.h>
#include <math_constants.h>

// ---------------------------------------------------------------------------
// SwinV2 block: window cosine-attention + res-post-norm MLP
// b=2, H=W=192, C=128, WS=16, NH=8, d=16
// GEMMs + attention on fp16 tensor cores (mma.sync m16n8k16), fp32 accumulate.
// Attention scores use hi/lo fp16 splitting => fp32-accurate logits.
// ---------------------------------------------------------------------------

#define M_TOK   73728
#define C_DIM   128
#define NH      8
#define HD      16
#define NWIN    288
#define NTOK    256
#define IMG     192
#define WPR     12

typedef unsigned int u32;

__device__ float g_qkv [ (size_t)M_TOK * 384 ];
__device__ uint2 g_biasF[ (size_t)NH * 16 * 32 * 32 ];   // C-fragment layout, 1MB
__device__ float g_attn[ (size_t)M_TOK * C_DIM ];
__device__ float g_proj[ (size_t)M_TOK * C_DIM ];
__device__ float g_x1  [ (size_t)M_TOK * C_DIM ];
__device__ float g_hid [ (size_t)M_TOK * 256 ];
__device__ float g_y   [ (size_t)M_TOK * C_DIM ];

#define MMA16816(d0,d1,d2,d3,a0,a1,a2,a3,b0,b1)                          \
    asm volatile(                                                        \
        "mma.sync.aligned.m16n8k16.row.col.f32.f16.f16.f32 "             \
        "{%0,%1,%2,%3}, {%4,%5,%6,%7}, {%8,%9}, {%0,%1,%2,%3};"          \
        : "+f"(d0), "+f"(d1), "+f"(d2), "+f"(d3)                         \
        : "r"(a0), "r"(a1), "r"(a2), "r"(a3), "r"(b0), "r"(b1))

// ---------------------------------------------------------------------------
// fp16 tensor-core GEMM: C = act(A[M,K]fp32 @ B[K,N]fp32 + bias), fp32 accum.
// Tile 128x128, BK=32, 8 warps (2m x 4n), warp tile 64x32.
// ---------------------------------------------------------------------------
__global__ __launch_bounds__(256) void hgemm_kernel(
    const float* __restrict__ A, const float* __restrict__ B,
    const float* __restrict__ bias, float* __restrict__ C,
    int M, int N, int K, int act)
{
    __shared__ __half As[128][40];
    __shared__ __half Bs[32][136];

    const int tid  = threadIdx.x;
    const int lane = tid & 31;
    const int wid  = tid >> 5;
    const int warp_m = wid >> 2;
    const int warp_n = wid & 3;
    const int brow = blockIdx.y * 128;
    const int bcol = blockIdx.x * 128;

    const int a_m0 = tid >> 3;
    const int a_k4 = (tid & 7) << 2;
    const int b_k0 = tid >> 5;
    const int b_n4 = (tid & 31) << 2;

    const u32 a_smem = (u32)__cvta_generic_to_shared(&As[0][0]);
    const u32 b_smem = (u32)__cvta_generic_to_shared(&Bs[0][0]);

    float acc[4][4][4];
    #pragma unroll
    for (int mi = 0; mi < 4; mi++)
        #pragma unroll
        for (int ni = 0; ni < 4; ni++)
            #pragma unroll
            for (int z = 0; z < 4; z++) acc[mi][ni][z] = 0.f;

    float4 a_pf[4], b_pf[4];
    #pragma unroll
    for (int t = 0; t < 4; t++) {
        a_pf[t] = *reinterpret_cast<const float4*>(
            &A[(size_t)(brow + a_m0 + t * 32) * K + a_k4]);
        b_pf[t] = *reinterpret_cast<const float4*>(
            &B[(size_t)(b_k0 + t * 8) * N + bcol + b_n4]);
    }

    for (int kt = 0; kt < K; kt += 32) {
        #pragma unroll
        for (int t = 0; t < 4; t++) {
            __half2 h0 = __float22half2_rn(make_float2(a_pf[t].x, a_pf[t].y));
            __half2 h1 = __float22half2_rn(make_float2(a_pf[t].z, a_pf[t].w));
            *reinterpret_cast<__half2*>(&As[a_m0 + t * 32][a_k4 + 0]) = h0;
            *reinterpret_cast<__half2*>(&As[a_m0 + t * 32][a_k4 + 2]) = h1;
            __half2 g0 = __float22half2_rn(make_float2(b_pf[t].x, b_pf[t].y));
            __half2 g1 = __float22half2_rn(make_float2(b_pf[t].z, b_pf[t].w));
            *reinterpret_cast<__half2*>(&Bs[b_k0 + t * 8][b_n4 + 0]) = g0;
            *reinterpret_cast<__half2*>(&Bs[b_k0 + t * 8][b_n4 + 2]) = g1;
        }
        __syncthreads();

        if (kt + 32 < K) {
            #pragma unroll
            for (int t = 0; t < 4; t++) {
                a_pf[t] = *reinterpret_cast<const float4*>(
                    &A[(size_t)(brow + a_m0 + t * 32) * K + kt + 32 + a_k4]);
                b_pf[t] = *reinterpret_cast<const float4*>(
                    &B[(size_t)(kt + 32 + b_k0 + t * 8) * N + bcol + b_n4]);
            }
        }

        #pragma unroll
        for (int ks = 0; ks < 32; ks += 16) {
            u32 af[4][4];
            #pragma unroll
            for (int mi = 0; mi < 4; mi++) {
                int r = warp_m * 64 + mi * 16 + (lane & 15);
                int c = ks + ((lane >> 4) << 3);
                u32 addr = a_smem + (u32)(r * 40 + c) * 2u;
                asm volatile(
                    "ldmatrix.sync.aligned.m8n8.x4.shared.b16 {%0,%1,%2,%3}, [%4];"
                    : "=r"(af[mi][0]), "=r"(af[mi][1]), "=r"(af[mi][2]), "=r"(af[mi][3])
                    : "r"(addr));
            }
            u32 bf[4][2];
            #pragma unroll
            for (int p = 0; p < 2; p++) {
                int r = ks + (lane & 15);
                int c = warp_n * 32 + p * 16 + ((lane >> 4) << 3);
                u32 addr = b_smem + (u32)(r * 136 + c) * 2u;
                asm volatile(
                    "ldmatrix.sync.aligned.m8n8.x4.trans.shared.b16 {%0,%1,%2,%3}, [%4];"
                    : "=r"(bf[2*p][0]), "=r"(bf[2*p][1]),
                      "=r"(bf[2*p+1][0]), "=r"(bf[2*p+1][1])
                    : "r"(addr));
            }
            #pragma unroll
            for (int mi = 0; mi < 4; mi++)
                #pragma unroll
                for (int ni = 0; ni < 4; ni++) {
                    MMA16816(acc[mi][ni][0], acc[mi][ni][1],
                             acc[mi][ni][2], acc[mi][ni][3],
                             af[mi][0], af[mi][1], af[mi][2], af[mi][3],
                             bf[ni][0], bf[ni][1]);
                }
        }
        __syncthreads();
    }

    #pragma unroll
    for (int mi = 0; mi < 4; mi++) {
        #pragma unroll
        for (int ni = 0; ni < 4; ni++) {
            const int r0 = brow + warp_m * 64 + mi * 16 + (lane >> 2);
            const int c  = bcol + warp_n * 32 + ni * 8 + ((lane & 3) << 1);
            float2 bb = *reinterpret_cast<const float2*>(&bias[c]);
            float2 v0, v1;
            v0.x = acc[mi][ni][0] + bb.x; v0.y = acc[mi][ni][1] + bb.y;
            v1.x = acc[mi][ni][2] + bb.x; v1.y = acc[mi][ni][3] + bb.y;
            if (act == 1) {
                v0.x *= normcdff(v0.x); v0.y *= normcdff(v0.y);
                v1.x *= normcdff(v1.x); v1.y *= normcdff(v1.y);
            }
            *reinterpret_cast<float2*>(&C[(size_t)r0 * N + c])       = v0;
            *reinterpret_cast<float2*>(&C[(size_t)(r0 + 8) * N + c]) = v1;
        }
    }
}

// ---------------------------------------------------------------------------
// Bias in mma C-fragment layout:
// biasF[((h*16+qb)*32+jt)*32+lane] = {half2(b(i0+g,j0+2t), b(i0+g,j0+2t+1)),
//                                     half2(b(i0+g+8,..),  b(i0+g+8,..+1))}
// with b(i,j) = table[rpi[i][j]][h], i0=qb*16, j0=jt*8, g=lane>>2, t=lane&3.
// ---------------------------------------------------------------------------
__global__ void biasf_kernel(const int* __restrict__ rpi,
                             const float* __restrict__ table,
                             uint2* __restrict__ biasF)
{
    const int qb = blockIdx.x >> 5;
    const int jt = blockIdx.x & 31;
    const int hd = blockIdx.y;
    const int lane = threadIdx.x;
    const int g = lane >> 2, t = lane & 3;
    const int i0 = qb * 16, j0 = jt * 8;

    float b00 = table[rpi[(i0 + g)     * NTOK + j0 + 2*t    ] * NH + hd];
    float b01 = table[rpi[(i0 + g)     * NTOK + j0 + 2*t + 1] * NH + hd];
    float b10 = table[rpi[(i0 + g + 8) * NTOK + j0 + 2*t    ] * NH + hd];
    float b11 = table[rpi[(i0 + g + 8) * NTOK + j0 + 2*t + 1] * NH + hd];

    uint2 r;
    *reinterpret_cast<__half2*>(&r.x) = __floats2half2_rn(b00, b01);
    *reinterpret_cast<__half2*>(&r.y) = __floats2half2_rn(b10, b11);
    biasF[((size_t)(hd * 16 + qb) * 32 + jt) * 32 + lane] = r;
}

// ---------------------------------------------------------------------------
// Tensor-core window attention. Block = (window, head), 128 threads (4 warps).
// smem (halfs): Qh/Ql/Kh/Kl [256][24], Vth/Vtl [16][264].
// Warp w handles query blocks 4w..4w+3 (16 rows each).
// S = qh*kh + qh*kl + ql*kh (fp32 accum) => logits accurate to ~1e-6.
// P -> fp16 A-fragments (register repack), PV = p*vh + p*vl.
// Single-pass softmax shifted by `scale` (logit upper bound).
// ---------------------------------------------------------------------------
#define SQH  0
#define SQL  (256*24)
#define SKH  (2*256*24)
#define SKL  (3*256*24)
#define SVTH (4*256*24)
#define SVTL (4*256*24 + 16*264)
#define ATTN_SMEM_HALFS (4*256*24 + 2*16*264)

__global__ __launch_bounds__(128) void attn_tc_kernel(
    const float* __restrict__ qkv, const uint2* __restrict__ biasF,
    const float* __restrict__ logit_scale, float* __restrict__ attn_out)
{
    extern __shared__ __half sm[];

    const int wi = blockIdx.x;
    const int hd = blockIdx.y;
    const int tid = threadIdx.x;

    const int bimg = wi / 144;
    const int wrem = wi % 144;
    const int wr = wrem / WPR, wc = wrem % WPR;
    const int rowbase = bimg * (IMG * IMG) + (wr * 16) * IMG + wc * 16;

    const float scale = __expf(fminf(logit_scale[hd], 4.6051702f)); // ln(100)

    // ---- stage q (normalized*scale, split), k (normalized, split), v (split, transposed)
    for (int tok = tid; tok < NTOK; tok += 128) {
        const int m = rowbase + (tok >> 4) * IMG + (tok & 15);
        const float* base = qkv + (size_t)m * 384 + hd * HD;

        float q[16], k[16], v[16];
        float qs = 0.f, ks = 0.f;
        #pragma unroll
        for (int z = 0; z < 4; z++) {
            float4 a = reinterpret_cast<const float4*>(base)[z];
            q[z*4+0]=a.x; q[z*4+1]=a.y; q[z*4+2]=a.z; q[z*4+3]=a.w;
            qs += a.x*a.x + a.y*a.y + a.z*a.z + a.w*a.w;
            float4 b = reinterpret_cast<const float4*>(base + 128)[z];
            k[z*4+0]=b.x; k[z*4+1]=b.y; k[z*4+2]=b.z; k[z*4+3]=b.w;
            ks += b.x*b.x + b.y*b.y + b.z*b.z + b.w*b.w;
            float4 c = reinterpret_cast<const float4*>(base + 256)[z];
            v[z*4+0]=c.x; v[z*4+1]=c.y; v[z*4+2]=c.z; v[z*4+3]=c.w;
        }
        const float qr = scale / fmaxf(sqrtf(qs), 1e-12f);
        const float kr = 1.f  / fmaxf(sqrtf(ks), 1e-12f);
        #pragma unroll
        for (int z = 0; z < 16; z++) {
            float qv = q[z] * qr;
            __half qh = __float2half_rn(qv);
            sm[SQH + tok*24 + z] = qh;
            sm[SQL + tok*24 + z] = __float2half_rn(qv - __half2float(qh));
            float kv = k[z] * kr;
            __half kh = __float2half_rn(kv);
            sm[SKH + tok*24 + z] = kh;
            sm[SKL + tok*24 + z] = __float2half_rn(kv - __half2float(kh));
            __half vh = __float2half_rn(v[z]);
            sm[SVTH + z*264 + tok] = vh;
            sm[SVTL + z*264 + tok] = __float2half_rn(v[z] - __half2float(vh));
        }
    }
    __syncthreads();

    const int warp = tid >> 5;
    const int lane = tid & 31;
    const int g = lane >> 2;
    const int t = lane & 3;

    for (int qi = 0; qi < 4; qi++) {
        const int qb = warp * 4 + qi;
        const int i0 = qb * 16;
        const int r0 = i0 + g, r1 = i0 + g + 8;

        // Q A-fragments (hi, lo)
        u32 qa[4], la[4];
        qa[0] = *reinterpret_cast<u32*>(&sm[SQH + r0*24 + 2*t]);
        qa[1] = *reinterpret_cast<u32*>(&sm[SQH + r1*24 + 2*t]);
        qa[2] = *reinterpret_cast<u32*>(&sm[SQH + r0*24 + 2*t + 8]);
        qa[3] = *reinterpret_cast<u32*>(&sm[SQH + r1*24 + 2*t + 8]);
        la[0] = *reinterpret_cast<u32*>(&sm[SQL + r0*24 + 2*t]);
        la[1] = *reinterpret_cast<u32*>(&sm[SQL + r1*24 + 2*t]);
        la[2] = *reinterpret_cast<u32*>(&sm[SQL + r0*24 + 2*t + 8]);
        la[3] = *reinterpret_cast<u32*>(&sm[SQL + r1*24 + 2*t + 8]);

        float o0[4] = {0.f,0.f,0.f,0.f};   // ntile 0 (d 0-7)
        float o1[4] = {0.f,0.f,0.f,0.f};   // ntile 1 (d 8-15)
        float l0 = 0.f, l1 = 0.f;

        const uint2* bp = biasF + ((size_t)(hd * 16 + qb) * 32) * 32 + lane;

        uint2 bcur[8], bnxt[8];
        #pragma unroll
        for (int u = 0; u < 8; u++) bcur[u] = __ldg(&bp[u * 32]);

        u32 pa0 = 0, pa1 = 0;   // P frag halves from even jtile

        #pragma unroll 1
        for (int bt = 0; bt < 4; bt++) {
            if (bt < 3) {
                #pragma unroll
                for (int u = 0; u < 8; u++)
                    bnxt[u] = __ldg(&bp[(bt * 8 + 8 + u) * 32]);
            }
            #pragma unroll
            for (int u = 0; u < 8; u++) {
                const int jt = bt * 8 + u;
                const int j0 = jt * 8;

                u32 kh0 = *reinterpret_cast<u32*>(&sm[SKH + (j0+g)*24 + 2*t]);
                u32 kh1 = *reinterpret_cast<u32*>(&sm[SKH + (j0+g)*24 + 2*t + 8]);
                u32 kl0 = *reinterpret_cast<u32*>(&sm[SKL + (j0+g)*24 + 2*t]);
                u32 kl1 = *reinterpret_cast<u32*>(&sm[SKL + (j0+g)*24 + 2*t + 8]);

                float s0 = 0.f, s1 = 0.f, s2 = 0.f, s3 = 0.f;
                MMA16816(s0,s1,s2,s3, qa[0],qa[1],qa[2],qa[3], kh0,kh1);
                MMA16816(s0,s1,s2,s3, qa[0],qa[1],qa[2],qa[3], kl0,kl1);
                MMA16816(s0,s1,s2,s3, la[0],la[1],la[2],la[3], kh0,kh1);

                uint2 bb = bcur[u];
                float2 blo = __half22float2(*reinterpret_cast<__half2*>(&bb.x));
                float2 bhi = __half22float2(*reinterpret_cast<__half2*>(&bb.y));
                float p0 = __expf(s0 + blo.x - scale);
                float p1 = __expf(s1 + blo.y - scale);
                float p2 = __expf(s2 + bhi.x - scale);
                float p3 = __expf(s3 + bhi.y - scale);
                l0 += p0 + p1;
                l1 += p2 + p3;
                __half2 plo = __floats2half2_rn(p0, p1);
                __half2 phi = __floats2half2_rn(p2, p3);

                if ((u & 1) == 0) {
                    pa0 = *reinterpret_cast<u32*>(&plo);
                    pa1 = *reinterpret_cast<u32*>(&phi);
                } else {
                    u32 pa2 = *reinterpret_cast<u32*>(&plo);
                    u32 pa3 = *reinterpret_cast<u32*>(&phi);
                    const int jb = (jt - 1) * 8;   // base key of this k-step
                    // ntile 0
                    u32 vh0 = *reinterpret_cast<u32*>(&sm[SVTH + g*264 + jb + 2*t]);
                    u32 vh1 = *reinterpret_cast<u32*>(&sm[SVTH + g*264 + jb + 2*t + 8]);
                    u32 vl0 = *reinterpret_cast<u32*>(&sm[SVTL + g*264 + jb + 2*t]);
                    u32 vl1 = *reinterpret_cast<u32*>(&sm[SVTL + g*264 + jb + 2*t + 8]);
                    MMA16816(o0[0],o0[1],o0[2],o0[3], pa0,pa1,pa2,pa3, vh0,vh1);
                    MMA16816(o0[0],o0[1],o0[2],o0[3], pa0,pa1,pa2,pa3, vl0,vl1);
                    // ntile 1
                    u32 wh0 = *reinterpret_cast<u32*>(&sm[SVTH + (8+g)*264 + jb + 2*t]);
                    u32 wh1 = *reinterpret_cast<u32*>(&sm[SVTH + (8+g)*264 + jb + 2*t + 8]);
                    u32 wl0 = *reinterpret_cast<u32*>(&sm[SVTL + (8+g)*264 + jb + 2*t]);
                    u32 wl1 = *reinterpret_cast<u32*>(&sm[SVTL + (8+g)*264 + jb + 2*t + 8]);
                    MMA16816(o1[0],o1[1],o1[2],o1[3], pa0,pa1,pa2,pa3, wh0,wh1);
                    MMA16816(o1[0],o1[1],o1[2],o1[3], pa0,pa1,pa2,pa3, wl0,wl1);
                }
            }
            #pragma unroll
            for (int u = 0; u < 8; u++) bcur[u] = bnxt[u];
        }

        // row-sum reduction across the 4 threads of each group
        l0 += __shfl_xor_sync(0xffffffffu, l0, 1);
        l0 += __shfl_xor_sync(0xffffffffu, l0, 2);
        l1 += __shfl_xor_sync(0xffffffffu, l1, 1);
        l1 += __shfl_xor_sync(0xffffffffu, l1, 2);
        const float inv0 = 1.f / l0, inv1 = 1.f / l1;

        const int m0 = rowbase + (r0 >> 4) * IMG + (r0 & 15);
        const int m1 = rowbase + (r1 >> 4) * IMG + (r1 & 15);
        const int col = hd * HD + 2 * t;
        float2 w00 = make_float2(o0[0] * inv0, o0[1] * inv0);
        float2 w01 = make_float2(o0[2] * inv1, o0[3] * inv1);
        float2 w10 = make_float2(o1[0] * inv0, o1[1] * inv0);
        float2 w11 = make_float2(o1[2] * inv1, o1[3] * inv1);
        *reinterpret_cast<float2*>(&attn_out[(size_t)m0 * C_DIM + col])     = w00;
        *reinterpret_cast<float2*>(&attn_out[(size_t)m1 * C_DIM + col])     = w01;
        *reinterpret_cast<float2*>(&attn_out[(size_t)m0 * C_DIM + col + 8]) = w10;
        *reinterpret_cast<float2*>(&attn_out[(size_t)m1 * C_DIM + col + 8]) = w11;
    }
}

// ---------------------------------------------------------------------------
// out = res + LayerNorm(in) * w + b
// ---------------------------------------------------------------------------
__global__ __launch_bounds__(256) void ln_res_kernel(
    const float* __restrict__ inp, const float* __restrict__ res,
    const float* __restrict__ w, const float* __restrict__ b,
    float* __restrict__ out)
{
    int row  = blockIdx.x * 8 + (threadIdx.x >> 5);
    int lane = threadIdx.x & 31;

    const float4 v  = reinterpret_cast<const float4*>(inp + (size_t)row * 128)[lane];
    float s  = v.x + v.y + v.z + v.w;
    float s2 = v.x*v.x + v.y*v.y + v.z*v.z + v.w*v.w;
    #pragma unroll
    for (int off = 16; off > 0; off >>= 1) {
        s  += __shfl_xor_sync(0xffffffffu, s,  off);
        s2 += __shfl_xor_sync(0xffffffffu, s2, off);
    }
    const float mu   = s * (1.f / 128.f);
    const float var  = s2 * (1.f / 128.f) - mu * mu;
    const float rstd = rsqrtf(var + 1e-5f);

    const float4 wv = reinterpret_cast<const float4*>(w)[lane];
    const float4 bv = reinterpret_cast<const float4*>(b)[lane];
    const float4 rv = reinterpret_cast<const float4*>(res + (size_t)row * 128)[lane];
    float4 o;
    o.x = rv.x + (v.x - mu) * rstd * wv.x + bv.x;
    o.y = rv.y + (v.y - mu) * rstd * wv.y + bv.y;
    o.z = rv.z + (v.z - mu) * rstd * wv.z + bv.z;
    o.w = rv.w + (v.w - mu) * rstd * wv.w + bv.w;
    reinterpret_cast<float4*>(out + (size_t)row * 128)[lane] = o;
}

// ---------------------------------------------------------------------------
extern "C" void kernel_launch(void* const* d_in, const int* in_sizes, int n_in,
                              void* d_out, int out_size)
{
    const float* x           = (const float*)d_in[0];
    const float* qkv_w       = (const float*)d_in[1];
    const float* qkv_b       = (const float*)d_in[2];
    const float* proj_w      = (const float*)d_in[3];
    const float* proj_b      = (const float*)d_in[4];
    const float* logit_scale = (const float*)d_in[5];
    const float* rpb_table   = (const float*)d_in[6];
    const float* n1w         = (const float*)d_in[7];
    const float* n1b         = (const float*)d_in[8];
    const float* n2w         = (const float*)d_in[9];
    const float* n2b         = (const float*)d_in[10];
    const float* fc1_w       = (const float*)d_in[11];
    const float* fc1_b       = (const float*)d_in[12];
    const float* fc2_w       = (const float*)d_in[13];
    const float* fc2_b       = (const float*)d_in[14];
    const int*   rpi         = (const int*)d_in[17];
    float* out = (float*)d_out;

    float *p_qkv, *p_attn, *p_proj, *p_x1, *p_hid, *p_y;
    uint2 *p_biasF;
    cudaGetSymbolAddress((void**)&p_qkv,   g_qkv);
    cudaGetSymbolAddress((void**)&p_biasF, g_biasF);
    cudaGetSymbolAddress((void**)&p_attn,  g_attn);
    cudaGetSymbolAddress((void**)&p_proj,  g_proj);
    cudaGetSymbolAddress((void**)&p_x1,    g_x1);
    cudaGetSymbolAddress((void**)&p_hid,   g_hid);
    cudaGetSymbolAddress((void**)&p_y,     g_y);

    const int attn_smem = ATTN_SMEM_HALFS * 2;   // 66048 bytes
    cudaFuncSetAttribute(attn_tc_kernel,
                         cudaFuncAttributeMaxDynamicSharedMemorySize, attn_smem);

    // 1) bias fragments
    biasf_kernel<<<dim3(16 * 32, NH), 32>>>(rpi, rpb_table, p_biasF);

    // 2) QKV: [73728,128] @ [128,384]
    hgemm_kernel<<<dim3(384/128, M_TOK/128), 256>>>(x, qkv_w, qkv_b, p_qkv,
                                                    M_TOK, 384, 128, 0);
    // 3) tensor-core window attention
    attn_tc_kernel<<<dim3(NWIN, NH), 128, attn_smem>>>(p_qkv, p_biasF,
                                                       logit_scale, p_attn);
    // 4) proj: [73728,128] @ [128,128]
    hgemm_kernel<<<dim3(128/128, M_TOK/128), 256>>>(p_attn, proj_w, proj_b, p_proj,
                                                    M_TOK, 128, 128, 0);
    // 5) x1 = x + LN(proj)
    ln_res_kernel<<<M_TOK/8, 256>>>(p_proj, x, n1w, n1b, p_x1);

    // 6) fc1 + GELU: [73728,128] @ [128,256]
    hgemm_kernel<<<dim3(256/128, M_TOK/128), 256>>>(p_x1, fc1_w, fc1_b, p_hid,
                                                    M_TOK, 256, 128, 1);
    // 7) fc2: [73728,256] @ [256,128]
    hgemm_kernel<<<dim3(128/128, M_TOK/128), 256>>>(p_hid, fc2_w, fc2_b, p_y,
                                                    M_TOK, 128, 256, 0);

    // 8) out = x1 + LN(y)
    ln_res_kernel<<<M_TOK/8, 256>>>(p_y, p_x1, n2w, n2b, out);
}

// round 7
// speedup vs baseline: 3.3691x; 1.0926x over previous
#include <cuda_runtime.h>
#include <cuda_fp16.h>
#include <cuda_bf16.h>
#include <math_constants.h>

// ---------------------------------------------------------------------------
// SwinV2 block: window cosine-attention + res-post-norm MLP
// b=2, H=W=192, C=128, WS=16, NH=8, d=16
// GEMMs + attention on fp16 tensor cores (mma.sync m16n8k16), fp32 accumulate.
// fp16 intermediates on edges whose consumer rounds to fp16 anyway.
// ---------------------------------------------------------------------------

#define M_TOK   73728
#define C_DIM   128
#define NH      8
#define HD      16
#define NWIN    288
#define NTOK    256
#define IMG     192
#define WPR     12

typedef unsigned int u32;

__device__ float  g_qkv  [ (size_t)M_TOK * 384 ];
__device__ uint2  g_biasF[ (size_t)NH * 16 * 32 * 32 ];   // C-fragment layout
__device__ __half g_attnh[ (size_t)M_TOK * C_DIM ];
__device__ float  g_proj [ (size_t)M_TOK * C_DIM ];
__device__ float  g_x1   [ (size_t)M_TOK * C_DIM ];
__device__ __half g_hidh [ (size_t)M_TOK * 256 ];
__device__ float  g_y    [ (size_t)M_TOK * C_DIM ];

#define MMA16816(d0,d1,d2,d3,a0,a1,a2,a3,b0,b1)                          \
    asm volatile(                                                        \
        "mma.sync.aligned.m16n8k16.row.col.f32.f16.f16.f32 "             \
        "{%0,%1,%2,%3}, {%4,%5,%6,%7}, {%8,%9}, {%0,%1,%2,%3};"          \
        : "+f"(d0), "+f"(d1), "+f"(d2), "+f"(d3)                         \
        : "r"(a0), "r"(a1), "r"(a2), "r"(a3), "r"(b0), "r"(b1))

// ---------------------------------------------------------------------------
// fp16 tensor-core GEMM, templated on A and C dtype.
// C = act(A[M,K] @ B[K,N]fp32 + bias), fp32 accum.
// Tile 128x128, BK=32, 8 warps (2m x 4n), warp tile 64x32.
// ---------------------------------------------------------------------------
template<bool A_HALF, bool C_HALF>
__global__ __launch_bounds__(256) void hgemm_kernel(
    const void* __restrict__ Av, const float* __restrict__ B,
    const float* __restrict__ bias, void* __restrict__ Cv,
    int M, int N, int K, int act)
{
    __shared__ __half As[128][40];
    __shared__ __half Bs[32][136];

    const float*  Af = (const float*)Av;
    const __half* Ah = (const __half*)Av;
    float*  Cf = (float*)Cv;
    __half* Ch = (__half*)Cv;

    const int tid  = threadIdx.x;
    const int lane = tid & 31;
    const int wid  = tid >> 5;
    const int warp_m = wid >> 2;
    const int warp_n = wid & 3;
    const int brow = blockIdx.y * 128;
    const int bcol = blockIdx.x * 128;

    // fp32-A staging: 4 iters of (row tid>>3 + t*32, k (tid&7)*4)
    const int a_m0 = tid >> 3;
    const int a_k4 = (tid & 7) << 2;
    // fp16-A staging: 2 iters of (row tid>>2 + t*64, k (tid&3)*8)
    const int a_m0h = tid >> 2;
    const int a_k8  = (tid & 3) << 3;

    const int b_k0 = tid >> 5;
    const int b_n4 = (tid & 31) << 2;

    const u32 a_smem = (u32)__cvta_generic_to_shared(&As[0][0]);
    const u32 b_smem = (u32)__cvta_generic_to_shared(&Bs[0][0]);

    float acc[4][4][4];
    #pragma unroll
    for (int mi = 0; mi < 4; mi++)
        #pragma unroll
        for (int ni = 0; ni < 4; ni++)
            #pragma unroll
            for (int z = 0; z < 4; z++) acc[mi][ni][z] = 0.f;

    float4 a_pf[4];
    uint4  a_pfh[2];
    float4 b_pf[4];
    if (A_HALF) {
        #pragma unroll
        for (int t = 0; t < 2; t++)
            a_pfh[t] = *reinterpret_cast<const uint4*>(
                &Ah[(size_t)(brow + a_m0h + t * 64) * K + a_k8]);
    } else {
        #pragma unroll
        for (int t = 0; t < 4; t++)
            a_pf[t] = *reinterpret_cast<const float4*>(
                &Af[(size_t)(brow + a_m0 + t * 32) * K + a_k4]);
    }
    #pragma unroll
    for (int t = 0; t < 4; t++)
        b_pf[t] = *reinterpret_cast<const float4*>(
            &B[(size_t)(b_k0 + t * 8) * N + bcol + b_n4]);

    for (int kt = 0; kt < K; kt += 32) {
        if (A_HALF) {
            #pragma unroll
            for (int t = 0; t < 2; t++)
                *reinterpret_cast<uint4*>(&As[a_m0h + t * 64][a_k8]) = a_pfh[t];
        } else {
            #pragma unroll
            for (int t = 0; t < 4; t++) {
                __half2 h0 = __float22half2_rn(make_float2(a_pf[t].x, a_pf[t].y));
                __half2 h1 = __float22half2_rn(make_float2(a_pf[t].z, a_pf[t].w));
                *reinterpret_cast<__half2*>(&As[a_m0 + t * 32][a_k4 + 0]) = h0;
                *reinterpret_cast<__half2*>(&As[a_m0 + t * 32][a_k4 + 2]) = h1;
            }
        }
        #pragma unroll
        for (int t = 0; t < 4; t++) {
            __half2 g0 = __float22half2_rn(make_float2(b_pf[t].x, b_pf[t].y));
            __half2 g1 = __float22half2_rn(make_float2(b_pf[t].z, b_pf[t].w));
            *reinterpret_cast<__half2*>(&Bs[b_k0 + t * 8][b_n4 + 0]) = g0;
            *reinterpret_cast<__half2*>(&Bs[b_k0 + t * 8][b_n4 + 2]) = g1;
        }
        __syncthreads();

        if (kt + 32 < K) {
            if (A_HALF) {
                #pragma unroll
                for (int t = 0; t < 2; t++)
                    a_pfh[t] = *reinterpret_cast<const uint4*>(
                        &Ah[(size_t)(brow + a_m0h + t * 64) * K + kt + 32 + a_k8]);
            } else {
                #pragma unroll
                for (int t = 0; t < 4; t++)
                    a_pf[t] = *reinterpret_cast<const float4*>(
                        &Af[(size_t)(brow + a_m0 + t * 32) * K + kt + 32 + a_k4]);
            }
            #pragma unroll
            for (int t = 0; t < 4; t++)
                b_pf[t] = *reinterpret_cast<const float4*>(
                    &B[(size_t)(kt + 32 + b_k0 + t * 8) * N + bcol + b_n4]);
        }

        #pragma unroll
        for (int ks = 0; ks < 32; ks += 16) {
            u32 af[4][4];
            #pragma unroll
            for (int mi = 0; mi < 4; mi++) {
                int r = warp_m * 64 + mi * 16 + (lane & 15);
                int c = ks + ((lane >> 4) << 3);
                u32 addr = a_smem + (u32)(r * 40 + c) * 2u;
                asm volatile(
                    "ldmatrix.sync.aligned.m8n8.x4.shared.b16 {%0,%1,%2,%3}, [%4];"
                    : "=r"(af[mi][0]), "=r"(af[mi][1]), "=r"(af[mi][2]), "=r"(af[mi][3])
                    : "r"(addr));
            }
            u32 bf[4][2];
            #pragma unroll
            for (int p = 0; p < 2; p++) {
                int r = ks + (lane & 15);
                int c = warp_n * 32 + p * 16 + ((lane >> 4) << 3);
                u32 addr = b_smem + (u32)(r * 136 + c) * 2u;
                asm volatile(
                    "ldmatrix.sync.aligned.m8n8.x4.trans.shared.b16 {%0,%1,%2,%3}, [%4];"
                    : "=r"(bf[2*p][0]), "=r"(bf[2*p][1]),
                      "=r"(bf[2*p+1][0]), "=r"(bf[2*p+1][1])
                    : "r"(addr));
            }
            #pragma unroll
            for (int mi = 0; mi < 4; mi++)
                #pragma unroll
                for (int ni = 0; ni < 4; ni++) {
                    MMA16816(acc[mi][ni][0], acc[mi][ni][1],
                             acc[mi][ni][2], acc[mi][ni][3],
                             af[mi][0], af[mi][1], af[mi][2], af[mi][3],
                             bf[ni][0], bf[ni][1]);
                }
        }
        __syncthreads();
    }

    #pragma unroll
    for (int mi = 0; mi < 4; mi++) {
        #pragma unroll
        for (int ni = 0; ni < 4; ni++) {
            const int r0 = brow + warp_m * 64 + mi * 16 + (lane >> 2);
            const int c  = bcol + warp_n * 32 + ni * 8 + ((lane & 3) << 1);
            float2 bb = *reinterpret_cast<const float2*>(&bias[c]);
            float2 v0, v1;
            v0.x = acc[mi][ni][0] + bb.x; v0.y = acc[mi][ni][1] + bb.y;
            v1.x = acc[mi][ni][2] + bb.x; v1.y = acc[mi][ni][3] + bb.y;
            if (act == 1) {
                v0.x *= normcdff(v0.x); v0.y *= normcdff(v0.y);
                v1.x *= normcdff(v1.x); v1.y *= normcdff(v1.y);
            }
            if (C_HALF) {
                *reinterpret_cast<__half2*>(&Ch[(size_t)r0 * N + c]) =
                    __float22half2_rn(v0);
                *reinterpret_cast<__half2*>(&Ch[(size_t)(r0 + 8) * N + c]) =
                    __float22half2_rn(v1);
            } else {
                *reinterpret_cast<float2*>(&Cf[(size_t)r0 * N + c])       = v0;
                *reinterpret_cast<float2*>(&Cf[(size_t)(r0 + 8) * N + c]) = v1;
            }
        }
    }
}

// ---------------------------------------------------------------------------
// Bias in mma C-fragment layout (see round-6 comment).
// ---------------------------------------------------------------------------
__global__ void biasf_kernel(const int* __restrict__ rpi,
                             const float* __restrict__ table,
                             uint2* __restrict__ biasF)
{
    const int qb = blockIdx.x >> 5;
    const int jt = blockIdx.x & 31;
    const int hd = blockIdx.y;
    const int lane = threadIdx.x;
    const int g = lane >> 2, t = lane & 3;
    const int i0 = qb * 16, j0 = jt * 8;

    float b00 = table[rpi[(i0 + g)     * NTOK + j0 + 2*t    ] * NH + hd];
    float b01 = table[rpi[(i0 + g)     * NTOK + j0 + 2*t + 1] * NH + hd];
    float b10 = table[rpi[(i0 + g + 8) * NTOK + j0 + 2*t    ] * NH + hd];
    float b11 = table[rpi[(i0 + g + 8) * NTOK + j0 + 2*t + 1] * NH + hd];

    uint2 r;
    *reinterpret_cast<__half2*>(&r.x) = __floats2half2_rn(b00, b01);
    *reinterpret_cast<__half2*>(&r.y) = __floats2half2_rn(b10, b11);
    biasF[((size_t)(hd * 16 + qb) * 32 + jt) * 32 + lane] = r;
}

// ---------------------------------------------------------------------------
// Tensor-core window attention. Block = (window, head), 128 threads (4 warps).
// smem (halfs): Kh/Kl [256][24], Vth/Vtl [16][264]  = 41.5 KB -> 5 blocks/SM.
// Q loaded per-warp gmem->registers, normalized via 4-lane shfl (fragment
// layout exact). S = qh*kh + qh*kl + ql*kh (fp32 acc). P fp16 -> PV hi+lo.
// Single-pass softmax shifted by `scale`. Output written fp16.
// ---------------------------------------------------------------------------
#define SKH  0
#define SKL  (256*24)
#define SVTH (2*256*24)
#define SVTL (2*256*24 + 16*264)
#define ATTN_SMEM_HALFS (2*256*24 + 2*16*264)

__device__ __forceinline__ void split2(float x, float y, u32& hi, u32& lo)
{
    __half2 h = __floats2half2_rn(x, y);
    float2 hf = __half22float2(h);
    __half2 l = __floats2half2_rn(x - hf.x, y - hf.y);
    hi = *reinterpret_cast<u32*>(&h);
    lo = *reinterpret_cast<u32*>(&l);
}

__global__ __launch_bounds__(128) void attn_tc_kernel(
    const float* __restrict__ qkv, const uint2* __restrict__ biasF,
    const float* __restrict__ logit_scale, __half* __restrict__ attn_out)
{
    __shared__ __half sm[ATTN_SMEM_HALFS];

    const int wi = blockIdx.x;
    const int hd = blockIdx.y;
    const int tid = threadIdx.x;

    const int bimg = wi / 144;
    const int wrem = wi % 144;
    const int wr = wrem / WPR, wc = wrem % WPR;
    const int rowbase = bimg * (IMG * IMG) + (wr * 16) * IMG + wc * 16;

    const float scale = __expf(fminf(logit_scale[hd], 4.6051702f)); // ln(100)

    // ---- stage k (normalized, hi/lo) and v (hi/lo, transposed)
    for (int tok = tid; tok < NTOK; tok += 128) {
        const int m = rowbase + (tok >> 4) * IMG + (tok & 15);
        const float* base = qkv + (size_t)m * 384 + hd * HD;

        float k[16], v[16];
        float ks = 0.f;
        #pragma unroll
        for (int z = 0; z < 4; z++) {
            float4 b = reinterpret_cast<const float4*>(base + 128)[z];
            k[z*4+0]=b.x; k[z*4+1]=b.y; k[z*4+2]=b.z; k[z*4+3]=b.w;
            ks += b.x*b.x + b.y*b.y + b.z*b.z + b.w*b.w;
            float4 c = reinterpret_cast<const float4*>(base + 256)[z];
            v[z*4+0]=c.x; v[z*4+1]=c.y; v[z*4+2]=c.z; v[z*4+3]=c.w;
        }
        const float kr = 1.f / fmaxf(sqrtf(ks), 1e-12f);
        #pragma unroll
        for (int z = 0; z < 16; z++) {
            float kv = k[z] * kr;
            __half kh = __float2half_rn(kv);
            sm[SKH + tok*24 + z] = kh;
            sm[SKL + tok*24 + z] = __float2half_rn(kv - __half2float(kh));
            __half vh = __float2half_rn(v[z]);
            sm[SVTH + z*264 + tok] = vh;
            sm[SVTL + z*264 + tok] = __float2half_rn(v[z] - __half2float(vh));
        }
    }
    __syncthreads();

    const int warp = tid >> 5;
    const int lane = tid & 31;
    const int g = lane >> 2;
    const int t = lane & 3;

    for (int qi = 0; qi < 4; qi++) {
        const int qb = warp * 4 + qi;
        const int i0 = qb * 16;
        const int r0 = i0 + g, r1 = i0 + g + 8;
        const int m0 = rowbase + (r0 >> 4) * IMG + (r0 & 15);
        const int m1 = rowbase + (r1 >> 4) * IMG + (r1 & 15);

        // ---- Q gmem -> registers, normalize via 4-lane shfl, fold in scale
        const float* q0p = qkv + (size_t)m0 * 384 + hd * HD;
        const float* q1p = qkv + (size_t)m1 * 384 + hd * HD;
        float2 a00 = *reinterpret_cast<const float2*>(q0p + 2*t);
        float2 a01 = *reinterpret_cast<const float2*>(q0p + 2*t + 8);
        float2 a10 = *reinterpret_cast<const float2*>(q1p + 2*t);
        float2 a11 = *reinterpret_cast<const float2*>(q1p + 2*t + 8);

        float s0 = a00.x*a00.x + a00.y*a00.y + a01.x*a01.x + a01.y*a01.y;
        float s1 = a10.x*a10.x + a10.y*a10.y + a11.x*a11.x + a11.y*a11.y;
        s0 += __shfl_xor_sync(0xffffffffu, s0, 1);
        s0 += __shfl_xor_sync(0xffffffffu, s0, 2);
        s1 += __shfl_xor_sync(0xffffffffu, s1, 1);
        s1 += __shfl_xor_sync(0xffffffffu, s1, 2);
        const float qr0 = scale / fmaxf(sqrtf(s0), 1e-12f);
        const float qr1 = scale / fmaxf(sqrtf(s1), 1e-12f);

        u32 qa[4], la[4];
        split2(a00.x * qr0, a00.y * qr0, qa[0], la[0]);
        split2(a10.x * qr1, a10.y * qr1, qa[1], la[1]);
        split2(a01.x * qr0, a01.y * qr0, qa[2], la[2]);
        split2(a11.x * qr1, a11.y * qr1, qa[3], la[3]);

        float o0[4] = {0.f,0.f,0.f,0.f};
        float o1[4] = {0.f,0.f,0.f,0.f};
        float l0 = 0.f, l1 = 0.f;

        const uint2* bp = biasF + ((size_t)(hd * 16 + qb) * 32) * 32 + lane;

        uint2 bcur[8], bnxt[8];
        #pragma unroll
        for (int u = 0; u < 8; u++) bcur[u] = __ldg(&bp[u * 32]);

        u32 pa0 = 0, pa1 = 0;

        #pragma unroll 1
        for (int bt = 0; bt < 4; bt++) {
            if (bt < 3) {
                #pragma unroll
                for (int u = 0; u < 8; u++)
                    bnxt[u] = __ldg(&bp[(bt * 8 + 8 + u) * 32]);
            }
            #pragma unroll
            for (int u = 0; u < 8; u++) {
                const int jt = bt * 8 + u;
                const int j0 = jt * 8;

                u32 kh0 = *reinterpret_cast<u32*>(&sm[SKH + (j0+g)*24 + 2*t]);
                u32 kh1 = *reinterpret_cast<u32*>(&sm[SKH + (j0+g)*24 + 2*t + 8]);
                u32 kl0 = *reinterpret_cast<u32*>(&sm[SKL + (j0+g)*24 + 2*t]);
                u32 kl1 = *reinterpret_cast<u32*>(&sm[SKL + (j0+g)*24 + 2*t + 8]);

                float s0v = 0.f, s1v = 0.f, s2v = 0.f, s3v = 0.f;
                MMA16816(s0v,s1v,s2v,s3v, qa[0],qa[1],qa[2],qa[3], kh0,kh1);
                MMA16816(s0v,s1v,s2v,s3v, qa[0],qa[1],qa[2],qa[3], kl0,kl1);
                MMA16816(s0v,s1v,s2v,s3v, la[0],la[1],la[2],la[3], kh0,kh1);

                uint2 bb = bcur[u];
                float2 blo = __half22float2(*reinterpret_cast<__half2*>(&bb.x));
                float2 bhi = __half22float2(*reinterpret_cast<__half2*>(&bb.y));
                float p0 = __expf(s0v + blo.x - scale);
                float p1 = __expf(s1v + blo.y - scale);
                float p2 = __expf(s2v + bhi.x - scale);
                float p3 = __expf(s3v + bhi.y - scale);
                l0 += p0 + p1;
                l1 += p2 + p3;
                __half2 plo = __floats2half2_rn(p0, p1);
                __half2 phi = __floats2half2_rn(p2, p3);

                if ((u & 1) == 0) {
                    pa0 = *reinterpret_cast<u32*>(&plo);
                    pa1 = *reinterpret_cast<u32*>(&phi);
                } else {
                    u32 pa2 = *reinterpret_cast<u32*>(&plo);
                    u32 pa3 = *reinterpret_cast<u32*>(&phi);
                    const int jb = (jt - 1) * 8;
                    u32 vh0 = *reinterpret_cast<u32*>(&sm[SVTH + g*264 + jb + 2*t]);
                    u32 vh1 = *reinterpret_cast<u32*>(&sm[SVTH + g*264 + jb + 2*t + 8]);
                    u32 vl0 = *reinterpret_cast<u32*>(&sm[SVTL + g*264 + jb + 2*t]);
                    u32 vl1 = *reinterpret_cast<u32*>(&sm[SVTL + g*264 + jb + 2*t + 8]);
                    MMA16816(o0[0],o0[1],o0[2],o0[3], pa0,pa1,pa2,pa3, vh0,vh1);
                    MMA16816(o0[0],o0[1],o0[2],o0[3], pa0,pa1,pa2,pa3, vl0,vl1);
                    u32 wh0 = *reinterpret_cast<u32*>(&sm[SVTH + (8+g)*264 + jb + 2*t]);
                    u32 wh1 = *reinterpret_cast<u32*>(&sm[SVTH + (8+g)*264 + jb + 2*t + 8]);
                    u32 wl0 = *reinterpret_cast<u32*>(&sm[SVTL + (8+g)*264 + jb + 2*t]);
                    u32 wl1 = *reinterpret_cast<u32*>(&sm[SVTL + (8+g)*264 + jb + 2*t + 8]);
                    MMA16816(o1[0],o1[1],o1[2],o1[3], pa0,pa1,pa2,pa3, wh0,wh1);
                    MMA16816(o1[0],o1[1],o1[2],o1[3], pa0,pa1,pa2,pa3, wl0,wl1);
                }
            }
            #pragma unroll
            for (int u = 0; u < 8; u++) bcur[u] = bnxt[u];
        }

        l0 += __shfl_xor_sync(0xffffffffu, l0, 1);
        l0 += __shfl_xor_sync(0xffffffffu, l0, 2);
        l1 += __shfl_xor_sync(0xffffffffu, l1, 1);
        l1 += __shfl_xor_sync(0xffffffffu, l1, 2);
        const float inv0 = 1.f / l0, inv1 = 1.f / l1;

        const int col = hd * HD + 2 * t;
        *reinterpret_cast<__half2*>(&attn_out[(size_t)m0 * C_DIM + col]) =
            __floats2half2_rn(o0[0] * inv0, o0[1] * inv0);
        *reinterpret_cast<__half2*>(&attn_out[(size_t)m1 * C_DIM + col]) =
            __floats2half2_rn(o0[2] * inv1, o0[3] * inv1);
        *reinterpret_cast<__half2*>(&attn_out[(size_t)m0 * C_DIM + col + 8]) =
            __floats2half2_rn(o1[0] * inv0, o1[1] * inv0);
        *reinterpret_cast<__half2*>(&attn_out[(size_t)m1 * C_DIM + col + 8]) =
            __floats2half2_rn(o1[2] * inv1, o1[3] * inv1);
    }
}

// ---------------------------------------------------------------------------
// out = res + LayerNorm(in) * w + b
// ---------------------------------------------------------------------------
__global__ __launch_bounds__(256) void ln_res_kernel(
    const float* __restrict__ inp, const float* __restrict__ res,
    const float* __restrict__ w, const float* __restrict__ b,
    float* __restrict__ out)
{
    int row  = blockIdx.x * 8 + (threadIdx.x >> 5);
    int lane = threadIdx.x & 31;

    const float4 v  = reinterpret_cast<const float4*>(inp + (size_t)row * 128)[lane];
    float s  = v.x + v.y + v.z + v.w;
    float s2 = v.x*v.x + v.y*v.y + v.z*v.z + v.w*v.w;
    #pragma unroll
    for (int off = 16; off > 0; off >>= 1) {
        s  += __shfl_xor_sync(0xffffffffu, s,  off);
        s2 += __shfl_xor_sync(0xffffffffu, s2, off);
    }
    const float mu   = s * (1.f / 128.f);
    const float var  = s2 * (1.f / 128.f) - mu * mu;
    const float rstd = rsqrtf(var + 1e-5f);

    const float4 wv = reinterpret_cast<const float4*>(w)[lane];
    const float4 bv = reinterpret_cast<const float4*>(b)[lane];
    const float4 rv = reinterpret_cast<const float4*>(res + (size_t)row * 128)[lane];
    float4 o;
    o.x = rv.x + (v.x - mu) * rstd * wv.x + bv.x;
    o.y = rv.y + (v.y - mu) * rstd * wv.y + bv.y;
    o.z = rv.z + (v.z - mu) * rstd * wv.z + bv.z;
    o.w = rv.w + (v.w - mu) * rstd * wv.w + bv.w;
    reinterpret_cast<float4*>(out + (size_t)row * 128)[lane] = o;
}

// ---------------------------------------------------------------------------
extern "C" void kernel_launch(void* const* d_in, const int* in_sizes, int n_in,
                              void* d_out, int out_size)
{
    const float* x           = (const float*)d_in[0];
    const float* qkv_w       = (const float*)d_in[1];
    const float* qkv_b       = (const float*)d_in[2];
    const float* proj_w      = (const float*)d_in[3];
    const float* proj_b      = (const float*)d_in[4];
    const float* logit_scale = (const float*)d_in[5];
    const float* rpb_table   = (const float*)d_in[6];
    const float* n1w         = (const float*)d_in[7];
    const float* n1b         = (const float*)d_in[8];
    const float* n2w         = (const float*)d_in[9];
    const float* n2b         = (const float*)d_in[10];
    const float* fc1_w       = (const float*)d_in[11];
    const float* fc1_b       = (const float*)d_in[12];
    const float* fc2_w       = (const float*)d_in[13];
    const float* fc2_b       = (const float*)d_in[14];
    const int*   rpi         = (const int*)d_in[17];
    float* out = (float*)d_out;

    float *p_qkv, *p_proj, *p_x1, *p_y;
    __half *p_attnh, *p_hidh;
    uint2 *p_biasF;
    cudaGetSymbolAddress((void**)&p_qkv,   g_qkv);
    cudaGetSymbolAddress((void**)&p_biasF, g_biasF);
    cudaGetSymbolAddress((void**)&p_attnh, g_attnh);
    cudaGetSymbolAddress((void**)&p_proj,  g_proj);
    cudaGetSymbolAddress((void**)&p_x1,    g_x1);
    cudaGetSymbolAddress((void**)&p_hidh,  g_hidh);
    cudaGetSymbolAddress((void**)&p_y,     g_y);

    // 1) bias fragments
    biasf_kernel<<<dim3(16 * 32, NH), 32>>>(rpi, rpb_table, p_biasF);

    // 2) QKV: fp32 A, fp32 C
    hgemm_kernel<false,false><<<dim3(384/128, M_TOK/128), 256>>>(
        x, qkv_w, qkv_b, p_qkv, M_TOK, 384, 128, 0);

    // 3) tensor-core window attention -> fp16
    attn_tc_kernel<<<dim3(NWIN, NH), 128>>>(p_qkv, p_biasF, logit_scale, p_attnh);

    // 4) proj: fp16 A, fp32 C
    hgemm_kernel<true,false><<<dim3(128/128, M_TOK/128), 256>>>(
        p_attnh, proj_w, proj_b, p_proj, M_TOK, 128, 128, 0);

    // 5) x1 = x + LN(proj)
    ln_res_kernel<<<M_TOK/8, 256>>>(p_proj, x, n1w, n1b, p_x1);

    // 6) fc1 + GELU: fp32 A, fp16 C
    hgemm_kernel<false,true><<<dim3(256/128, M_TOK/128), 256>>>(
        p_x1, fc1_w, fc1_b, p_hidh, M_TOK, 256, 128, 1);

    // 7) fc2: fp16 A, fp32 C
    hgemm_kernel<true,false><<<dim3(128/128, M_TOK/128), 256>>>(
        p_hidh, fc2_w, fc2_b, p_y, M_TOK, 128, 256, 0);

    // 8) out = x1 + LN(y)
    ln_res_kernel<<<M_TOK/8, 256>>>(p_y, p_x1, n2w, n2b, out);
}

// round 8
// speedup vs baseline: 3.5484x; 1.0532x over previous
#include <cuda_runtime.h>
#include <cuda_fp16.h>
#include <cuda_bf16.h>
#include <math_constants.h>

// ---------------------------------------------------------------------------
// SwinV2 block: window cosine-attention + res-post-norm MLP
// b=2, H=W=192, C=128, WS=16, NH=8, d=16
// GEMMs + attention on fp16 tensor cores (mma.sync m16n8k16), fp32 accumulate.
// LayerNorm+residual fused into proj/fc2 GEMM epilogues (N==128 -> block owns
// complete rows).
// ---------------------------------------------------------------------------

#define M_TOK   73728
#define C_DIM   128
#define NH      8
#define HD      16
#define NWIN    288
#define NTOK    256
#define IMG     192
#define WPR     12

typedef unsigned int u32;

__device__ float  g_qkv  [ (size_t)M_TOK * 384 ];
__device__ uint2  g_biasF[ (size_t)NH * 16 * 32 * 32 ];   // C-fragment layout
__device__ __half g_attnh[ (size_t)M_TOK * C_DIM ];
__device__ float  g_x1   [ (size_t)M_TOK * C_DIM ];
__device__ __half g_hidh [ (size_t)M_TOK * 256 ];

#define MMA16816(d0,d1,d2,d3,a0,a1,a2,a3,b0,b1)                          \
    asm volatile(                                                        \
        "mma.sync.aligned.m16n8k16.row.col.f32.f16.f16.f32 "             \
        "{%0,%1,%2,%3}, {%4,%5,%6,%7}, {%8,%9}, {%0,%1,%2,%3};"          \
        : "+f"(d0), "+f"(d1), "+f"(d2), "+f"(d3)                         \
        : "r"(a0), "r"(a1), "r"(a2), "r"(a3), "r"(b0), "r"(b1))

// ---------------------------------------------------------------------------
// fp16 tensor-core GEMM, templated on A/C dtype.
// act: 0 = none, 1 = exact GELU, 2 = fused "res + LayerNorm(.)*lnw + lnb"
// (act==2 requires N==128; C written fp32).
// Tile 128x128, BK=32, 8 warps (2m x 4n), warp tile 64x32.
// ---------------------------------------------------------------------------
template<bool A_HALF, bool C_HALF, int ACT>
__global__ __launch_bounds__(256) void hgemm_kernel(
    const void* __restrict__ Av, const float* __restrict__ B,
    const float* __restrict__ bias, void* __restrict__ Cv,
    int M, int N, int K,
    const float* __restrict__ res,
    const float* __restrict__ lnw, const float* __restrict__ lnb)
{
    __shared__ __half As[128][40];
    __shared__ __half Bs[32][136];
    __shared__ float2 red[128][4];   // per-row (sum, sumsq) per warp_n

    const float*  Af = (const float*)Av;
    const __half* Ah = (const __half*)Av;
    float*  Cf = (float*)Cv;
    __half* Ch = (__half*)Cv;

    const int tid  = threadIdx.x;
    const int lane = tid & 31;
    const int wid  = tid >> 5;
    const int warp_m = wid >> 2;
    const int warp_n = wid & 3;
    const int brow = blockIdx.y * 128;
    const int bcol = blockIdx.x * 128;

    const int a_m0 = tid >> 3;
    const int a_k4 = (tid & 7) << 2;
    const int a_m0h = tid >> 2;
    const int a_k8  = (tid & 3) << 3;
    const int b_k0 = tid >> 5;
    const int b_n4 = (tid & 31) << 2;

    const u32 a_smem = (u32)__cvta_generic_to_shared(&As[0][0]);
    const u32 b_smem = (u32)__cvta_generic_to_shared(&Bs[0][0]);

    float acc[4][4][4];
    #pragma unroll
    for (int mi = 0; mi < 4; mi++)
        #pragma unroll
        for (int ni = 0; ni < 4; ni++)
            #pragma unroll
            for (int z = 0; z < 4; z++) acc[mi][ni][z] = 0.f;

    float4 a_pf[4];
    uint4  a_pfh[2];
    float4 b_pf[4];
    if (A_HALF) {
        #pragma unroll
        for (int t = 0; t < 2; t++)
            a_pfh[t] = *reinterpret_cast<const uint4*>(
                &Ah[(size_t)(brow + a_m0h + t * 64) * K + a_k8]);
    } else {
        #pragma unroll
        for (int t = 0; t < 4; t++)
            a_pf[t] = *reinterpret_cast<const float4*>(
                &Af[(size_t)(brow + a_m0 + t * 32) * K + a_k4]);
    }
    #pragma unroll
    for (int t = 0; t < 4; t++)
        b_pf[t] = *reinterpret_cast<const float4*>(
            &B[(size_t)(b_k0 + t * 8) * N + bcol + b_n4]);

    for (int kt = 0; kt < K; kt += 32) {
        if (A_HALF) {
            #pragma unroll
            for (int t = 0; t < 2; t++)
                *reinterpret_cast<uint4*>(&As[a_m0h + t * 64][a_k8]) = a_pfh[t];
        } else {
            #pragma unroll
            for (int t = 0; t < 4; t++) {
                __half2 h0 = __float22half2_rn(make_float2(a_pf[t].x, a_pf[t].y));
                __half2 h1 = __float22half2_rn(make_float2(a_pf[t].z, a_pf[t].w));
                *reinterpret_cast<__half2*>(&As[a_m0 + t * 32][a_k4 + 0]) = h0;
                *reinterpret_cast<__half2*>(&As[a_m0 + t * 32][a_k4 + 2]) = h1;
            }
        }
        #pragma unroll
        for (int t = 0; t < 4; t++) {
            __half2 g0 = __float22half2_rn(make_float2(b_pf[t].x, b_pf[t].y));
            __half2 g1 = __float22half2_rn(make_float2(b_pf[t].z, b_pf[t].w));
            *reinterpret_cast<__half2*>(&Bs[b_k0 + t * 8][b_n4 + 0]) = g0;
            *reinterpret_cast<__half2*>(&Bs[b_k0 + t * 8][b_n4 + 2]) = g1;
        }
        __syncthreads();

        if (kt + 32 < K) {
            if (A_HALF) {
                #pragma unroll
                for (int t = 0; t < 2; t++)
                    a_pfh[t] = *reinterpret_cast<const uint4*>(
                        &Ah[(size_t)(brow + a_m0h + t * 64) * K + kt + 32 + a_k8]);
            } else {
                #pragma unroll
                for (int t = 0; t < 4; t++)
                    a_pf[t] = *reinterpret_cast<const float4*>(
                        &Af[(size_t)(brow + a_m0 + t * 32) * K + kt + 32 + a_k4]);
            }
            #pragma unroll
            for (int t = 0; t < 4; t++)
                b_pf[t] = *reinterpret_cast<const float4*>(
                    &B[(size_t)(kt + 32 + b_k0 + t * 8) * N + bcol + b_n4]);
        }

        #pragma unroll
        for (int ks = 0; ks < 32; ks += 16) {
            u32 af[4][4];
            #pragma unroll
            for (int mi = 0; mi < 4; mi++) {
                int r = warp_m * 64 + mi * 16 + (lane & 15);
                int c = ks + ((lane >> 4) << 3);
                u32 addr = a_smem + (u32)(r * 40 + c) * 2u;
                asm volatile(
                    "ldmatrix.sync.aligned.m8n8.x4.shared.b16 {%0,%1,%2,%3}, [%4];"
                    : "=r"(af[mi][0]), "=r"(af[mi][1]), "=r"(af[mi][2]), "=r"(af[mi][3])
                    : "r"(addr));
            }
            u32 bf[4][2];
            #pragma unroll
            for (int p = 0; p < 2; p++) {
                int r = ks + (lane & 15);
                int c = warp_n * 32 + p * 16 + ((lane >> 4) << 3);
                u32 addr = b_smem + (u32)(r * 136 + c) * 2u;
                asm volatile(
                    "ldmatrix.sync.aligned.m8n8.x4.trans.shared.b16 {%0,%1,%2,%3}, [%4];"
                    : "=r"(bf[2*p][0]), "=r"(bf[2*p][1]),
                      "=r"(bf[2*p+1][0]), "=r"(bf[2*p+1][1])
                    : "r"(addr));
            }
            #pragma unroll
            for (int mi = 0; mi < 4; mi++)
                #pragma unroll
                for (int ni = 0; ni < 4; ni++) {
                    MMA16816(acc[mi][ni][0], acc[mi][ni][1],
                             acc[mi][ni][2], acc[mi][ni][3],
                             af[mi][0], af[mi][1], af[mi][2], af[mi][3],
                             bf[ni][0], bf[ni][1]);
                }
        }
        __syncthreads();
    }

    const int g = lane >> 2;
    const int t = lane & 3;

    if (ACT == 2) {
        // ---- fused bias + LayerNorm + residual (N == 128, bcol == 0) ----
        #pragma unroll
        for (int mi = 0; mi < 4; mi++) {
            #pragma unroll
            for (int ni = 0; ni < 4; ni++) {
                const int c = warp_n * 32 + ni * 8 + (t << 1);
                float2 bb = *reinterpret_cast<const float2*>(&bias[c]);
                acc[mi][ni][0] += bb.x; acc[mi][ni][1] += bb.y;
                acc[mi][ni][2] += bb.x; acc[mi][ni][3] += bb.y;
            }
            float s0 = 0.f, q0 = 0.f, s1 = 0.f, q1 = 0.f;
            #pragma unroll
            for (int ni = 0; ni < 4; ni++) {
                s0 += acc[mi][ni][0] + acc[mi][ni][1];
                q0 += acc[mi][ni][0]*acc[mi][ni][0] + acc[mi][ni][1]*acc[mi][ni][1];
                s1 += acc[mi][ni][2] + acc[mi][ni][3];
                q1 += acc[mi][ni][2]*acc[mi][ni][2] + acc[mi][ni][3]*acc[mi][ni][3];
            }
            s0 += __shfl_xor_sync(0xffffffffu, s0, 1);
            s0 += __shfl_xor_sync(0xffffffffu, s0, 2);
            q0 += __shfl_xor_sync(0xffffffffu, q0, 1);
            q0 += __shfl_xor_sync(0xffffffffu, q0, 2);
            s1 += __shfl_xor_sync(0xffffffffu, s1, 1);
            s1 += __shfl_xor_sync(0xffffffffu, s1, 2);
            q1 += __shfl_xor_sync(0xffffffffu, q1, 1);
            q1 += __shfl_xor_sync(0xffffffffu, q1, 2);
            if (t == 0) {
                const int rl = warp_m * 64 + mi * 16 + g;
                red[rl][warp_n]     = make_float2(s0, q0);
                red[rl + 8][warp_n] = make_float2(s1, q1);
            }
        }
        __syncthreads();

        #pragma unroll
        for (int mi = 0; mi < 4; mi++) {
            const int rl0 = warp_m * 64 + mi * 16 + g;
            const int rl1 = rl0 + 8;
            float2 p;
            float s0 = 0.f, q0 = 0.f, s1 = 0.f, q1 = 0.f;
            #pragma unroll
            for (int w = 0; w < 4; w++) {
                p = red[rl0][w]; s0 += p.x; q0 += p.y;
                p = red[rl1][w]; s1 += p.x; q1 += p.y;
            }
            const float mu0 = s0 * (1.f/128.f);
            const float mu1 = s1 * (1.f/128.f);
            const float rs0 = rsqrtf(q0 * (1.f/128.f) - mu0*mu0 + 1e-5f);
            const float rs1 = rsqrtf(q1 * (1.f/128.f) - mu1*mu1 + 1e-5f);

            const size_t gr0 = (size_t)(brow + rl0) * 128;
            const size_t gr1 = (size_t)(brow + rl1) * 128;
            #pragma unroll
            for (int ni = 0; ni < 4; ni++) {
                const int c = warp_n * 32 + ni * 8 + (t << 1);
                float2 wv = *reinterpret_cast<const float2*>(&lnw[c]);
                float2 bv = *reinterpret_cast<const float2*>(&lnb[c]);
                float2 r0v = *reinterpret_cast<const float2*>(&res[gr0 + c]);
                float2 r1v = *reinterpret_cast<const float2*>(&res[gr1 + c]);
                float2 o0, o1;
                o0.x = r0v.x + (acc[mi][ni][0] - mu0) * rs0 * wv.x + bv.x;
                o0.y = r0v.y + (acc[mi][ni][1] - mu0) * rs0 * wv.y + bv.y;
                o1.x = r1v.x + (acc[mi][ni][2] - mu1) * rs1 * wv.x + bv.x;
                o1.y = r1v.y + (acc[mi][ni][3] - mu1) * rs1 * wv.y + bv.y;
                *reinterpret_cast<float2*>(&Cf[gr0 + c]) = o0;
                *reinterpret_cast<float2*>(&Cf[gr1 + c]) = o1;
            }
        }
        return;
    }

    // ---- plain epilogue (none / GELU) ----
    #pragma unroll
    for (int mi = 0; mi < 4; mi++) {
        #pragma unroll
        for (int ni = 0; ni < 4; ni++) {
            const int r0 = brow + warp_m * 64 + mi * 16 + g;
            const int c  = bcol + warp_n * 32 + ni * 8 + (t << 1);
            float2 bb = *reinterpret_cast<const float2*>(&bias[c]);
            float2 v0, v1;
            v0.x = acc[mi][ni][0] + bb.x; v0.y = acc[mi][ni][1] + bb.y;
            v1.x = acc[mi][ni][2] + bb.x; v1.y = acc[mi][ni][3] + bb.y;
            if (ACT == 1) {
                v0.x *= normcdff(v0.x); v0.y *= normcdff(v0.y);
                v1.x *= normcdff(v1.x); v1.y *= normcdff(v1.y);
            }
            if (C_HALF) {
                *reinterpret_cast<__half2*>(&Ch[(size_t)r0 * N + c]) =
                    __float22half2_rn(v0);
                *reinterpret_cast<__half2*>(&Ch[(size_t)(r0 + 8) * N + c]) =
                    __float22half2_rn(v1);
            } else {
                *reinterpret_cast<float2*>(&Cf[(size_t)r0 * N + c])       = v0;
                *reinterpret_cast<float2*>(&Cf[(size_t)(r0 + 8) * N + c]) = v1;
            }
        }
    }
}

// ---------------------------------------------------------------------------
// Bias in mma C-fragment layout.
// ---------------------------------------------------------------------------
__global__ void biasf_kernel(const int* __restrict__ rpi,
                             const float* __restrict__ table,
                             uint2* __restrict__ biasF)
{
    const int qb = blockIdx.x >> 5;
    const int jt = blockIdx.x & 31;
    const int hd = blockIdx.y;
    const int lane = threadIdx.x;
    const int g = lane >> 2, t = lane & 3;
    const int i0 = qb * 16, j0 = jt * 8;

    float b00 = table[rpi[(i0 + g)     * NTOK + j0 + 2*t    ] * NH + hd];
    float b01 = table[rpi[(i0 + g)     * NTOK + j0 + 2*t + 1] * NH + hd];
    float b10 = table[rpi[(i0 + g + 8) * NTOK + j0 + 2*t    ] * NH + hd];
    float b11 = table[rpi[(i0 + g + 8) * NTOK + j0 + 2*t + 1] * NH + hd];

    uint2 r;
    *reinterpret_cast<__half2*>(&r.x) = __floats2half2_rn(b00, b01);
    *reinterpret_cast<__half2*>(&r.y) = __floats2half2_rn(b10, b11);
    biasF[((size_t)(hd * 16 + qb) * 32 + jt) * 32 + lane] = r;
}

// ---------------------------------------------------------------------------
// Tensor-core window attention (see round-7 comments). Output fp16.
// ---------------------------------------------------------------------------
#define SKH  0
#define SKL  (256*24)
#define SVTH (2*256*24)
#define SVTL (2*256*24 + 16*264)
#define ATTN_SMEM_HALFS (2*256*24 + 2*16*264)

__device__ __forceinline__ void split2(float x, float y, u32& hi, u32& lo)
{
    __half2 h = __floats2half2_rn(x, y);
    float2 hf = __half22float2(h);
    __half2 l = __floats2half2_rn(x - hf.x, y - hf.y);
    hi = *reinterpret_cast<u32*>(&h);
    lo = *reinterpret_cast<u32*>(&l);
}

__global__ __launch_bounds__(128) void attn_tc_kernel(
    const float* __restrict__ qkv, const uint2* __restrict__ biasF,
    const float* __restrict__ logit_scale, __half* __restrict__ attn_out)
{
    __shared__ __half sm[ATTN_SMEM_HALFS];

    const int wi = blockIdx.x;
    const int hd = blockIdx.y;
    const int tid = threadIdx.x;

    const int bimg = wi / 144;
    const int wrem = wi % 144;
    const int wr = wrem / WPR, wc = wrem % WPR;
    const int rowbase = bimg * (IMG * IMG) + (wr * 16) * IMG + wc * 16;

    const float scale = __expf(fminf(logit_scale[hd], 4.6051702f)); // ln(100)

    for (int tok = tid; tok < NTOK; tok += 128) {
        const int m = rowbase + (tok >> 4) * IMG + (tok & 15);
        const float* base = qkv + (size_t)m * 384 + hd * HD;

        float k[16], v[16];
        float ks = 0.f;
        #pragma unroll
        for (int z = 0; z < 4; z++) {
            float4 b = reinterpret_cast<const float4*>(base + 128)[z];
            k[z*4+0]=b.x; k[z*4+1]=b.y; k[z*4+2]=b.z; k[z*4+3]=b.w;
            ks += b.x*b.x + b.y*b.y + b.z*b.z + b.w*b.w;
            float4 c = reinterpret_cast<const float4*>(base + 256)[z];
            v[z*4+0]=c.x; v[z*4+1]=c.y; v[z*4+2]=c.z; v[z*4+3]=c.w;
        }
        const float kr = 1.f / fmaxf(sqrtf(ks), 1e-12f);
        #pragma unroll
        for (int z = 0; z < 16; z++) {
            float kv = k[z] * kr;
            __half kh = __float2half_rn(kv);
            sm[SKH + tok*24 + z] = kh;
            sm[SKL + tok*24 + z] = __float2half_rn(kv - __half2float(kh));
            __half vh = __float2half_rn(v[z]);
            sm[SVTH + z*264 + tok] = vh;
            sm[SVTL + z*264 + tok] = __float2half_rn(v[z] - __half2float(vh));
        }
    }
    __syncthreads();

    const int warp = tid >> 5;
    const int lane = tid & 31;
    const int g = lane >> 2;
    const int t = lane & 3;

    for (int qi = 0; qi < 4; qi++) {
        const int qb = warp * 4 + qi;
        const int i0 = qb * 16;
        const int r0 = i0 + g, r1 = i0 + g + 8;
        const int m0 = rowbase + (r0 >> 4) * IMG + (r0 & 15);
        const int m1 = rowbase + (r1 >> 4) * IMG + (r1 & 15);

        const float* q0p = qkv + (size_t)m0 * 384 + hd * HD;
        const float* q1p = qkv + (size_t)m1 * 384 + hd * HD;
        float2 a00 = *reinterpret_cast<const float2*>(q0p + 2*t);
        float2 a01 = *reinterpret_cast<const float2*>(q0p + 2*t + 8);
        float2 a10 = *reinterpret_cast<const float2*>(q1p + 2*t);
        float2 a11 = *reinterpret_cast<const float2*>(q1p + 2*t + 8);

        float s0 = a00.x*a00.x + a00.y*a00.y + a01.x*a01.x + a01.y*a01.y;
        float s1 = a10.x*a10.x + a10.y*a10.y + a11.x*a11.x + a11.y*a11.y;
        s0 += __shfl_xor_sync(0xffffffffu, s0, 1);
        s0 += __shfl_xor_sync(0xffffffffu, s0, 2);
        s1 += __shfl_xor_sync(0xffffffffu, s1, 1);
        s1 += __shfl_xor_sync(0xffffffffu, s1, 2);
        const float qr0 = scale / fmaxf(sqrtf(s0), 1e-12f);
        const float qr1 = scale / fmaxf(sqrtf(s1), 1e-12f);

        u32 qa[4], la[4];
        split2(a00.x * qr0, a00.y * qr0, qa[0], la[0]);
        split2(a10.x * qr1, a10.y * qr1, qa[1], la[1]);
        split2(a01.x * qr0, a01.y * qr0, qa[2], la[2]);
        split2(a11.x * qr1, a11.y * qr1, qa[3], la[3]);

        float o0[4] = {0.f,0.f,0.f,0.f};
        float o1[4] = {0.f,0.f,0.f,0.f};
        float l0 = 0.f, l1 = 0.f;

        const uint2* bp = biasF + ((size_t)(hd * 16 + qb) * 32) * 32 + lane;

        uint2 bcur[8], bnxt[8];
        #pragma unroll
        for (int u = 0; u < 8; u++) bcur[u] = __ldg(&bp[u * 32]);

        u32 pa0 = 0, pa1 = 0;

        #pragma unroll 1
        for (int bt = 0; bt < 4; bt++) {
            if (bt < 3) {
                #pragma unroll
                for (int u = 0; u < 8; u++)
                    bnxt[u] = __ldg(&bp[(bt * 8 + 8 + u) * 32]);
            }
            #pragma unroll
            for (int u = 0; u < 8; u++) {
                const int jt = bt * 8 + u;
                const int j0 = jt * 8;

                u32 kh0 = *reinterpret_cast<u32*>(&sm[SKH + (j0+g)*24 + 2*t]);
                u32 kh1 = *reinterpret_cast<u32*>(&sm[SKH + (j0+g)*24 + 2*t + 8]);
                u32 kl0 = *reinterpret_cast<u32*>(&sm[SKL + (j0+g)*24 + 2*t]);
                u32 kl1 = *reinterpret_cast<u32*>(&sm[SKL + (j0+g)*24 + 2*t + 8]);

                float s0v = 0.f, s1v = 0.f, s2v = 0.f, s3v = 0.f;
                MMA16816(s0v,s1v,s2v,s3v, qa[0],qa[1],qa[2],qa[3], kh0,kh1);
                MMA16816(s0v,s1v,s2v,s3v, qa[0],qa[1],qa[2],qa[3], kl0,kl1);
                MMA16816(s0v,s1v,s2v,s3v, la[0],la[1],la[2],la[3], kh0,kh1);

                uint2 bb = bcur[u];
                float2 blo = __half22float2(*reinterpret_cast<__half2*>(&bb.x));
                float2 bhi = __half22float2(*reinterpret_cast<__half2*>(&bb.y));
                float p0 = __expf(s0v + blo.x - scale);
                float p1 = __expf(s1v + blo.y - scale);
                float p2 = __expf(s2v + bhi.x - scale);
                float p3 = __expf(s3v + bhi.y - scale);
                l0 += p0 + p1;
                l1 += p2 + p3;
                __half2 plo = __floats2half2_rn(p0, p1);
                __half2 phi = __floats2half2_rn(p2, p3);

                if ((u & 1) == 0) {
                    pa0 = *reinterpret_cast<u32*>(&plo);
                    pa1 = *reinterpret_cast<u32*>(&phi);
                } else {
                    u32 pa2 = *reinterpret_cast<u32*>(&plo);
                    u32 pa3 = *reinterpret_cast<u32*>(&phi);
                    const int jb = (jt - 1) * 8;
                    u32 vh0 = *reinterpret_cast<u32*>(&sm[SVTH + g*264 + jb + 2*t]);
                    u32 vh1 = *reinterpret_cast<u32*>(&sm[SVTH + g*264 + jb + 2*t + 8]);
                    u32 vl0 = *reinterpret_cast<u32*>(&sm[SVTL + g*264 + jb + 2*t]);
                    u32 vl1 = *reinterpret_cast<u32*>(&sm[SVTL + g*264 + jb + 2*t + 8]);
                    MMA16816(o0[0],o0[1],o0[2],o0[3], pa0,pa1,pa2,pa3, vh0,vh1);
                    MMA16816(o0[0],o0[1],o0[2],o0[3], pa0,pa1,pa2,pa3, vl0,vl1);
                    u32 wh0 = *reinterpret_cast<u32*>(&sm[SVTH + (8+g)*264 + jb + 2*t]);
                    u32 wh1 = *reinterpret_cast<u32*>(&sm[SVTH + (8+g)*264 + jb + 2*t + 8]);
                    u32 wl0 = *reinterpret_cast<u32*>(&sm[SVTL + (8+g)*264 + jb + 2*t]);
                    u32 wl1 = *reinterpret_cast<u32*>(&sm[SVTL + (8+g)*264 + jb + 2*t + 8]);
                    MMA16816(o1[0],o1[1],o1[2],o1[3], pa0,pa1,pa2,pa3, wh0,wh1);
                    MMA16816(o1[0],o1[1],o1[2],o1[3], pa0,pa1,pa2,pa3, wl0,wl1);
                }
            }
            #pragma unroll
            for (int u = 0; u < 8; u++) bcur[u] = bnxt[u];
        }

        l0 += __shfl_xor_sync(0xffffffffu, l0, 1);
        l0 += __shfl_xor_sync(0xffffffffu, l0, 2);
        l1 += __shfl_xor_sync(0xffffffffu, l1, 1);
        l1 += __shfl_xor_sync(0xffffffffu, l1, 2);
        const float inv0 = 1.f / l0, inv1 = 1.f / l1;

        const int col = hd * HD + 2 * t;
        *reinterpret_cast<__half2*>(&attn_out[(size_t)m0 * C_DIM + col]) =
            __floats2half2_rn(o0[0] * inv0, o0[1] * inv0);
        *reinterpret_cast<__half2*>(&attn_out[(size_t)m1 * C_DIM + col]) =
            __floats2half2_rn(o0[2] * inv1, o0[3] * inv1);
        *reinterpret_cast<__half2*>(&attn_out[(size_t)m0 * C_DIM + col + 8]) =
            __floats2half2_rn(o1[0] * inv0, o1[1] * inv0);
        *reinterpret_cast<__half2*>(&attn_out[(size_t)m1 * C_DIM + col + 8]) =
            __floats2half2_rn(o1[2] * inv1, o1[3] * inv1);
    }
}

// ---------------------------------------------------------------------------
extern "C" void kernel_launch(void* const* d_in, const int* in_sizes, int n_in,
                              void* d_out, int out_size)
{
    const float* x           = (const float*)d_in[0];
    const float* qkv_w       = (const float*)d_in[1];
    const float* qkv_b       = (const float*)d_in[2];
    const float* proj_w      = (const float*)d_in[3];
    const float* proj_b      = (const float*)d_in[4];
    const float* logit_scale = (const float*)d_in[5];
    const float* rpb_table   = (const float*)d_in[6];
    const float* n1w         = (const float*)d_in[7];
    const float* n1b         = (const float*)d_in[8];
    const float* n2w         = (const float*)d_in[9];
    const float* n2b         = (const float*)d_in[10];
    const float* fc1_w       = (const float*)d_in[11];
    const float* fc1_b       = (const float*)d_in[12];
    const float* fc2_w       = (const float*)d_in[13];
    const float* fc2_b       = (const float*)d_in[14];
    const int*   rpi         = (const int*)d_in[17];
    float* out = (float*)d_out;

    float *p_qkv, *p_x1;
    __half *p_attnh, *p_hidh;
    uint2 *p_biasF;
    cudaGetSymbolAddress((void**)&p_qkv,   g_qkv);
    cudaGetSymbolAddress((void**)&p_biasF, g_biasF);
    cudaGetSymbolAddress((void**)&p_attnh, g_attnh);
    cudaGetSymbolAddress((void**)&p_x1,    g_x1);
    cudaGetSymbolAddress((void**)&p_hidh,  g_hidh);

    // 1) bias fragments
    biasf_kernel<<<dim3(16 * 32, NH), 32>>>(rpi, rpb_table, p_biasF);

    // 2) QKV: fp32 A, fp32 C
    hgemm_kernel<false,false,0><<<dim3(384/128, M_TOK/128), 256>>>(
        x, qkv_w, qkv_b, p_qkv, M_TOK, 384, 128, nullptr, nullptr, nullptr);

    // 3) tensor-core window attention -> fp16
    attn_tc_kernel<<<dim3(NWIN, NH), 128>>>(p_qkv, p_biasF, logit_scale, p_attnh);

    // 4) proj + fused LN + residual: x1 = x + LN(attn @ proj_w + proj_b)
    hgemm_kernel<true,false,2><<<dim3(1, M_TOK/128), 256>>>(
        p_attnh, proj_w, proj_b, p_x1, M_TOK, 128, 128, x, n1w, n1b);

    // 5) fc1 + GELU: fp32 A, fp16 C
    hgemm_kernel<false,true,1><<<dim3(256/128, M_TOK/128), 256>>>(
        p_x1, fc1_w, fc1_b, p_hidh, M_TOK, 256, 128, nullptr, nullptr, nullptr);

    // 6) fc2 + fused LN + residual: out = x1 + LN(hid @ fc2_w + fc2_b)
    hgemm_kernel<true,false,2><<<dim3(1, M_TOK/128), 256>>>(
        p_hidh, fc2_w, fc2_b, out, M_TOK, 128, 256, p_x1, n2w, n2b);
}

// round 9
// speedup vs baseline: 3.7331x; 1.0520x over previous
#include <cuda_runtime.h>
#include <cuda_fp16.h>
#include <cuda_bf16.h>
#include <math_constants.h>

// ---------------------------------------------------------------------------
// SwinV2 block: window cosine-attention + res-post-norm MLP
// b=2, H=W=192, C=128, WS=16, NH=8, d=16
// GEMMs + attention on fp16 tensor cores (mma.sync m16n8k16), fp32 accumulate.
// LayerNorm+residual fused into proj/fc2 GEMM epilogues.
// Attention: S = qh*(kh+kl) (2 MMAs), PV = p*vh (per ntile) — measured error
// budget shows the extra split terms were unnecessary.
// ---------------------------------------------------------------------------

#define M_TOK   73728
#define C_DIM   128
#define NH      8
#define HD      16
#define NWIN    288
#define NTOK    256
#define IMG     192
#define WPR     12

typedef unsigned int u32;

__device__ float  g_qkv  [ (size_t)M_TOK * 384 ];
__device__ uint2  g_biasF[ (size_t)NH * 16 * 32 * 32 ];   // C-fragment layout
__device__ __half g_attnh[ (size_t)M_TOK * C_DIM ];
__device__ float  g_x1   [ (size_t)M_TOK * C_DIM ];
__device__ __half g_hidh [ (size_t)M_TOK * 256 ];

#define MMA16816(d0,d1,d2,d3,a0,a1,a2,a3,b0,b1)                          \
    asm volatile(                                                        \
        "mma.sync.aligned.m16n8k16.row.col.f32.f16.f16.f32 "             \
        "{%0,%1,%2,%3}, {%4,%5,%6,%7}, {%8,%9}, {%0,%1,%2,%3};"          \
        : "+f"(d0), "+f"(d1), "+f"(d2), "+f"(d3)                         \
        : "r"(a0), "r"(a1), "r"(a2), "r"(a3), "r"(b0), "r"(b1))

// ---------------------------------------------------------------------------
// fp16 tensor-core GEMM, templated on A/C dtype.
// act: 0 = none, 1 = exact GELU, 2 = fused "res + LayerNorm(.)*lnw + lnb"
// (act==2 requires N==128; C written fp32).
// Tile 128x128, BK=32, 8 warps (2m x 4n), warp tile 64x32.
// ---------------------------------------------------------------------------
template<bool A_HALF, bool C_HALF, int ACT>
__global__ __launch_bounds__(256) void hgemm_kernel(
    const void* __restrict__ Av, const float* __restrict__ B,
    const float* __restrict__ bias, void* __restrict__ Cv,
    int M, int N, int K,
    const float* __restrict__ res,
    const float* __restrict__ lnw, const float* __restrict__ lnb)
{
    __shared__ __half As[128][40];
    __shared__ __half Bs[32][136];
    __shared__ float2 red[128][4];   // per-row (sum, sumsq) per warp_n

    const float*  Af = (const float*)Av;
    const __half* Ah = (const __half*)Av;
    float*  Cf = (float*)Cv;
    __half* Ch = (__half*)Cv;

    const int tid  = threadIdx.x;
    const int lane = tid & 31;
    const int wid  = tid >> 5;
    const int warp_m = wid >> 2;
    const int warp_n = wid & 3;
    const int brow = blockIdx.y * 128;
    const int bcol = blockIdx.x * 128;

    const int a_m0 = tid >> 3;
    const int a_k4 = (tid & 7) << 2;
    const int a_m0h = tid >> 2;
    const int a_k8  = (tid & 3) << 3;
    const int b_k0 = tid >> 5;
    const int b_n4 = (tid & 31) << 2;

    const u32 a_smem = (u32)__cvta_generic_to_shared(&As[0][0]);
    const u32 b_smem = (u32)__cvta_generic_to_shared(&Bs[0][0]);

    float acc[4][4][4];
    #pragma unroll
    for (int mi = 0; mi < 4; mi++)
        #pragma unroll
        for (int ni = 0; ni < 4; ni++)
            #pragma unroll
            for (int z = 0; z < 4; z++) acc[mi][ni][z] = 0.f;

    float4 a_pf[4];
    uint4  a_pfh[2];
    float4 b_pf[4];
    if (A_HALF) {
        #pragma unroll
        for (int t = 0; t < 2; t++)
            a_pfh[t] = *reinterpret_cast<const uint4*>(
                &Ah[(size_t)(brow + a_m0h + t * 64) * K + a_k8]);
    } else {
        #pragma unroll
        for (int t = 0; t < 4; t++)
            a_pf[t] = *reinterpret_cast<const float4*>(
                &Af[(size_t)(brow + a_m0 + t * 32) * K + a_k4]);
    }
    #pragma unroll
    for (int t = 0; t < 4; t++)
        b_pf[t] = *reinterpret_cast<const float4*>(
            &B[(size_t)(b_k0 + t * 8) * N + bcol + b_n4]);

    for (int kt = 0; kt < K; kt += 32) {
        if (A_HALF) {
            #pragma unroll
            for (int t = 0; t < 2; t++)
                *reinterpret_cast<uint4*>(&As[a_m0h + t * 64][a_k8]) = a_pfh[t];
        } else {
            #pragma unroll
            for (int t = 0; t < 4; t++) {
                __half2 h0 = __float22half2_rn(make_float2(a_pf[t].x, a_pf[t].y));
                __half2 h1 = __float22half2_rn(make_float2(a_pf[t].z, a_pf[t].w));
                *reinterpret_cast<__half2*>(&As[a_m0 + t * 32][a_k4 + 0]) = h0;
                *reinterpret_cast<__half2*>(&As[a_m0 + t * 32][a_k4 + 2]) = h1;
            }
        }
        #pragma unroll
        for (int t = 0; t < 4; t++) {
            __half2 g0 = __float22half2_rn(make_float2(b_pf[t].x, b_pf[t].y));
            __half2 g1 = __float22half2_rn(make_float2(b_pf[t].z, b_pf[t].w));
            *reinterpret_cast<__half2*>(&Bs[b_k0 + t * 8][b_n4 + 0]) = g0;
            *reinterpret_cast<__half2*>(&Bs[b_k0 + t * 8][b_n4 + 2]) = g1;
        }
        __syncthreads();

        if (kt + 32 < K) {
            if (A_HALF) {
                #pragma unroll
                for (int t = 0; t < 2; t++)
                    a_pfh[t] = *reinterpret_cast<const uint4*>(
                        &Ah[(size_t)(brow + a_m0h + t * 64) * K + kt + 32 + a_k8]);
            } else {
                #pragma unroll
                for (int t = 0; t < 4; t++)
                    a_pf[t] = *reinterpret_cast<const float4*>(
                        &Af[(size_t)(brow + a_m0 + t * 32) * K + kt + 32 + a_k4]);
            }
            #pragma unroll
            for (int t = 0; t < 4; t++)
                b_pf[t] = *reinterpret_cast<const float4*>(
                    &B[(size_t)(kt + 32 + b_k0 + t * 8) * N + bcol + b_n4]);
        }

        #pragma unroll
        for (int ks = 0; ks < 32; ks += 16) {
            u32 af[4][4];
            #pragma unroll
            for (int mi = 0; mi < 4; mi++) {
                int r = warp_m * 64 + mi * 16 + (lane & 15);
                int c = ks + ((lane >> 4) << 3);
                u32 addr = a_smem + (u32)(r * 40 + c) * 2u;
                asm volatile(
                    "ldmatrix.sync.aligned.m8n8.x4.shared.b16 {%0,%1,%2,%3}, [%4];"
                    : "=r"(af[mi][0]), "=r"(af[mi][1]), "=r"(af[mi][2]), "=r"(af[mi][3])
                    : "r"(addr));
            }
            u32 bf[4][2];
            #pragma unroll
            for (int p = 0; p < 2; p++) {
                int r = ks + (lane & 15);
                int c = warp_n * 32 + p * 16 + ((lane >> 4) << 3);
                u32 addr = b_smem + (u32)(r * 136 + c) * 2u;
                asm volatile(
                    "ldmatrix.sync.aligned.m8n8.x4.trans.shared.b16 {%0,%1,%2,%3}, [%4];"
                    : "=r"(bf[2*p][0]), "=r"(bf[2*p][1]),
                      "=r"(bf[2*p+1][0]), "=r"(bf[2*p+1][1])
                    : "r"(addr));
            }
            #pragma unroll
            for (int mi = 0; mi < 4; mi++)
                #pragma unroll
                for (int ni = 0; ni < 4; ni++) {
                    MMA16816(acc[mi][ni][0], acc[mi][ni][1],
                             acc[mi][ni][2], acc[mi][ni][3],
                             af[mi][0], af[mi][1], af[mi][2], af[mi][3],
                             bf[ni][0], bf[ni][1]);
                }
        }
        __syncthreads();
    }

    const int g = lane >> 2;
    const int t = lane & 3;

    if (ACT == 2) {
        // ---- fused bias + LayerNorm + residual (N == 128, bcol == 0) ----
        #pragma unroll
        for (int mi = 0; mi < 4; mi++) {
            #pragma unroll
            for (int ni = 0; ni < 4; ni++) {
                const int c = warp_n * 32 + ni * 8 + (t << 1);
                float2 bb = *reinterpret_cast<const float2*>(&bias[c]);
                acc[mi][ni][0] += bb.x; acc[mi][ni][1] += bb.y;
                acc[mi][ni][2] += bb.x; acc[mi][ni][3] += bb.y;
            }
            float s0 = 0.f, q0 = 0.f, s1 = 0.f, q1 = 0.f;
            #pragma unroll
            for (int ni = 0; ni < 4; ni++) {
                s0 += acc[mi][ni][0] + acc[mi][ni][1];
                q0 += acc[mi][ni][0]*acc[mi][ni][0] + acc[mi][ni][1]*acc[mi][ni][1];
                s1 += acc[mi][ni][2] + acc[mi][ni][3];
                q1 += acc[mi][ni][2]*acc[mi][ni][2] + acc[mi][ni][3]*acc[mi][ni][3];
            }
            s0 += __shfl_xor_sync(0xffffffffu, s0, 1);
            s0 += __shfl_xor_sync(0xffffffffu, s0, 2);
            q0 += __shfl_xor_sync(0xffffffffu, q0, 1);
            q0 += __shfl_xor_sync(0xffffffffu, q0, 2);
            s1 += __shfl_xor_sync(0xffffffffu, s1, 1);
            s1 += __shfl_xor_sync(0xffffffffu, s1, 2);
            q1 += __shfl_xor_sync(0xffffffffu, q1, 1);
            q1 += __shfl_xor_sync(0xffffffffu, q1, 2);
            if (t == 0) {
                const int rl = warp_m * 64 + mi * 16 + g;
                red[rl][warp_n]     = make_float2(s0, q0);
                red[rl + 8][warp_n] = make_float2(s1, q1);
            }
        }
        __syncthreads();

        #pragma unroll
        for (int mi = 0; mi < 4; mi++) {
            const int rl0 = warp_m * 64 + mi * 16 + g;
            const int rl1 = rl0 + 8;
            float2 p;
            float s0 = 0.f, q0 = 0.f, s1 = 0.f, q1 = 0.f;
            #pragma unroll
            for (int w = 0; w < 4; w++) {
                p = red[rl0][w]; s0 += p.x; q0 += p.y;
                p = red[rl1][w]; s1 += p.x; q1 += p.y;
            }
            const float mu0 = s0 * (1.f/128.f);
            const float mu1 = s1 * (1.f/128.f);
            const float rs0 = rsqrtf(q0 * (1.f/128.f) - mu0*mu0 + 1e-5f);
            const float rs1 = rsqrtf(q1 * (1.f/128.f) - mu1*mu1 + 1e-5f);

            const size_t gr0 = (size_t)(brow + rl0) * 128;
            const size_t gr1 = (size_t)(brow + rl1) * 128;
            #pragma unroll
            for (int ni = 0; ni < 4; ni++) {
                const int c = warp_n * 32 + ni * 8 + (t << 1);
                float2 wv = *reinterpret_cast<const float2*>(&lnw[c]);
                float2 bv = *reinterpret_cast<const float2*>(&lnb[c]);
                float2 r0v = *reinterpret_cast<const float2*>(&res[gr0 + c]);
                float2 r1v = *reinterpret_cast<const float2*>(&res[gr1 + c]);
                float2 o0, o1;
                o0.x = r0v.x + (acc[mi][ni][0] - mu0) * rs0 * wv.x + bv.x;
                o0.y = r0v.y + (acc[mi][ni][1] - mu0) * rs0 * wv.y + bv.y;
                o1.x = r1v.x + (acc[mi][ni][2] - mu1) * rs1 * wv.x + bv.x;
                o1.y = r1v.y + (acc[mi][ni][3] - mu1) * rs1 * wv.y + bv.y;
                *reinterpret_cast<float2*>(&Cf[gr0 + c]) = o0;
                *reinterpret_cast<float2*>(&Cf[gr1 + c]) = o1;
            }
        }
        return;
    }

    // ---- plain epilogue (none / GELU) ----
    #pragma unroll
    for (int mi = 0; mi < 4; mi++) {
        #pragma unroll
        for (int ni = 0; ni < 4; ni++) {
            const int r0 = brow + warp_m * 64 + mi * 16 + g;
            const int c  = bcol + warp_n * 32 + ni * 8 + (t << 1);
            float2 bb = *reinterpret_cast<const float2*>(&bias[c]);
            float2 v0, v1;
            v0.x = acc[mi][ni][0] + bb.x; v0.y = acc[mi][ni][1] + bb.y;
            v1.x = acc[mi][ni][2] + bb.x; v1.y = acc[mi][ni][3] + bb.y;
            if (ACT == 1) {
                v0.x *= normcdff(v0.x); v0.y *= normcdff(v0.y);
                v1.x *= normcdff(v1.x); v1.y *= normcdff(v1.y);
            }
            if (C_HALF) {
                *reinterpret_cast<__half2*>(&Ch[(size_t)r0 * N + c]) =
                    __float22half2_rn(v0);
                *reinterpret_cast<__half2*>(&Ch[(size_t)(r0 + 8) * N + c]) =
                    __float22half2_rn(v1);
            } else {
                *reinterpret_cast<float2*>(&Cf[(size_t)r0 * N + c])       = v0;
                *reinterpret_cast<float2*>(&Cf[(size_t)(r0 + 8) * N + c]) = v1;
            }
        }
    }
}

// ---------------------------------------------------------------------------
// Bias in mma C-fragment layout.
// ---------------------------------------------------------------------------
__global__ void biasf_kernel(const int* __restrict__ rpi,
                             const float* __restrict__ table,
                             uint2* __restrict__ biasF)
{
    const int qb = blockIdx.x >> 5;
    const int jt = blockIdx.x & 31;
    const int hd = blockIdx.y;
    const int lane = threadIdx.x;
    const int g = lane >> 2, t = lane & 3;
    const int i0 = qb * 16, j0 = jt * 8;

    float b00 = table[rpi[(i0 + g)     * NTOK + j0 + 2*t    ] * NH + hd];
    float b01 = table[rpi[(i0 + g)     * NTOK + j0 + 2*t + 1] * NH + hd];
    float b10 = table[rpi[(i0 + g + 8) * NTOK + j0 + 2*t    ] * NH + hd];
    float b11 = table[rpi[(i0 + g + 8) * NTOK + j0 + 2*t + 1] * NH + hd];

    uint2 r;
    *reinterpret_cast<__half2*>(&r.x) = __floats2half2_rn(b00, b01);
    *reinterpret_cast<__half2*>(&r.y) = __floats2half2_rn(b10, b11);
    biasF[((size_t)(hd * 16 + qb) * 32 + jt) * 32 + lane] = r;
}

// ---------------------------------------------------------------------------
// Tensor-core window attention. Block = (window, head), 128 threads (4 warps).
// smem (halfs): Kh/Kl [256][24], Vth [16][264]  = 32.25 KB.
// S = qh*kh + qh*kl (fp32 acc; residual logit err ~3.5e-4).
// PV = p*vh (V fp16; err ~2.4e-4). Single-pass softmax shifted by `scale`.
// Output written fp16.
// ---------------------------------------------------------------------------
#define SKH  0
#define SKL  (256*24)
#define SVTH (2*256*24)
#define ATTN_SMEM_HALFS (2*256*24 + 16*264)

__global__ __launch_bounds__(128) void attn_tc_kernel(
    const float* __restrict__ qkv, const uint2* __restrict__ biasF,
    const float* __restrict__ logit_scale, __half* __restrict__ attn_out)
{
    __shared__ __half sm[ATTN_SMEM_HALFS];

    const int wi = blockIdx.x;
    const int hd = blockIdx.y;
    const int tid = threadIdx.x;

    const int bimg = wi / 144;
    const int wrem = wi % 144;
    const int wr = wrem / WPR, wc = wrem % WPR;
    const int rowbase = bimg * (IMG * IMG) + (wr * 16) * IMG + wc * 16;

    const float scale = __expf(fminf(logit_scale[hd], 4.6051702f)); // ln(100)

    for (int tok = tid; tok < NTOK; tok += 128) {
        const int m = rowbase + (tok >> 4) * IMG + (tok & 15);
        const float* base = qkv + (size_t)m * 384 + hd * HD;

        float k[16], v[16];
        float ks = 0.f;
        #pragma unroll
        for (int z = 0; z < 4; z++) {
            float4 b = reinterpret_cast<const float4*>(base + 128)[z];
            k[z*4+0]=b.x; k[z*4+1]=b.y; k[z*4+2]=b.z; k[z*4+3]=b.w;
            ks += b.x*b.x + b.y*b.y + b.z*b.z + b.w*b.w;
            float4 c = reinterpret_cast<const float4*>(base + 256)[z];
            v[z*4+0]=c.x; v[z*4+1]=c.y; v[z*4+2]=c.z; v[z*4+3]=c.w;
        }
        const float kr = 1.f / fmaxf(sqrtf(ks), 1e-12f);
        #pragma unroll
        for (int z = 0; z < 16; z++) {
            float kv = k[z] * kr;
            __half kh = __float2half_rn(kv);
            sm[SKH + tok*24 + z] = kh;
            sm[SKL + tok*24 + z] = __float2half_rn(kv - __half2float(kh));
            sm[SVTH + z*264 + tok] = __float2half_rn(v[z]);
        }
    }
    __syncthreads();

    const int warp = tid >> 5;
    const int lane = tid & 31;
    const int g = lane >> 2;
    const int t = lane & 3;

    for (int qi = 0; qi < 4; qi++) {
        const int qb = warp * 4 + qi;
        const int i0 = qb * 16;
        const int r0 = i0 + g, r1 = i0 + g + 8;
        const int m0 = rowbase + (r0 >> 4) * IMG + (r0 & 15);
        const int m1 = rowbase + (r1 >> 4) * IMG + (r1 & 15);

        const float* q0p = qkv + (size_t)m0 * 384 + hd * HD;
        const float* q1p = qkv + (size_t)m1 * 384 + hd * HD;
        float2 a00 = *reinterpret_cast<const float2*>(q0p + 2*t);
        float2 a01 = *reinterpret_cast<const float2*>(q0p + 2*t + 8);
        float2 a10 = *reinterpret_cast<const float2*>(q1p + 2*t);
        float2 a11 = *reinterpret_cast<const float2*>(q1p + 2*t + 8);

        float s0 = a00.x*a00.x + a00.y*a00.y + a01.x*a01.x + a01.y*a01.y;
        float s1 = a10.x*a10.x + a10.y*a10.y + a11.x*a11.x + a11.y*a11.y;
        s0 += __shfl_xor_sync(0xffffffffu, s0, 1);
        s0 += __shfl_xor_sync(0xffffffffu, s0, 2);
        s1 += __shfl_xor_sync(0xffffffffu, s1, 1);
        s1 += __shfl_xor_sync(0xffffffffu, s1, 2);
        const float qr0 = scale / fmaxf(sqrtf(s0), 1e-12f);
        const float qr1 = scale / fmaxf(sqrtf(s1), 1e-12f);

        u32 qa[4];
        {
            __half2 h;
            h = __floats2half2_rn(a00.x * qr0, a00.y * qr0); qa[0] = *reinterpret_cast<u32*>(&h);
            h = __floats2half2_rn(a10.x * qr1, a10.y * qr1); qa[1] = *reinterpret_cast<u32*>(&h);
            h = __floats2half2_rn(a01.x * qr0, a01.y * qr0); qa[2] = *reinterpret_cast<u32*>(&h);
            h = __floats2half2_rn(a11.x * qr1, a11.y * qr1); qa[3] = *reinterpret_cast<u32*>(&h);
        }

        float o0[4] = {0.f,0.f,0.f,0.f};
        float o1[4] = {0.f,0.f,0.f,0.f};
        float l0 = 0.f, l1 = 0.f;

        const uint2* bp = biasF + ((size_t)(hd * 16 + qb) * 32) * 32 + lane;

        uint2 bcur[8], bnxt[8];
        #pragma unroll
        for (int u = 0; u < 8; u++) bcur[u] = __ldg(&bp[u * 32]);

        u32 pa0 = 0, pa1 = 0;

        #pragma unroll 1
        for (int bt = 0; bt < 4; bt++) {
            if (bt < 3) {
                #pragma unroll
                for (int u = 0; u < 8; u++)
                    bnxt[u] = __ldg(&bp[(bt * 8 + 8 + u) * 32]);
            }
            #pragma unroll
            for (int u = 0; u < 8; u++) {
                const int jt = bt * 8 + u;
                const int j0 = jt * 8;

                u32 kh0 = *reinterpret_cast<u32*>(&sm[SKH + (j0+g)*24 + 2*t]);
                u32 kh1 = *reinterpret_cast<u32*>(&sm[SKH + (j0+g)*24 + 2*t + 8]);
                u32 kl0 = *reinterpret_cast<u32*>(&sm[SKL + (j0+g)*24 + 2*t]);
                u32 kl1 = *reinterpret_cast<u32*>(&sm[SKL + (j0+g)*24 + 2*t + 8]);

                float s0v = 0.f, s1v = 0.f, s2v = 0.f, s3v = 0.f;
                MMA16816(s0v,s1v,s2v,s3v, qa[0],qa[1],qa[2],qa[3], kh0,kh1);
                MMA16816(s0v,s1v,s2v,s3v, qa[0],qa[1],qa[2],qa[3], kl0,kl1);

                uint2 bb = bcur[u];
                float2 blo = __half22float2(*reinterpret_cast<__half2*>(&bb.x));
                float2 bhi = __half22float2(*reinterpret_cast<__half2*>(&bb.y));
                float p0 = __expf(s0v + blo.x - scale);
                float p1 = __expf(s1v + blo.y - scale);
                float p2 = __expf(s2v + bhi.x - scale);
                float p3 = __expf(s3v + bhi.y - scale);
                l0 += p0 + p1;
                l1 += p2 + p3;
                __half2 plo = __floats2half2_rn(p0, p1);
                __half2 phi = __floats2half2_rn(p2, p3);

                if ((u & 1) == 0) {
                    pa0 = *reinterpret_cast<u32*>(&plo);
                    pa1 = *reinterpret_cast<u32*>(&phi);
                } else {
                    u32 pa2 = *reinterpret_cast<u32*>(&plo);
                    u32 pa3 = *reinterpret_cast<u32*>(&phi);
                    const int jb = (jt - 1) * 8;
                    u32 vh0 = *reinterpret_cast<u32*>(&sm[SVTH + g*264 + jb + 2*t]);
                    u32 vh1 = *reinterpret_cast<u32*>(&sm[SVTH + g*264 + jb + 2*t + 8]);
                    MMA16816(o0[0],o0[1],o0[2],o0[3], pa0,pa1,pa2,pa3, vh0,vh1);
                    u32 wh0 = *reinterpret_cast<u32*>(&sm[SVTH + (8+g)*264 + jb + 2*t]);
                    u32 wh1 = *reinterpret_cast<u32*>(&sm[SVTH + (8+g)*264 + jb + 2*t + 8]);
                    MMA16816(o1[0],o1[1],o1[2],o1[3], pa0,pa1,pa2,pa3, wh0,wh1);
                }
            }
            #pragma unroll
            for (int u = 0; u < 8; u++) bcur[u] = bnxt[u];
        }

        l0 += __shfl_xor_sync(0xffffffffu, l0, 1);
        l0 += __shfl_xor_sync(0xffffffffu, l0, 2);
        l1 += __shfl_xor_sync(0xffffffffu, l1, 1);
        l1 += __shfl_xor_sync(0xffffffffu, l1, 2);
        const float inv0 = 1.f / l0, inv1 = 1.f / l1;

        const int col = hd * HD + 2 * t;
        *reinterpret_cast<__half2*>(&attn_out[(size_t)m0 * C_DIM + col]) =
            __floats2half2_rn(o0[0] * inv0, o0[1] * inv0);
        *reinterpret_cast<__half2*>(&attn_out[(size_t)m1 * C_DIM + col]) =
            __floats2half2_rn(o0[2] * inv1, o0[3] * inv1);
        *reinterpret_cast<__half2*>(&attn_out[(size_t)m0 * C_DIM + col + 8]) =
            __floats2half2_rn(o1[0] * inv0, o1[1] * inv0);
        *reinterpret_cast<__half2*>(&attn_out[(size_t)m1 * C_DIM + col + 8]) =
            __floats2half2_rn(o1[2] * inv1, o1[3] * inv1);
    }
}

// ---------------------------------------------------------------------------
extern "C" void kernel_launch(void* const* d_in, const int* in_sizes, int n_in,
                              void* d_out, int out_size)
{
    const float* x           = (const float*)d_in[0];
    const float* qkv_w       = (const float*)d_in[1];
    const float* qkv_b       = (const float*)d_in[2];
    const float* proj_w      = (const float*)d_in[3];
    const float* proj_b      = (const float*)d_in[4];
    const float* logit_scale = (const float*)d_in[5];
    const float* rpb_table   = (const float*)d_in[6];
    const float* n1w         = (const float*)d_in[7];
    const float* n1b         = (const float*)d_in[8];
    const float* n2w         = (const float*)d_in[9];
    const float* n2b         = (const float*)d_in[10];
    const float* fc1_w       = (const float*)d_in[11];
    const float* fc1_b       = (const float*)d_in[12];
    const float* fc2_w       = (const float*)d_in[13];
    const float* fc2_b       = (const float*)d_in[14];
    const int*   rpi         = (const int*)d_in[17];
    float* out = (float*)d_out;

    float *p_qkv, *p_x1;
    __half *p_attnh, *p_hidh;
    uint2 *p_biasF;
    cudaGetSymbolAddress((void**)&p_qkv,   g_qkv);
    cudaGetSymbolAddress((void**)&p_biasF, g_biasF);
    cudaGetSymbolAddress((void**)&p_attnh, g_attnh);
    cudaGetSymbolAddress((void**)&p_x1,    g_x1);
    cudaGetSymbolAddress((void**)&p_hidh,  g_hidh);

    // 1) bias fragments
    biasf_kernel<<<dim3(16 * 32, NH), 32>>>(rpi, rpb_table, p_biasF);

    // 2) QKV: fp32 A, fp32 C
    hgemm_kernel<false,false,0><<<dim3(384/128, M_TOK/128), 256>>>(
        x, qkv_w, qkv_b, p_qkv, M_TOK, 384, 128, nullptr, nullptr, nullptr);

    // 3) tensor-core window attention -> fp16
    attn_tc_kernel<<<dim3(NWIN, NH), 128>>>(p_qkv, p_biasF, logit_scale, p_attnh);

    // 4) proj + fused LN + residual: x1 = x + LN(attn @ proj_w + proj_b)
    hgemm_kernel<true,false,2><<<dim3(1, M_TOK/128), 256>>>(
        p_attnh, proj_w, proj_b, p_x1, M_TOK, 128, 128, x, n1w, n1b);

    // 5) fc1 + GELU: fp32 A, fp16 C
    hgemm_kernel<false,true,1><<<dim3(256/128, M_TOK/128), 256>>>(
        p_x1, fc1_w, fc1_b, p_hidh, M_TOK, 256, 128, nullptr, nullptr, nullptr);

    // 6) fc2 + fused LN + residual: out = x1 + LN(hid @ fc2_w + fc2_b)
    hgemm_kernel<true,false,2><<<dim3(1, M_TOK/128), 256>>>(
        p_hidh, fc2_w, fc2_b, out, M_TOK, 128, 256, p_x1, n2w, n2b);
}

// round 10
// speedup vs baseline: 4.0093x; 1.0740x over previous
#include <cuda_runtime.h>
#include <cuda_fp16.h>
#include <cuda_bf16.h>
#include <math_constants.h>

// ---------------------------------------------------------------------------
// SwinV2 block: window cosine-attention + res-post-norm MLP
// b=2, H=W=192, C=128, WS=16, NH=8, d=16
// GEMMs + attention on fp16 tensor cores, fp32 accumulate.
// qkv intermediate is fp16 (normalization happens after rounding).
// Attention softmax uses unshifted exp2 (range-safe: logits*log2e <= 14.5).
// ---------------------------------------------------------------------------

#define M_TOK   73728
#define C_DIM   128
#define NH      8
#define HD      16
#define NWIN    288
#define NTOK    256
#define IMG     192
#define WPR     12
#define LOG2E   1.4426950408889634f

typedef unsigned int u32;

__device__ __half g_qkvh [ (size_t)M_TOK * 384 ];        // 56.6 MB
__device__ uint2  g_biasF[ (size_t)NH * 16 * 32 * 32 ];  // C-fragment layout
__device__ __half g_attnh[ (size_t)M_TOK * C_DIM ];
__device__ float  g_x1   [ (size_t)M_TOK * C_DIM ];
__device__ __half g_hidh [ (size_t)M_TOK * 256 ];

#define MMA16816(d0,d1,d2,d3,a0,a1,a2,a3,b0,b1)                          \
    asm volatile(                                                        \
        "mma.sync.aligned.m16n8k16.row.col.f32.f16.f16.f32 "             \
        "{%0,%1,%2,%3}, {%4,%5,%6,%7}, {%8,%9}, {%0,%1,%2,%3};"          \
        : "+f"(d0), "+f"(d1), "+f"(d2), "+f"(d3)                         \
        : "r"(a0), "r"(a1), "r"(a2), "r"(a3), "r"(b0), "r"(b1))

__device__ __forceinline__ float ex2(float x)
{
    float r;
    asm("ex2.approx.f32 %0, %1;" : "=f"(r) : "f"(x));
    return r;
}

// ---------------------------------------------------------------------------
// fp16 tensor-core GEMM, templated on A/C dtype.
// act: 0 = none, 1 = exact GELU, 2 = fused "res + LayerNorm(.)*lnw + lnb"
// (act==2 requires N==128; C written fp32).
// Tile 128x128, BK=32, 8 warps (2m x 4n), warp tile 64x32.
// ---------------------------------------------------------------------------
template<bool A_HALF, bool C_HALF, int ACT>
__global__ __launch_bounds__(256) void hgemm_kernel(
    const void* __restrict__ Av, const float* __restrict__ B,
    const float* __restrict__ bias, void* __restrict__ Cv,
    int M, int N, int K,
    const float* __restrict__ res,
    const float* __restrict__ lnw, const float* __restrict__ lnb)
{
    __shared__ __half As[128][40];
    __shared__ __half Bs[32][136];
    __shared__ float2 red[128][4];

    const float*  Af = (const float*)Av;
    const __half* Ah = (const __half*)Av;
    float*  Cf = (float*)Cv;
    __half* Ch = (__half*)Cv;

    const int tid  = threadIdx.x;
    const int lane = tid & 31;
    const int wid  = tid >> 5;
    const int warp_m = wid >> 2;
    const int warp_n = wid & 3;
    const int brow = blockIdx.y * 128;
    const int bcol = blockIdx.x * 128;

    const int a_m0 = tid >> 3;
    const int a_k4 = (tid & 7) << 2;
    const int a_m0h = tid >> 2;
    const int a_k8  = (tid & 3) << 3;
    const int b_k0 = tid >> 5;
    const int b_n4 = (tid & 31) << 2;

    const u32 a_smem = (u32)__cvta_generic_to_shared(&As[0][0]);
    const u32 b_smem = (u32)__cvta_generic_to_shared(&Bs[0][0]);

    float acc[4][4][4];
    #pragma unroll
    for (int mi = 0; mi < 4; mi++)
        #pragma unroll
        for (int ni = 0; ni < 4; ni++)
            #pragma unroll
            for (int z = 0; z < 4; z++) acc[mi][ni][z] = 0.f;

    float4 a_pf[4];
    uint4  a_pfh[2];
    float4 b_pf[4];
    if (A_HALF) {
        #pragma unroll
        for (int t = 0; t < 2; t++)
            a_pfh[t] = *reinterpret_cast<const uint4*>(
                &Ah[(size_t)(brow + a_m0h + t * 64) * K + a_k8]);
    } else {
        #pragma unroll
        for (int t = 0; t < 4; t++)
            a_pf[t] = *reinterpret_cast<const float4*>(
                &Af[(size_t)(brow + a_m0 + t * 32) * K + a_k4]);
    }
    #pragma unroll
    for (int t = 0; t < 4; t++)
        b_pf[t] = *reinterpret_cast<const float4*>(
            &B[(size_t)(b_k0 + t * 8) * N + bcol + b_n4]);

    for (int kt = 0; kt < K; kt += 32) {
        if (A_HALF) {
            #pragma unroll
            for (int t = 0; t < 2; t++)
                *reinterpret_cast<uint4*>(&As[a_m0h + t * 64][a_k8]) = a_pfh[t];
        } else {
            #pragma unroll
            for (int t = 0; t < 4; t++) {
                __half2 h0 = __float22half2_rn(make_float2(a_pf[t].x, a_pf[t].y));
                __half2 h1 = __float22half2_rn(make_float2(a_pf[t].z, a_pf[t].w));
                *reinterpret_cast<__half2*>(&As[a_m0 + t * 32][a_k4 + 0]) = h0;
                *reinterpret_cast<__half2*>(&As[a_m0 + t * 32][a_k4 + 2]) = h1;
            }
        }
        #pragma unroll
        for (int t = 0; t < 4; t++) {
            __half2 g0 = __float22half2_rn(make_float2(b_pf[t].x, b_pf[t].y));
            __half2 g1 = __float22half2_rn(make_float2(b_pf[t].z, b_pf[t].w));
            *reinterpret_cast<__half2*>(&Bs[b_k0 + t * 8][b_n4 + 0]) = g0;
            *reinterpret_cast<__half2*>(&Bs[b_k0 + t * 8][b_n4 + 2]) = g1;
        }
        __syncthreads();

        if (kt + 32 < K) {
            if (A_HALF) {
                #pragma unroll
                for (int t = 0; t < 2; t++)
                    a_pfh[t] = *reinterpret_cast<const uint4*>(
                        &Ah[(size_t)(brow + a_m0h + t * 64) * K + kt + 32 + a_k8]);
            } else {
                #pragma unroll
                for (int t = 0; t < 4; t++)
                    a_pf[t] = *reinterpret_cast<const float4*>(
                        &Af[(size_t)(brow + a_m0 + t * 32) * K + kt + 32 + a_k4]);
            }
            #pragma unroll
            for (int t = 0; t < 4; t++)
                b_pf[t] = *reinterpret_cast<const float4*>(
                    &B[(size_t)(kt + 32 + b_k0 + t * 8) * N + bcol + b_n4]);
        }

        #pragma unroll
        for (int ks = 0; ks < 32; ks += 16) {
            u32 af[4][4];
            #pragma unroll
            for (int mi = 0; mi < 4; mi++) {
                int r = warp_m * 64 + mi * 16 + (lane & 15);
                int c = ks + ((lane >> 4) << 3);
                u32 addr = a_smem + (u32)(r * 40 + c) * 2u;
                asm volatile(
                    "ldmatrix.sync.aligned.m8n8.x4.shared.b16 {%0,%1,%2,%3}, [%4];"
                    : "=r"(af[mi][0]), "=r"(af[mi][1]), "=r"(af[mi][2]), "=r"(af[mi][3])
                    : "r"(addr));
            }
            u32 bf[4][2];
            #pragma unroll
            for (int p = 0; p < 2; p++) {
                int r = ks + (lane & 15);
                int c = warp_n * 32 + p * 16 + ((lane >> 4) << 3);
                u32 addr = b_smem + (u32)(r * 136 + c) * 2u;
                asm volatile(
                    "ldmatrix.sync.aligned.m8n8.x4.trans.shared.b16 {%0,%1,%2,%3}, [%4];"
                    : "=r"(bf[2*p][0]), "=r"(bf[2*p][1]),
                      "=r"(bf[2*p+1][0]), "=r"(bf[2*p+1][1])
                    : "r"(addr));
            }
            #pragma unroll
            for (int mi = 0; mi < 4; mi++)
                #pragma unroll
                for (int ni = 0; ni < 4; ni++) {
                    MMA16816(acc[mi][ni][0], acc[mi][ni][1],
                             acc[mi][ni][2], acc[mi][ni][3],
                             af[mi][0], af[mi][1], af[mi][2], af[mi][3],
                             bf[ni][0], bf[ni][1]);
                }
        }
        __syncthreads();
    }

    const int g = lane >> 2;
    const int t = lane & 3;

    if (ACT == 2) {
        #pragma unroll
        for (int mi = 0; mi < 4; mi++) {
            #pragma unroll
            for (int ni = 0; ni < 4; ni++) {
                const int c = warp_n * 32 + ni * 8 + (t << 1);
                float2 bb = *reinterpret_cast<const float2*>(&bias[c]);
                acc[mi][ni][0] += bb.x; acc[mi][ni][1] += bb.y;
                acc[mi][ni][2] += bb.x; acc[mi][ni][3] += bb.y;
            }
            float s0 = 0.f, q0 = 0.f, s1 = 0.f, q1 = 0.f;
            #pragma unroll
            for (int ni = 0; ni < 4; ni++) {
                s0 += acc[mi][ni][0] + acc[mi][ni][1];
                q0 += acc[mi][ni][0]*acc[mi][ni][0] + acc[mi][ni][1]*acc[mi][ni][1];
                s1 += acc[mi][ni][2] + acc[mi][ni][3];
                q1 += acc[mi][ni][2]*acc[mi][ni][2] + acc[mi][ni][3]*acc[mi][ni][3];
            }
            s0 += __shfl_xor_sync(0xffffffffu, s0, 1);
            s0 += __shfl_xor_sync(0xffffffffu, s0, 2);
            q0 += __shfl_xor_sync(0xffffffffu, q0, 1);
            q0 += __shfl_xor_sync(0xffffffffu, q0, 2);
            s1 += __shfl_xor_sync(0xffffffffu, s1, 1);
            s1 += __shfl_xor_sync(0xffffffffu, s1, 2);
            q1 += __shfl_xor_sync(0xffffffffu, q1, 1);
            q1 += __shfl_xor_sync(0xffffffffu, q1, 2);
            if (t == 0) {
                const int rl = warp_m * 64 + mi * 16 + g;
                red[rl][warp_n]     = make_float2(s0, q0);
                red[rl + 8][warp_n] = make_float2(s1, q1);
            }
        }
        __syncthreads();

        #pragma unroll
        for (int mi = 0; mi < 4; mi++) {
            const int rl0 = warp_m * 64 + mi * 16 + g;
            const int rl1 = rl0 + 8;
            float2 p;
            float s0 = 0.f, q0 = 0.f, s1 = 0.f, q1 = 0.f;
            #pragma unroll
            for (int w = 0; w < 4; w++) {
                p = red[rl0][w]; s0 += p.x; q0 += p.y;
                p = red[rl1][w]; s1 += p.x; q1 += p.y;
            }
            const float mu0 = s0 * (1.f/128.f);
            const float mu1 = s1 * (1.f/128.f);
            const float rs0 = rsqrtf(q0 * (1.f/128.f) - mu0*mu0 + 1e-5f);
            const float rs1 = rsqrtf(q1 * (1.f/128.f) - mu1*mu1 + 1e-5f);

            const size_t gr0 = (size_t)(brow + rl0) * 128;
            const size_t gr1 = (size_t)(brow + rl1) * 128;
            #pragma unroll
            for (int ni = 0; ni < 4; ni++) {
                const int c = warp_n * 32 + ni * 8 + (t << 1);
                float2 wv = *reinterpret_cast<const float2*>(&lnw[c]);
                float2 bv = *reinterpret_cast<const float2*>(&lnb[c]);
                float2 r0v = *reinterpret_cast<const float2*>(&res[gr0 + c]);
                float2 r1v = *reinterpret_cast<const float2*>(&res[gr1 + c]);
                float2 o0, o1;
                o0.x = r0v.x + (acc[mi][ni][0] - mu0) * rs0 * wv.x + bv.x;
                o0.y = r0v.y + (acc[mi][ni][1] - mu0) * rs0 * wv.y + bv.y;
                o1.x = r1v.x + (acc[mi][ni][2] - mu1) * rs1 * wv.x + bv.x;
                o1.y = r1v.y + (acc[mi][ni][3] - mu1) * rs1 * wv.y + bv.y;
                *reinterpret_cast<float2*>(&Cf[gr0 + c]) = o0;
                *reinterpret_cast<float2*>(&Cf[gr1 + c]) = o1;
            }
        }
        return;
    }

    #pragma unroll
    for (int mi = 0; mi < 4; mi++) {
        #pragma unroll
        for (int ni = 0; ni < 4; ni++) {
            const int r0 = brow + warp_m * 64 + mi * 16 + g;
            const int c  = bcol + warp_n * 32 + ni * 8 + (t << 1);
            float2 bb = *reinterpret_cast<const float2*>(&bias[c]);
            float2 v0, v1;
            v0.x = acc[mi][ni][0] + bb.x; v0.y = acc[mi][ni][1] + bb.y;
            v1.x = acc[mi][ni][2] + bb.x; v1.y = acc[mi][ni][3] + bb.y;
            if (ACT == 1) {
                v0.x *= normcdff(v0.x); v0.y *= normcdff(v0.y);
                v1.x *= normcdff(v1.x); v1.y *= normcdff(v1.y);
            }
            if (C_HALF) {
                *reinterpret_cast<__half2*>(&Ch[(size_t)r0 * N + c]) =
                    __float22half2_rn(v0);
                *reinterpret_cast<__half2*>(&Ch[(size_t)(r0 + 8) * N + c]) =
                    __float22half2_rn(v1);
            } else {
                *reinterpret_cast<float2*>(&Cf[(size_t)r0 * N + c])       = v0;
                *reinterpret_cast<float2*>(&Cf[(size_t)(r0 + 8) * N + c]) = v1;
            }
        }
    }
}

// ---------------------------------------------------------------------------
// Bias in mma C-fragment layout, pre-multiplied by log2(e).
// ---------------------------------------------------------------------------
__global__ void biasf_kernel(const int* __restrict__ rpi,
                             const float* __restrict__ table,
                             uint2* __restrict__ biasF)
{
    const int qb = blockIdx.x >> 5;
    const int jt = blockIdx.x & 31;
    const int hd = blockIdx.y;
    const int lane = threadIdx.x;
    const int g = lane >> 2, t = lane & 3;
    const int i0 = qb * 16, j0 = jt * 8;

    float b00 = table[rpi[(i0 + g)     * NTOK + j0 + 2*t    ] * NH + hd] * LOG2E;
    float b01 = table[rpi[(i0 + g)     * NTOK + j0 + 2*t + 1] * NH + hd] * LOG2E;
    float b10 = table[rpi[(i0 + g + 8) * NTOK + j0 + 2*t    ] * NH + hd] * LOG2E;
    float b11 = table[rpi[(i0 + g + 8) * NTOK + j0 + 2*t + 1] * NH + hd] * LOG2E;

    uint2 r;
    *reinterpret_cast<__half2*>(&r.x) = __floats2half2_rn(b00, b01);
    *reinterpret_cast<__half2*>(&r.y) = __floats2half2_rn(b10, b11);
    biasF[((size_t)(hd * 16 + qb) * 32 + jt) * 32 + lane] = r;
}

// ---------------------------------------------------------------------------
// Tensor-core window attention. Block = (window, head), 128 threads (4 warps).
// qkv input fp16. q scaled by scale*log2e; bias pre-scaled by log2e;
// p = ex2(s + b) UNSHIFTED (max logit*log2e ~ 14.5 -> p <= ~23000, fp16-safe;
// the common factor cancels in p/l). S = qh*kh + qh*kl. PV = p*vh.
// ---------------------------------------------------------------------------
#define SKH  0
#define SKL  (256*24)
#define SVTH (2*256*24)
#define ATTN_SMEM_HALFS (2*256*24 + 16*264)

__global__ __launch_bounds__(128) void attn_tc_kernel(
    const __half* __restrict__ qkv, const uint2* __restrict__ biasF,
    const float* __restrict__ logit_scale, __half* __restrict__ attn_out)
{
    __shared__ __half sm[ATTN_SMEM_HALFS];

    const int wi = blockIdx.x;
    const int hd = blockIdx.y;
    const int tid = threadIdx.x;

    const int bimg = wi / 144;
    const int wrem = wi % 144;
    const int wr = wrem / WPR, wc = wrem % WPR;
    const int rowbase = bimg * (IMG * IMG) + (wr * 16) * IMG + wc * 16;

    const float scale = __expf(fminf(logit_scale[hd], 4.6051702f)); // ln(100)
    const float qmul  = scale * LOG2E;

    // ---- stage k (normalized, hi/lo) and v (transposed, verbatim fp16)
    for (int tok = tid; tok < NTOK; tok += 128) {
        const int m = rowbase + (tok >> 4) * IMG + (tok & 15);
        const __half* base = qkv + (size_t)m * 384 + hd * HD;

        uint4 kraw0 = *reinterpret_cast<const uint4*>(base + 128);
        uint4 kraw1 = *reinterpret_cast<const uint4*>(base + 136);
        uint4 vraw0 = *reinterpret_cast<const uint4*>(base + 256);
        uint4 vraw1 = *reinterpret_cast<const uint4*>(base + 264);

        float kf[16];
        {
            const __half2* k2a = reinterpret_cast<const __half2*>(&kraw0);
            const __half2* k2b = reinterpret_cast<const __half2*>(&kraw1);
            #pragma unroll
            for (int z = 0; z < 4; z++) {
                float2 f = __half22float2(k2a[z]);
                kf[2*z] = f.x; kf[2*z+1] = f.y;
                f = __half22float2(k2b[z]);
                kf[8+2*z] = f.x; kf[8+2*z+1] = f.y;
            }
        }
        float ks = 0.f;
        #pragma unroll
        for (int z = 0; z < 16; z++) ks += kf[z] * kf[z];
        const float kr = 1.f / fmaxf(sqrtf(ks), 1e-12f);
        #pragma unroll
        for (int z = 0; z < 16; z++) {
            float kv = kf[z] * kr;
            __half kh = __float2half_rn(kv);
            sm[SKH + tok*24 + z] = kh;
            sm[SKL + tok*24 + z] = __float2half_rn(kv - __half2float(kh));
        }
        const __half* vh = reinterpret_cast<const __half*>(&vraw0);
        #pragma unroll
        for (int z = 0; z < 8; z++) sm[SVTH + z*264 + tok] = vh[z];
        vh = reinterpret_cast<const __half*>(&vraw1);
        #pragma unroll
        for (int z = 0; z < 8; z++) sm[SVTH + (8+z)*264 + tok] = vh[z];
    }
    __syncthreads();

    const int warp = tid >> 5;
    const int lane = tid & 31;
    const int g = lane >> 2;
    const int t = lane & 3;

    for (int qi = 0; qi < 4; qi++) {
        const int qb = warp * 4 + qi;
        const int i0 = qb * 16;
        const int r0 = i0 + g, r1 = i0 + g + 8;
        const int m0 = rowbase + (r0 >> 4) * IMG + (r0 & 15);
        const int m1 = rowbase + (r1 >> 4) * IMG + (r1 & 15);

        const __half* q0p = qkv + (size_t)m0 * 384 + hd * HD;
        const __half* q1p = qkv + (size_t)m1 * 384 + hd * HD;
        float2 a00 = __half22float2(*reinterpret_cast<const __half2*>(q0p + 2*t));
        float2 a01 = __half22float2(*reinterpret_cast<const __half2*>(q0p + 2*t + 8));
        float2 a10 = __half22float2(*reinterpret_cast<const __half2*>(q1p + 2*t));
        float2 a11 = __half22float2(*reinterpret_cast<const __half2*>(q1p + 2*t + 8));

        float s0 = a00.x*a00.x + a00.y*a00.y + a01.x*a01.x + a01.y*a01.y;
        float s1 = a10.x*a10.x + a10.y*a10.y + a11.x*a11.x + a11.y*a11.y;
        s0 += __shfl_xor_sync(0xffffffffu, s0, 1);
        s0 += __shfl_xor_sync(0xffffffffu, s0, 2);
        s1 += __shfl_xor_sync(0xffffffffu, s1, 1);
        s1 += __shfl_xor_sync(0xffffffffu, s1, 2);
        const float qr0 = qmul / fmaxf(sqrtf(s0), 1e-12f);
        const float qr1 = qmul / fmaxf(sqrtf(s1), 1e-12f);

        u32 qa[4];
        {
            __half2 h;
            h = __floats2half2_rn(a00.x * qr0, a00.y * qr0); qa[0] = *reinterpret_cast<u32*>(&h);
            h = __floats2half2_rn(a10.x * qr1, a10.y * qr1); qa[1] = *reinterpret_cast<u32*>(&h);
            h = __floats2half2_rn(a01.x * qr0, a01.y * qr0); qa[2] = *reinterpret_cast<u32*>(&h);
            h = __floats2half2_rn(a11.x * qr1, a11.y * qr1); qa[3] = *reinterpret_cast<u32*>(&h);
        }

        float o0[4] = {0.f,0.f,0.f,0.f};
        float o1[4] = {0.f,0.f,0.f,0.f};
        float l0 = 0.f, l1 = 0.f;

        const uint2* bp = biasF + ((size_t)(hd * 16 + qb) * 32) * 32 + lane;

        uint2 bcur[8], bnxt[8];
        #pragma unroll
        for (int u = 0; u < 8; u++) bcur[u] = __ldg(&bp[u * 32]);

        u32 pa0 = 0, pa1 = 0;

        #pragma unroll 1
        for (int bt = 0; bt < 4; bt++) {
            if (bt < 3) {
                #pragma unroll
                for (int u = 0; u < 8; u++)
                    bnxt[u] = __ldg(&bp[(bt * 8 + 8 + u) * 32]);
            }
            #pragma unroll
            for (int u = 0; u < 8; u++) {
                const int jt = bt * 8 + u;
                const int j0 = jt * 8;

                u32 kh0 = *reinterpret_cast<u32*>(&sm[SKH + (j0+g)*24 + 2*t]);
                u32 kh1 = *reinterpret_cast<u32*>(&sm[SKH + (j0+g)*24 + 2*t + 8]);
                u32 kl0 = *reinterpret_cast<u32*>(&sm[SKL + (j0+g)*24 + 2*t]);
                u32 kl1 = *reinterpret_cast<u32*>(&sm[SKL + (j0+g)*24 + 2*t + 8]);

                float s0v = 0.f, s1v = 0.f, s2v = 0.f, s3v = 0.f;
                MMA16816(s0v,s1v,s2v,s3v, qa[0],qa[1],qa[2],qa[3], kh0,kh1);
                MMA16816(s0v,s1v,s2v,s3v, qa[0],qa[1],qa[2],qa[3], kl0,kl1);

                uint2 bb = bcur[u];
                float2 blo = __half22float2(*reinterpret_cast<__half2*>(&bb.x));
                float2 bhi = __half22float2(*reinterpret_cast<__half2*>(&bb.y));
                float p0 = ex2(s0v + blo.x);
                float p1 = ex2(s1v + blo.y);
                float p2 = ex2(s2v + bhi.x);
                float p3 = ex2(s3v + bhi.y);
                l0 += p0 + p1;
                l1 += p2 + p3;
                __half2 plo = __floats2half2_rn(p0, p1);
                __half2 phi = __floats2half2_rn(p2, p3);

                if ((u & 1) == 0) {
                    pa0 = *reinterpret_cast<u32*>(&plo);
                    pa1 = *reinterpret_cast<u32*>(&phi);
                } else {
                    u32 pa2 = *reinterpret_cast<u32*>(&plo);
                    u32 pa3 = *reinterpret_cast<u32*>(&phi);
                    const int jb = (jt - 1) * 8;
                    u32 vh0 = *reinterpret_cast<u32*>(&sm[SVTH + g*264 + jb + 2*t]);
                    u32 vh1 = *reinterpret_cast<u32*>(&sm[SVTH + g*264 + jb + 2*t + 8]);
                    MMA16816(o0[0],o0[1],o0[2],o0[3], pa0,pa1,pa2,pa3, vh0,vh1);
                    u32 wh0 = *reinterpret_cast<u32*>(&sm[SVTH + (8+g)*264 + jb + 2*t]);
                    u32 wh1 = *reinterpret_cast<u32*>(&sm[SVTH + (8+g)*264 + jb + 2*t + 8]);
                    MMA16816(o1[0],o1[1],o1[2],o1[3], pa0,pa1,pa2,pa3, wh0,wh1);
                }
            }
            #pragma unroll
            for (int u = 0; u < 8; u++) bcur[u] = bnxt[u];
        }

        l0 += __shfl_xor_sync(0xffffffffu, l0, 1);
        l0 += __shfl_xor_sync(0xffffffffu, l0, 2);
        l1 += __shfl_xor_sync(0xffffffffu, l1, 1);
        l1 += __shfl_xor_sync(0xffffffffu, l1, 2);
        const float inv0 = 1.f / l0, inv1 = 1.f / l1;

        const int col = hd * HD + 2 * t;
        *reinterpret_cast<__half2*>(&attn_out[(size_t)m0 * C_DIM + col]) =
            __floats2half2_rn(o0[0] * inv0, o0[1] * inv0);
        *reinterpret_cast<__half2*>(&attn_out[(size_t)m1 * C_DIM + col]) =
            __floats2half2_rn(o0[2] * inv1, o0[3] * inv1);
        *reinterpret_cast<__half2*>(&attn_out[(size_t)m0 * C_DIM + col + 8]) =
            __floats2half2_rn(o1[0] * inv0, o1[1] * inv0);
        *reinterpret_cast<__half2*>(&attn_out[(size_t)m1 * C_DIM + col + 8]) =
            __floats2half2_rn(o1[2] * inv1, o1[3] * inv1);
    }
}

// ---------------------------------------------------------------------------
extern "C" void kernel_launch(void* const* d_in, const int* in_sizes, int n_in,
                              void* d_out, int out_size)
{
    const float* x           = (const float*)d_in[0];
    const float* qkv_w       = (const float*)d_in[1];
    const float* qkv_b       = (const float*)d_in[2];
    const float* proj_w      = (const float*)d_in[3];
    const float* proj_b      = (const float*)d_in[4];
    const float* logit_scale = (const float*)d_in[5];
    const float* rpb_table   = (const float*)d_in[6];
    const float* n1w         = (const float*)d_in[7];
    const float* n1b         = (const float*)d_in[8];
    const float* n2w         = (const float*)d_in[9];
    const float* n2b         = (const float*)d_in[10];
    const float* fc1_w       = (const float*)d_in[11];
    const float* fc1_b       = (const float*)d_in[12];
    const float* fc2_w       = (const float*)d_in[13];
    const float* fc2_b       = (const float*)d_in[14];
    const int*   rpi         = (const int*)d_in[17];
    float* out = (float*)d_out;

    float *p_x1;
    __half *p_qkvh, *p_attnh, *p_hidh;
    uint2 *p_biasF;
    cudaGetSymbolAddress((void**)&p_qkvh,  g_qkvh);
    cudaGetSymbolAddress((void**)&p_biasF, g_biasF);
    cudaGetSymbolAddress((void**)&p_attnh, g_attnh);
    cudaGetSymbolAddress((void**)&p_x1,    g_x1);
    cudaGetSymbolAddress((void**)&p_hidh,  g_hidh);

    // 1) bias fragments (pre-scaled by log2e)
    biasf_kernel<<<dim3(16 * 32, NH), 32>>>(rpi, rpb_table, p_biasF);

    // 2) QKV: fp32 A, fp16 C
    hgemm_kernel<false,true,0><<<dim3(384/128, M_TOK/128), 256>>>(
        x, qkv_w, qkv_b, p_qkvh, M_TOK, 384, 128, nullptr, nullptr, nullptr);

    // 3) tensor-core window attention (fp16 in/out)
    attn_tc_kernel<<<dim3(NWIN, NH), 128>>>(p_qkvh, p_biasF, logit_scale, p_attnh);

    // 4) proj + fused LN + residual: x1 = x + LN(attn @ proj_w + proj_b)
    hgemm_kernel<true,false,2><<<dim3(1, M_TOK/128), 256>>>(
        p_attnh, proj_w, proj_b, p_x1, M_TOK, 128, 128, x, n1w, n1b);

    // 5) fc1 + GELU: fp32 A, fp16 C
    hgemm_kernel<false,true,1><<<dim3(256/128, M_TOK/128), 256>>>(
        p_x1, fc1_w, fc1_b, p_hidh, M_TOK, 256, 128, nullptr, nullptr, nullptr);

    // 6) fc2 + fused LN + residual: out = x1 + LN(hid @ fc2_w + fc2_b)
    hgemm_kernel<true,false,2><<<dim3(1, M_TOK/128), 256>>>(
        p_hidh, fc2_w, fc2_b, out, M_TOK, 128, 256, p_x1, n2w, n2b);
}

// round 11
// speedup vs baseline: 4.0219x; 1.0031x over previous
#include <cuda_runtime.h>
#include <cuda_fp16.h>
#include <cuda_bf16.h>
#include <math_constants.h>

// ---------------------------------------------------------------------------
// SwinV2 block: window cosine-attention + res-post-norm MLP
// b=2, H=W=192, C=128, WS=16, NH=8, d=16
// GEMMs + attention on fp16 tensor cores, fp32 accumulate.
// qkv intermediate fp16; unshifted exp2 softmax; LN fused into proj/fc2.
// Attention tuned for occupancy: launch_bounds(128,6), no bias double-buffer.
// ---------------------------------------------------------------------------

#define M_TOK   73728
#define C_DIM   128
#define NH      8
#define HD      16
#define NWIN    288
#define NTOK    256
#define IMG     192
#define WPR     12
#define LOG2E   1.4426950408889634f

typedef unsigned int u32;

__device__ __half g_qkvh [ (size_t)M_TOK * 384 ];
__device__ uint2  g_biasF[ (size_t)NH * 16 * 32 * 32 ];  // C-fragment layout
__device__ __half g_attnh[ (size_t)M_TOK * C_DIM ];
__device__ float  g_x1   [ (size_t)M_TOK * C_DIM ];
__device__ __half g_hidh [ (size_t)M_TOK * 256 ];

#define MMA16816(d0,d1,d2,d3,a0,a1,a2,a3,b0,b1)                          \
    asm volatile(                                                        \
        "mma.sync.aligned.m16n8k16.row.col.f32.f16.f16.f32 "             \
        "{%0,%1,%2,%3}, {%4,%5,%6,%7}, {%8,%9}, {%0,%1,%2,%3};"          \
        : "+f"(d0), "+f"(d1), "+f"(d2), "+f"(d3)                         \
        : "r"(a0), "r"(a1), "r"(a2), "r"(a3), "r"(b0), "r"(b1))

__device__ __forceinline__ float ex2(float x)
{
    float r;
    asm("ex2.approx.f32 %0, %1;" : "=f"(r) : "f"(x));
    return r;
}

// ---------------------------------------------------------------------------
// fp16 tensor-core GEMM (unchanged from round 10).
// ---------------------------------------------------------------------------
template<bool A_HALF, bool C_HALF, int ACT>
__global__ __launch_bounds__(256) void hgemm_kernel(
    const void* __restrict__ Av, const float* __restrict__ B,
    const float* __restrict__ bias, void* __restrict__ Cv,
    int M, int N, int K,
    const float* __restrict__ res,
    const float* __restrict__ lnw, const float* __restrict__ lnb)
{
    __shared__ __half As[128][40];
    __shared__ __half Bs[32][136];
    __shared__ float2 red[128][4];

    const float*  Af = (const float*)Av;
    const __half* Ah = (const __half*)Av;
    float*  Cf = (float*)Cv;
    __half* Ch = (__half*)Cv;

    const int tid  = threadIdx.x;
    const int lane = tid & 31;
    const int wid  = tid >> 5;
    const int warp_m = wid >> 2;
    const int warp_n = wid & 3;
    const int brow = blockIdx.y * 128;
    const int bcol = blockIdx.x * 128;

    const int a_m0 = tid >> 3;
    const int a_k4 = (tid & 7) << 2;
    const int a_m0h = tid >> 2;
    const int a_k8  = (tid & 3) << 3;
    const int b_k0 = tid >> 5;
    const int b_n4 = (tid & 31) << 2;

    const u32 a_smem = (u32)__cvta_generic_to_shared(&As[0][0]);
    const u32 b_smem = (u32)__cvta_generic_to_shared(&Bs[0][0]);

    float acc[4][4][4];
    #pragma unroll
    for (int mi = 0; mi < 4; mi++)
        #pragma unroll
        for (int ni = 0; ni < 4; ni++)
            #pragma unroll
            for (int z = 0; z < 4; z++) acc[mi][ni][z] = 0.f;

    float4 a_pf[4];
    uint4  a_pfh[2];
    float4 b_pf[4];
    if (A_HALF) {
        #pragma unroll
        for (int t = 0; t < 2; t++)
            a_pfh[t] = *reinterpret_cast<const uint4*>(
                &Ah[(size_t)(brow + a_m0h + t * 64) * K + a_k8]);
    } else {
        #pragma unroll
        for (int t = 0; t < 4; t++)
            a_pf[t] = *reinterpret_cast<const float4*>(
                &Af[(size_t)(brow + a_m0 + t * 32) * K + a_k4]);
    }
    #pragma unroll
    for (int t = 0; t < 4; t++)
        b_pf[t] = *reinterpret_cast<const float4*>(
            &B[(size_t)(b_k0 + t * 8) * N + bcol + b_n4]);

    for (int kt = 0; kt < K; kt += 32) {
        if (A_HALF) {
            #pragma unroll
            for (int t = 0; t < 2; t++)
                *reinterpret_cast<uint4*>(&As[a_m0h + t * 64][a_k8]) = a_pfh[t];
        } else {
            #pragma unroll
            for (int t = 0; t < 4; t++) {
                __half2 h0 = __float22half2_rn(make_float2(a_pf[t].x, a_pf[t].y));
                __half2 h1 = __float22half2_rn(make_float2(a_pf[t].z, a_pf[t].w));
                *reinterpret_cast<__half2*>(&As[a_m0 + t * 32][a_k4 + 0]) = h0;
                *reinterpret_cast<__half2*>(&As[a_m0 + t * 32][a_k4 + 2]) = h1;
            }
        }
        #pragma unroll
        for (int t = 0; t < 4; t++) {
            __half2 g0 = __float22half2_rn(make_float2(b_pf[t].x, b_pf[t].y));
            __half2 g1 = __float22half2_rn(make_float2(b_pf[t].z, b_pf[t].w));
            *reinterpret_cast<__half2*>(&Bs[b_k0 + t * 8][b_n4 + 0]) = g0;
            *reinterpret_cast<__half2*>(&Bs[b_k0 + t * 8][b_n4 + 2]) = g1;
        }
        __syncthreads();

        if (kt + 32 < K) {
            if (A_HALF) {
                #pragma unroll
                for (int t = 0; t < 2; t++)
                    a_pfh[t] = *reinterpret_cast<const uint4*>(
                        &Ah[(size_t)(brow + a_m0h + t * 64) * K + kt + 32 + a_k8]);
            } else {
                #pragma unroll
                for (int t = 0; t < 4; t++)
                    a_pf[t] = *reinterpret_cast<const float4*>(
                        &Af[(size_t)(brow + a_m0 + t * 32) * K + kt + 32 + a_k4]);
            }
            #pragma unroll
            for (int t = 0; t < 4; t++)
                b_pf[t] = *reinterpret_cast<const float4*>(
                    &B[(size_t)(kt + 32 + b_k0 + t * 8) * N + bcol + b_n4]);
        }

        #pragma unroll
        for (int ks = 0; ks < 32; ks += 16) {
            u32 af[4][4];
            #pragma unroll
            for (int mi = 0; mi < 4; mi++) {
                int r = warp_m * 64 + mi * 16 + (lane & 15);
                int c = ks + ((lane >> 4) << 3);
                u32 addr = a_smem + (u32)(r * 40 + c) * 2u;
                asm volatile(
                    "ldmatrix.sync.aligned.m8n8.x4.shared.b16 {%0,%1,%2,%3}, [%4];"
                    : "=r"(af[mi][0]), "=r"(af[mi][1]), "=r"(af[mi][2]), "=r"(af[mi][3])
                    : "r"(addr));
            }
            u32 bf[4][2];
            #pragma unroll
            for (int p = 0; p < 2; p++) {
                int r = ks + (lane & 15);
                int c = warp_n * 32 + p * 16 + ((lane >> 4) << 3);
                u32 addr = b_smem + (u32)(r * 136 + c) * 2u;
                asm volatile(
                    "ldmatrix.sync.aligned.m8n8.x4.trans.shared.b16 {%0,%1,%2,%3}, [%4];"
                    : "=r"(bf[2*p][0]), "=r"(bf[2*p][1]),
                      "=r"(bf[2*p+1][0]), "=r"(bf[2*p+1][1])
                    : "r"(addr));
            }
            #pragma unroll
            for (int mi = 0; mi < 4; mi++)
                #pragma unroll
                for (int ni = 0; ni < 4; ni++) {
                    MMA16816(acc[mi][ni][0], acc[mi][ni][1],
                             acc[mi][ni][2], acc[mi][ni][3],
                             af[mi][0], af[mi][1], af[mi][2], af[mi][3],
                             bf[ni][0], bf[ni][1]);
                }
        }
        __syncthreads();
    }

    const int g = lane >> 2;
    const int t = lane & 3;

    if (ACT == 2) {
        #pragma unroll
        for (int mi = 0; mi < 4; mi++) {
            #pragma unroll
            for (int ni = 0; ni < 4; ni++) {
                const int c = warp_n * 32 + ni * 8 + (t << 1);
                float2 bb = *reinterpret_cast<const float2*>(&bias[c]);
                acc[mi][ni][0] += bb.x; acc[mi][ni][1] += bb.y;
                acc[mi][ni][2] += bb.x; acc[mi][ni][3] += bb.y;
            }
            float s0 = 0.f, q0 = 0.f, s1 = 0.f, q1 = 0.f;
            #pragma unroll
            for (int ni = 0; ni < 4; ni++) {
                s0 += acc[mi][ni][0] + acc[mi][ni][1];
                q0 += acc[mi][ni][0]*acc[mi][ni][0] + acc[mi][ni][1]*acc[mi][ni][1];
                s1 += acc[mi][ni][2] + acc[mi][ni][3];
                q1 += acc[mi][ni][2]*acc[mi][ni][2] + acc[mi][ni][3]*acc[mi][ni][3];
            }
            s0 += __shfl_xor_sync(0xffffffffu, s0, 1);
            s0 += __shfl_xor_sync(0xffffffffu, s0, 2);
            q0 += __shfl_xor_sync(0xffffffffu, q0, 1);
            q0 += __shfl_xor_sync(0xffffffffu, q0, 2);
            s1 += __shfl_xor_sync(0xffffffffu, s1, 1);
            s1 += __shfl_xor_sync(0xffffffffu, s1, 2);
            q1 += __shfl_xor_sync(0xffffffffu, q1, 1);
            q1 += __shfl_xor_sync(0xffffffffu, q1, 2);
            if (t == 0) {
                const int rl = warp_m * 64 + mi * 16 + g;
                red[rl][warp_n]     = make_float2(s0, q0);
                red[rl + 8][warp_n] = make_float2(s1, q1);
            }
        }
        __syncthreads();

        #pragma unroll
        for (int mi = 0; mi < 4; mi++) {
            const int rl0 = warp_m * 64 + mi * 16 + g;
            const int rl1 = rl0 + 8;
            float2 p;
            float s0 = 0.f, q0 = 0.f, s1 = 0.f, q1 = 0.f;
            #pragma unroll
            for (int w = 0; w < 4; w++) {
                p = red[rl0][w]; s0 += p.x; q0 += p.y;
                p = red[rl1][w]; s1 += p.x; q1 += p.y;
            }
            const float mu0 = s0 * (1.f/128.f);
            const float mu1 = s1 * (1.f/128.f);
            const float rs0 = rsqrtf(q0 * (1.f/128.f) - mu0*mu0 + 1e-5f);
            const float rs1 = rsqrtf(q1 * (1.f/128.f) - mu1*mu1 + 1e-5f);

            const size_t gr0 = (size_t)(brow + rl0) * 128;
            const size_t gr1 = (size_t)(brow + rl1) * 128;
            #pragma unroll
            for (int ni = 0; ni < 4; ni++) {
                const int c = warp_n * 32 + ni * 8 + (t << 1);
                float2 wv = *reinterpret_cast<const float2*>(&lnw[c]);
                float2 bv = *reinterpret_cast<const float2*>(&lnb[c]);
                float2 r0v = *reinterpret_cast<const float2*>(&res[gr0 + c]);
                float2 r1v = *reinterpret_cast<const float2*>(&res[gr1 + c]);
                float2 o0, o1;
                o0.x = r0v.x + (acc[mi][ni][0] - mu0) * rs0 * wv.x + bv.x;
                o0.y = r0v.y + (acc[mi][ni][1] - mu0) * rs0 * wv.y + bv.y;
                o1.x = r1v.x + (acc[mi][ni][2] - mu1) * rs1 * wv.x + bv.x;
                o1.y = r1v.y + (acc[mi][ni][3] - mu1) * rs1 * wv.y + bv.y;
                *reinterpret_cast<float2*>(&Cf[gr0 + c]) = o0;
                *reinterpret_cast<float2*>(&Cf[gr1 + c]) = o1;
            }
        }
        return;
    }

    #pragma unroll
    for (int mi = 0; mi < 4; mi++) {
        #pragma unroll
        for (int ni = 0; ni < 4; ni++) {
            const int r0 = brow + warp_m * 64 + mi * 16 + g;
            const int c  = bcol + warp_n * 32 + ni * 8 + (t << 1);
            float2 bb = *reinterpret_cast<const float2*>(&bias[c]);
            float2 v0, v1;
            v0.x = acc[mi][ni][0] + bb.x; v0.y = acc[mi][ni][1] + bb.y;
            v1.x = acc[mi][ni][2] + bb.x; v1.y = acc[mi][ni][3] + bb.y;
            if (ACT == 1) {
                v0.x *= normcdff(v0.x); v0.y *= normcdff(v0.y);
                v1.x *= normcdff(v1.x); v1.y *= normcdff(v1.y);
            }
            if (C_HALF) {
                *reinterpret_cast<__half2*>(&Ch[(size_t)r0 * N + c]) =
                    __float22half2_rn(v0);
                *reinterpret_cast<__half2*>(&Ch[(size_t)(r0 + 8) * N + c]) =
                    __float22half2_rn(v1);
            } else {
                *reinterpret_cast<float2*>(&Cf[(size_t)r0 * N + c])       = v0;
                *reinterpret_cast<float2*>(&Cf[(size_t)(r0 + 8) * N + c]) = v1;
            }
        }
    }
}

// ---------------------------------------------------------------------------
// Bias in mma C-fragment layout, pre-multiplied by log2(e).
// ---------------------------------------------------------------------------
__global__ void biasf_kernel(const int* __restrict__ rpi,
                             const float* __restrict__ table,
                             uint2* __restrict__ biasF)
{
    const int qb = blockIdx.x >> 5;
    const int jt = blockIdx.x & 31;
    const int hd = blockIdx.y;
    const int lane = threadIdx.x;
    const int g = lane >> 2, t = lane & 3;
    const int i0 = qb * 16, j0 = jt * 8;

    float b00 = table[rpi[(i0 + g)     * NTOK + j0 + 2*t    ] * NH + hd] * LOG2E;
    float b01 = table[rpi[(i0 + g)     * NTOK + j0 + 2*t + 1] * NH + hd] * LOG2E;
    float b10 = table[rpi[(i0 + g + 8) * NTOK + j0 + 2*t    ] * NH + hd] * LOG2E;
    float b11 = table[rpi[(i0 + g + 8) * NTOK + j0 + 2*t + 1] * NH + hd] * LOG2E;

    uint2 r;
    *reinterpret_cast<__half2*>(&r.x) = __floats2half2_rn(b00, b01);
    *reinterpret_cast<__half2*>(&r.y) = __floats2half2_rn(b10, b11);
    biasF[((size_t)(hd * 16 + qb) * 32 + jt) * 32 + lane] = r;
}

// ---------------------------------------------------------------------------
// Tensor-core window attention. Block = (window, head), 128 threads (4 warps),
// __launch_bounds__(128, 6) for >=6 blocks/SM (smem 32.25 KB).
// Bias loaded per jtile-pair via __ldg (L2-resident, MLP-covered).
// Math identical to round 10.
// ---------------------------------------------------------------------------
#define SKH  0
#define SKL  (256*24)
#define SVTH (2*256*24)
#define ATTN_SMEM_HALFS (2*256*24 + 16*264)

__global__ __launch_bounds__(128, 6) void attn_tc_kernel(
    const __half* __restrict__ qkv, const uint2* __restrict__ biasF,
    const float* __restrict__ logit_scale, __half* __restrict__ attn_out)
{
    __shared__ __half sm[ATTN_SMEM_HALFS];

    const int wi = blockIdx.x;
    const int hd = blockIdx.y;
    const int tid = threadIdx.x;

    const int bimg = wi / 144;
    const int wrem = wi % 144;
    const int wr = wrem / WPR, wc = wrem % WPR;
    const int rowbase = bimg * (IMG * IMG) + (wr * 16) * IMG + wc * 16;

    const float scale = __expf(fminf(logit_scale[hd], 4.6051702f)); // ln(100)
    const float qmul  = scale * LOG2E;

    // ---- stage k (normalized, hi/lo) and v (transposed, verbatim fp16)
    for (int tok = tid; tok < NTOK; tok += 128) {
        const int m = rowbase + (tok >> 4) * IMG + (tok & 15);
        const __half* base = qkv + (size_t)m * 384 + hd * HD;

        uint4 kraw0 = *reinterpret_cast<const uint4*>(base + 128);
        uint4 kraw1 = *reinterpret_cast<const uint4*>(base + 136);
        uint4 vraw0 = *reinterpret_cast<const uint4*>(base + 256);
        uint4 vraw1 = *reinterpret_cast<const uint4*>(base + 264);

        float kf[16];
        {
            const __half2* k2a = reinterpret_cast<const __half2*>(&kraw0);
            const __half2* k2b = reinterpret_cast<const __half2*>(&kraw1);
            #pragma unroll
            for (int z = 0; z < 4; z++) {
                float2 f = __half22float2(k2a[z]);
                kf[2*z] = f.x; kf[2*z+1] = f.y;
                f = __half22float2(k2b[z]);
                kf[8+2*z] = f.x; kf[8+2*z+1] = f.y;
            }
        }
        float ks = 0.f;
        #pragma unroll
        for (int z = 0; z < 16; z++) ks += kf[z] * kf[z];
        const float kr = 1.f / fmaxf(sqrtf(ks), 1e-12f);
        #pragma unroll
        for (int z = 0; z < 16; z++) {
            float kv = kf[z] * kr;
            __half kh = __float2half_rn(kv);
            sm[SKH + tok*24 + z] = kh;
            sm[SKL + tok*24 + z] = __float2half_rn(kv - __half2float(kh));
        }
        const __half* vh = reinterpret_cast<const __half*>(&vraw0);
        #pragma unroll
        for (int z = 0; z < 8; z++) sm[SVTH + z*264 + tok] = vh[z];
        vh = reinterpret_cast<const __half*>(&vraw1);
        #pragma unroll
        for (int z = 0; z < 8; z++) sm[SVTH + (8+z)*264 + tok] = vh[z];
    }
    __syncthreads();

    const int warp = tid >> 5;
    const int lane = tid & 31;
    const int g = lane >> 2;
    const int t = lane & 3;

    for (int qi = 0; qi < 4; qi++) {
        const int qb = warp * 4 + qi;
        const int i0 = qb * 16;
        const int r0 = i0 + g, r1 = i0 + g + 8;
        const int m0 = rowbase + (r0 >> 4) * IMG + (r0 & 15);
        const int m1 = rowbase + (r1 >> 4) * IMG + (r1 & 15);

        const __half* q0p = qkv + (size_t)m0 * 384 + hd * HD;
        const __half* q1p = qkv + (size_t)m1 * 384 + hd * HD;
        float2 a00 = __half22float2(*reinterpret_cast<const __half2*>(q0p + 2*t));
        float2 a01 = __half22float2(*reinterpret_cast<const __half2*>(q0p + 2*t + 8));
        float2 a10 = __half22float2(*reinterpret_cast<const __half2*>(q1p + 2*t));
        float2 a11 = __half22float2(*reinterpret_cast<const __half2*>(q1p + 2*t + 8));

        float s0 = a00.x*a00.x + a00.y*a00.y + a01.x*a01.x + a01.y*a01.y;
        float s1 = a10.x*a10.x + a10.y*a10.y + a11.x*a11.x + a11.y*a11.y;
        s0 += __shfl_xor_sync(0xffffffffu, s0, 1);
        s0 += __shfl_xor_sync(0xffffffffu, s0, 2);
        s1 += __shfl_xor_sync(0xffffffffu, s1, 1);
        s1 += __shfl_xor_sync(0xffffffffu, s1, 2);
        const float qr0 = qmul / fmaxf(sqrtf(s0), 1e-12f);
        const float qr1 = qmul / fmaxf(sqrtf(s1), 1e-12f);

        u32 qa[4];
        {
            __half2 h;
            h = __floats2half2_rn(a00.x * qr0, a00.y * qr0); qa[0] = *reinterpret_cast<u32*>(&h);
            h = __floats2half2_rn(a10.x * qr1, a10.y * qr1); qa[1] = *reinterpret_cast<u32*>(&h);
            h = __floats2half2_rn(a01.x * qr0, a01.y * qr0); qa[2] = *reinterpret_cast<u32*>(&h);
            h = __floats2half2_rn(a11.x * qr1, a11.y * qr1); qa[3] = *reinterpret_cast<u32*>(&h);
        }

        float o0[4] = {0.f,0.f,0.f,0.f};
        float o1[4] = {0.f,0.f,0.f,0.f};
        float l0 = 0.f, l1 = 0.f;

        const uint2* bp = biasF + ((size_t)(hd * 16 + qb) * 32) * 32 + lane;

        #pragma unroll 2
        for (int jp = 0; jp < 16; jp++) {
            const int j0a = (2 * jp) * 8;
            const int j0b = (2 * jp + 1) * 8;
            uint2 bb0 = __ldg(&bp[(2 * jp) * 32]);
            uint2 bb1 = __ldg(&bp[(2 * jp + 1) * 32]);

            // jtile even
            u32 kh0 = *reinterpret_cast<u32*>(&sm[SKH + (j0a+g)*24 + 2*t]);
            u32 kh1 = *reinterpret_cast<u32*>(&sm[SKH + (j0a+g)*24 + 2*t + 8]);
            u32 kl0 = *reinterpret_cast<u32*>(&sm[SKL + (j0a+g)*24 + 2*t]);
            u32 kl1 = *reinterpret_cast<u32*>(&sm[SKL + (j0a+g)*24 + 2*t + 8]);
            float sa0 = 0.f, sa1 = 0.f, sa2 = 0.f, sa3 = 0.f;
            MMA16816(sa0,sa1,sa2,sa3, qa[0],qa[1],qa[2],qa[3], kh0,kh1);
            MMA16816(sa0,sa1,sa2,sa3, qa[0],qa[1],qa[2],qa[3], kl0,kl1);

            // jtile odd
            u32 mh0 = *reinterpret_cast<u32*>(&sm[SKH + (j0b+g)*24 + 2*t]);
            u32 mh1 = *reinterpret_cast<u32*>(&sm[SKH + (j0b+g)*24 + 2*t + 8]);
            u32 ml0 = *reinterpret_cast<u32*>(&sm[SKL + (j0b+g)*24 + 2*t]);
            u32 ml1 = *reinterpret_cast<u32*>(&sm[SKL + (j0b+g)*24 + 2*t + 8]);
            float sb0 = 0.f, sb1 = 0.f, sb2 = 0.f, sb3 = 0.f;
            MMA16816(sb0,sb1,sb2,sb3, qa[0],qa[1],qa[2],qa[3], mh0,mh1);
            MMA16816(sb0,sb1,sb2,sb3, qa[0],qa[1],qa[2],qa[3], ml0,ml1);

            float2 blo0 = __half22float2(*reinterpret_cast<__half2*>(&bb0.x));
            float2 bhi0 = __half22float2(*reinterpret_cast<__half2*>(&bb0.y));
            float2 blo1 = __half22float2(*reinterpret_cast<__half2*>(&bb1.x));
            float2 bhi1 = __half22float2(*reinterpret_cast<__half2*>(&bb1.y));

            float p0 = ex2(sa0 + blo0.x);
            float p1 = ex2(sa1 + blo0.y);
            float p2 = ex2(sa2 + bhi0.x);
            float p3 = ex2(sa3 + bhi0.y);
            float p4 = ex2(sb0 + blo1.x);
            float p5 = ex2(sb1 + blo1.y);
            float p6 = ex2(sb2 + bhi1.x);
            float p7 = ex2(sb3 + bhi1.y);
            l0 += p0 + p1 + p4 + p5;
            l1 += p2 + p3 + p6 + p7;

            __half2 h;
            u32 pa0, pa1, pa2, pa3;
            h = __floats2half2_rn(p0, p1); pa0 = *reinterpret_cast<u32*>(&h);
            h = __floats2half2_rn(p2, p3); pa1 = *reinterpret_cast<u32*>(&h);
            h = __floats2half2_rn(p4, p5); pa2 = *reinterpret_cast<u32*>(&h);
            h = __floats2half2_rn(p6, p7); pa3 = *reinterpret_cast<u32*>(&h);

            const int jb = jp * 16;
            u32 vh0 = *reinterpret_cast<u32*>(&sm[SVTH + g*264 + jb + 2*t]);
            u32 vh1 = *reinterpret_cast<u32*>(&sm[SVTH + g*264 + jb + 2*t + 8]);
            MMA16816(o0[0],o0[1],o0[2],o0[3], pa0,pa1,pa2,pa3, vh0,vh1);
            u32 wh0 = *reinterpret_cast<u32*>(&sm[SVTH + (8+g)*264 + jb + 2*t]);
            u32 wh1 = *reinterpret_cast<u32*>(&sm[SVTH + (8+g)*264 + jb + 2*t + 8]);
            MMA16816(o1[0],o1[1],o1[2],o1[3], pa0,pa1,pa2,pa3, wh0,wh1);
        }

        l0 += __shfl_xor_sync(0xffffffffu, l0, 1);
        l0 += __shfl_xor_sync(0xffffffffu, l0, 2);
        l1 += __shfl_xor_sync(0xffffffffu, l1, 1);
        l1 += __shfl_xor_sync(0xffffffffu, l1, 2);
        const float inv0 = 1.f / l0, inv1 = 1.f / l1;

        const int col = hd * HD + 2 * t;
        *reinterpret_cast<__half2*>(&attn_out[(size_t)m0 * C_DIM + col]) =
            __floats2half2_rn(o0[0] * inv0, o0[1] * inv0);
        *reinterpret_cast<__half2*>(&attn_out[(size_t)m1 * C_DIM + col]) =
            __floats2half2_rn(o0[2] * inv1, o0[3] * inv1);
        *reinterpret_cast<__half2*>(&attn_out[(size_t)m0 * C_DIM + col + 8]) =
            __floats2half2_rn(o1[0] * inv0, o1[1] * inv0);
        *reinterpret_cast<__half2*>(&attn_out[(size_t)m1 * C_DIM + col + 8]) =
            __floats2half2_rn(o1[2] * inv1, o1[3] * inv1);
    }
}

// ---------------------------------------------------------------------------
extern "C" void kernel_launch(void* const* d_in, const int* in_sizes, int n_in,
                              void* d_out, int out_size)
{
    const float* x           = (const float*)d_in[0];
    const float* qkv_w       = (const float*)d_in[1];
    const float* qkv_b       = (const float*)d_in[2];
    const float* proj_w      = (const float*)d_in[3];
    const float* proj_b      = (const float*)d_in[4];
    const float* logit_scale = (const float*)d_in[5];
    const float* rpb_table   = (const float*)d_in[6];
    const float* n1w         = (const float*)d_in[7];
    const float* n1b         = (const float*)d_in[8];
    const float* n2w         = (const float*)d_in[9];
    const float* n2b         = (const float*)d_in[10];
    const float* fc1_w       = (const float*)d_in[11];
    const float* fc1_b       = (const float*)d_in[12];
    const float* fc2_w       = (const float*)d_in[13];
    const float* fc2_b       = (const float*)d_in[14];
    const int*   rpi         = (const int*)d_in[17];
    float* out = (float*)d_out;

    float *p_x1;
    __half *p_qkvh, *p_attnh, *p_hidh;
    uint2 *p_biasF;
    cudaGetSymbolAddress((void**)&p_qkvh,  g_qkvh);
    cudaGetSymbolAddress((void**)&p_biasF, g_biasF);
    cudaGetSymbolAddress((void**)&p_attnh, g_attnh);
    cudaGetSymbolAddress((void**)&p_x1,    g_x1);
    cudaGetSymbolAddress((void**)&p_hidh,  g_hidh);

    // 1) bias fragments (pre-scaled by log2e)
    biasf_kernel<<<dim3(16 * 32, NH), 32>>>(rpi, rpb_table, p_biasF);

    // 2) QKV: fp32 A, fp16 C
    hgemm_kernel<false,true,0><<<dim3(384/128, M_TOK/128), 256>>>(
        x, qkv_w, qkv_b, p_qkvh, M_TOK, 384, 128, nullptr, nullptr, nullptr);

    // 3) tensor-core window attention (fp16 in/out)
    attn_tc_kernel<<<dim3(NWIN, NH), 128>>>(p_qkvh, p_biasF, logit_scale, p_attnh);

    // 4) proj + fused LN + residual: x1 = x + LN(attn @ proj_w + proj_b)
    hgemm_kernel<true,false,2><<<dim3(1, M_TOK/128), 256>>>(
        p_attnh, proj_w, proj_b, p_x1, M_TOK, 128, 128, x, n1w, n1b);

    // 5) fc1 + GELU: fp32 A, fp16 C
    hgemm_kernel<false,true,1><<<dim3(256/128, M_TOK/128), 256>>>(
        p_x1, fc1_w, fc1_b, p_hidh, M_TOK, 256, 128, nullptr, nullptr, nullptr);

    // 6) fc2 + fused LN + residual: out = x1 + LN(hid @ fc2_w + fc2_b)
    hgemm_kernel<true,false,2><<<dim3(1, M_TOK/128), 256>>>(
        p_hidh, fc2_w, fc2_b, out, M_TOK, 128, 256, p_x1, n2w, n2b);
}